// round 6
// baseline (speedup 1.0000x reference)
#include <cuda_runtime.h>
#include <cuda_bf16.h>
#include <cstdint>
#include <cstddef>

#define DIM     4096
#define SEQ     2048
#define HEADS   32
#define KVHEADS 8
#define HDIM    128
#define KVDIM   1024   // KVHEADS*HDIM

// ------------------------- scratch (static, no allocation) -------------------
__device__ float g_xq[SEQ * DIM];      // fp32 Q proj
__device__ float g_xk[SEQ * KVDIM];
__device__ float g_xv[SEQ * KVDIM];

// bf16 hi/lo splits
__device__ __nv_bfloat16 g_xh[SEQ * DIM],    g_xl[SEQ * DIM];
__device__ __nv_bfloat16 g_wqh[DIM * DIM],   g_wql[DIM * DIM];
__device__ __nv_bfloat16 g_wkh[KVDIM * DIM], g_wkl[KVDIM * DIM];
__device__ __nv_bfloat16 g_wvh[KVDIM * DIM], g_wvl[KVDIM * DIM];
__device__ __nv_bfloat16 g_woh[DIM * DIM],   g_wol[DIM * DIM];
__device__ __nv_bfloat16 g_ath[SEQ * DIM],   g_atl[SEQ * DIM];
__device__ __nv_bfloat16 g_qh[SEQ * DIM],    g_ql[SEQ * DIM];
__device__ __nv_bfloat16 g_kh[SEQ * KVDIM],  g_kl[SEQ * KVDIM];
__device__ __nv_bfloat16 g_vh[SEQ * KVDIM],  g_vl[SEQ * KVDIM];

// ============================================================================
// split: fp32 -> bf16 hi + bf16 lo. z==1 switches to (x2, hi2, lo2).
// ============================================================================
__global__ void split_kernel(const float* __restrict__ x,
                             __nv_bfloat16* __restrict__ hi,
                             __nv_bfloat16* __restrict__ lo,
                             const float* __restrict__ x2,
                             __nv_bfloat16* __restrict__ hi2,
                             __nv_bfloat16* __restrict__ lo2, int n4)
{
    const int i = blockIdx.x * blockDim.x + threadIdx.x;
    if (i >= n4) return;
    if (blockIdx.y == 1) { x = x2; hi = hi2; lo = lo2; }
    float4 v = ((const float4*)x)[i];
    __nv_bfloat16 h0 = __float2bfloat16(v.x);
    __nv_bfloat16 h1 = __float2bfloat16(v.y);
    __nv_bfloat16 h2 = __float2bfloat16(v.z);
    __nv_bfloat16 h3 = __float2bfloat16(v.w);
    __nv_bfloat16 l0 = __float2bfloat16(v.x - __bfloat162float(h0));
    __nv_bfloat16 l1 = __float2bfloat16(v.y - __bfloat162float(h1));
    __nv_bfloat16 l2 = __float2bfloat16(v.z - __bfloat162float(h2));
    __nv_bfloat16 l3 = __float2bfloat16(v.w - __bfloat162float(h3));
    __nv_bfloat162 hp0 = __halves2bfloat162(h0, h1);
    __nv_bfloat162 hp1 = __halves2bfloat162(h2, h3);
    __nv_bfloat162 lp0 = __halves2bfloat162(l0, l1);
    __nv_bfloat162 lp1 = __halves2bfloat162(l2, l3);
    uint2 hv, lv;
    hv.x = *(uint32_t*)&hp0; hv.y = *(uint32_t*)&hp1;
    lv.x = *(uint32_t*)&lp0; lv.y = *(uint32_t*)&lp1;
    ((uint2*)hi)[i] = hv;
    ((uint2*)lo)[i] = lv;
}

// ============================================================================
// RoPE + split: reads fp32 [SEQ][nheads*HDIM], writes rotated bf16 hi/lo
// ============================================================================
__global__ void rope_split_kernel(const float* __restrict__ t,
                                  const float* __restrict__ fc,
                                  const float* __restrict__ fs,
                                  __nv_bfloat16* __restrict__ hi,
                                  __nv_bfloat16* __restrict__ lo,
                                  int nheads)
{
    const int idx = blockIdx.x * blockDim.x + threadIdx.x;
    const int total = SEQ * nheads * (HDIM / 2);
    if (idx >= total) return;
    const int p  = idx & 63;
    const int t2 = idx >> 6;
    const int hh = t2 % nheads;
    const int s  = t2 / nheads;
    const float c  = fc[s * 64 + p];
    const float sn = fs[s * 64 + p];
    const size_t base = ((size_t)s * nheads + hh) * HDIM + 2 * p;
    const float a = t[base];
    const float b = t[base + 1];
    const float ra = a * c - b * sn;
    const float rb = a * sn + b * c;
    __nv_bfloat16 ha = __float2bfloat16(ra);
    __nv_bfloat16 hb = __float2bfloat16(rb);
    __nv_bfloat16 la = __float2bfloat16(ra - __bfloat162float(ha));
    __nv_bfloat16 lb = __float2bfloat16(rb - __bfloat162float(hb));
    __nv_bfloat162 hp = __halves2bfloat162(ha, hb);
    __nv_bfloat162 lp = __halves2bfloat162(la, lb);
    *(uint32_t*)&hi[base] = *(uint32_t*)&hp;
    *(uint32_t*)&lo[base] = *(uint32_t*)&lp;
}

// ============================================================================
// shared mma helpers
// ============================================================================
__device__ __forceinline__ void ldsm4(uint32_t* r, uint32_t addr) {
    asm volatile("ldmatrix.sync.aligned.m8n8.x4.shared.b16 {%0,%1,%2,%3}, [%4];"
                 : "=r"(r[0]), "=r"(r[1]), "=r"(r[2]), "=r"(r[3]) : "r"(addr));
}
__device__ __forceinline__ void ldsm4t(uint32_t* r, uint32_t addr) {
    asm volatile("ldmatrix.sync.aligned.m8n8.x4.trans.shared.b16 {%0,%1,%2,%3}, [%4];"
                 : "=r"(r[0]), "=r"(r[1]), "=r"(r[2]), "=r"(r[3]) : "r"(addr));
}
__device__ __forceinline__ void mma16816(float* c, const uint32_t* a, const uint32_t* b) {
    asm volatile("mma.sync.aligned.m16n8k16.row.col.f32.bf16.bf16.f32 "
                 "{%0,%1,%2,%3},{%4,%5,%6,%7},{%8,%9},{%0,%1,%2,%3};"
                 : "+f"(c[0]), "+f"(c[1]), "+f"(c[2]), "+f"(c[3])
                 : "r"(a[0]), "r"(a[1]), "r"(a[2]), "r"(a[3]), "r"(b[0]), "r"(b[1]));
}

#define CP16(dst, src) asm volatile("cp.async.cg.shared.global [%0], [%1], 16;" :: "r"(dst), "l"(src))
#define CP_COMMIT()    asm volatile("cp.async.commit_group;")
#define CP_WAIT(n)     asm volatile("cp.async.wait_group %0;" :: "n"(n))

// smem byte offset with XOR swizzle (row stride 64B, 16B chunks)
__device__ __forceinline__ uint32_t soff(int row, int chunk) {
    return (uint32_t)((row << 6) + ((chunk ^ ((row >> 1) & 3)) << 4));
}

// ============================================================================
// bf16x3 tensor-core GEMM:  C[M,N](fp32) = A[M,K] * B[N,K]^T
// 128x256x32 CTA tile, 256 thr (8 warps, 2x4), warp tile 64x64,
// 3-stage cp.async pipeline. z==1 switches to (B2,C2).
// Bigger N-tile halves redundant A reads and doubles MACs per loaded byte:
// per stage 48KB loads vs 3072 MMA-cycles -> loads fully hidden.
// ============================================================================
#define GBM 128
#define GBN 256
#define GBK 32
#define AMAT 8192                  // 128 rows x 64B
#define BMAT 16384                 // 256 rows x 64B
#define GSTAGE (2 * AMAT + 2 * BMAT)   // Ah, Al, Bh, Bl = 48KB
#define GEMM_SMEM (3 * GSTAGE)         // 144KB

__global__ void __launch_bounds__(256, 1) gemm_bf16x3_kernel(
    const __nv_bfloat16* __restrict__ Ah, const __nv_bfloat16* __restrict__ Al,
    const __nv_bfloat16* Bh, const __nv_bfloat16* Bl, float* C,
    const __nv_bfloat16* B2h, const __nv_bfloat16* B2l, float* C2,
    int M, int N, int K)
{
    if (blockIdx.z == 1) { Bh = B2h; Bl = B2l; C = C2; }

    extern __shared__ char smem[];
    const int tid  = threadIdx.x;
    const int lane = tid & 31;
    const int w    = tid >> 5;
    const int wm   = w >> 2;          // 0..1  (64-row band)
    const int wn   = w & 3;           // 0..3  (64-col band)
    const int bm   = blockIdx.y * GBM;
    const int bn   = blockIdx.x * GBN;

    float acc[4][8][4];
    #pragma unroll
    for (int i = 0; i < 4; i++)
        #pragma unroll
        for (int j = 0; j < 8; j++)
            #pragma unroll
            for (int r = 0; r < 4; r++) acc[i][j][r] = 0.0f;

    const uint32_t sbase = (uint32_t)__cvta_generic_to_shared(smem);

    // stage loader: A 128x4 chunks (2/thread), B 256x4 chunks (4/thread)
    auto ldstage = [&](int s) {
        const uint32_t buf = sbase + (uint32_t)(s % 3) * GSTAGE;
        const int k0 = s * GBK;
        #pragma unroll
        for (int i = 0; i < 2; i++) {
            const int f = tid + 256 * i;
            const int row = f >> 2, chk = f & 3;
            const uint32_t so = soff(row, chk);
            const size_t ga = (size_t)(bm + row) * K + k0 + chk * 8;
            CP16(buf + so,        Ah + ga);
            CP16(buf + AMAT + so, Al + ga);
        }
        #pragma unroll
        for (int i = 0; i < 4; i++) {
            const int f = tid + 256 * i;
            const int row = f >> 2, chk = f & 3;
            const uint32_t so = soff(row, chk);
            const size_t gb = (size_t)(bn + row) * K + k0 + chk * 8;
            CP16(buf + 2 * AMAT + so,        Bh + gb);
            CP16(buf + 2 * AMAT + BMAT + so, Bl + gb);
        }
    };

    const int nst = K / GBK;
    ldstage(0); CP_COMMIT();
    ldstage(1); CP_COMMIT();
    ldstage(2); CP_COMMIT();

    const int rl = lane & 15;
    const int rh = lane >> 4;

    for (int it = 0; it < nst; ++it) {
        if (it < nst - 2)       { CP_WAIT(2); }
        else if (it == nst - 2) { CP_WAIT(1); }
        else                    { CP_WAIT(0); }
        __syncthreads();

        const uint32_t buf = sbase + (uint32_t)(it % 3) * GSTAGE;
        const uint32_t sAh = buf;
        const uint32_t sAl = buf + AMAT;
        const uint32_t sBh = buf + 2 * AMAT;
        const uint32_t sBl = buf + 2 * AMAT + BMAT;

        #pragma unroll
        for (int ks = 0; ks < 2; ks++) {
            const int chunk = 2 * ks + rh;
            uint32_t ah[4][4], al[4][4], bh[8][2], bl[8][2];

            #pragma unroll
            for (int mi = 0; mi < 4; mi++)
                ldsm4(ah[mi], sAh + soff(wm * 64 + mi * 16 + rl, chunk));
            #pragma unroll
            for (int mi = 0; mi < 4; mi++)
                ldsm4(al[mi], sAl + soff(wm * 64 + mi * 16 + rl, chunk));
            #pragma unroll
            for (int nb = 0; nb < 4; nb++) {
                uint32_t r4[4];
                ldsm4(r4, sBh + soff(wn * 64 + nb * 16 + rl, chunk));
                bh[2 * nb][0] = r4[0]; bh[2 * nb + 1][0] = r4[1];
                bh[2 * nb][1] = r4[2]; bh[2 * nb + 1][1] = r4[3];
            }
            #pragma unroll
            for (int nb = 0; nb < 4; nb++) {
                uint32_t r4[4];
                ldsm4(r4, sBl + soff(wn * 64 + nb * 16 + rl, chunk));
                bl[2 * nb][0] = r4[0]; bl[2 * nb + 1][0] = r4[1];
                bl[2 * nb][1] = r4[2]; bl[2 * nb + 1][1] = r4[3];
            }

            // pass 1: hi*hi (32 independent accumulator chains)
            #pragma unroll
            for (int mi = 0; mi < 4; mi++)
                #pragma unroll
                for (int nj = 0; nj < 8; nj++)
                    mma16816(acc[mi][nj], ah[mi], bh[nj]);
            // pass 2: hi*lo
            #pragma unroll
            for (int mi = 0; mi < 4; mi++)
                #pragma unroll
                for (int nj = 0; nj < 8; nj++)
                    mma16816(acc[mi][nj], ah[mi], bl[nj]);
            // pass 3: lo*hi
            #pragma unroll
            for (int mi = 0; mi < 4; mi++)
                #pragma unroll
                for (int nj = 0; nj < 8; nj++)
                    mma16816(acc[mi][nj], al[mi], bh[nj]);
        }
        __syncthreads();

        if (it + 3 < nst) {
            ldstage(it + 3);
            CP_COMMIT();
        }
    }

    const int tg = lane >> 2;
    const int ti = lane & 3;
    #pragma unroll
    for (int mi = 0; mi < 4; mi++) {
        const int row = bm + wm * 64 + mi * 16 + tg;
        #pragma unroll
        for (int nj = 0; nj < 8; nj++) {
            const int col = bn + wn * 64 + nj * 8 + 2 * ti;
            float2 v0 = make_float2(acc[mi][nj][0], acc[mi][nj][1]);
            float2 v1 = make_float2(acc[mi][nj][2], acc[mi][nj][3]);
            *(float2*)&C[(size_t)row * N + col]       = v0;
            *(float2*)&C[(size_t)(row + 8) * N + col] = v1;
        }
    }
}

// ============================================================================
// Tensor-core flash attention, bf16x3, causal, GQA. Pass-major schedule (R5).
// ============================================================================
#define BQ 128
#define BKV 64
#define QMAT 32768
#define KVMAT 16384
#define FSTAGE (4 * KVMAT)
#define FLASH_SMEM (2 * QMAT + 2 * FSTAGE)

__device__ __forceinline__ uint32_t fsw(int r, int c) {
    return (uint32_t)((r << 8) + ((c ^ (r & 7)) << 4));
}
__device__ __forceinline__ uint32_t pack_hi_rz(float p0, float p1, float& lo0, float& lo1) {
    uint32_t u0 = __float_as_uint(p0), u1 = __float_as_uint(p1);
    lo0 = p0 - __uint_as_float(u0 & 0xffff0000u);
    lo1 = p1 - __uint_as_float(u1 & 0xffff0000u);
    return __byte_perm(u0, u1, 0x7632);
}
__device__ __forceinline__ uint32_t pack_rn(float a, float b) {
    __nv_bfloat162 t = __floats2bfloat162_rn(a, b);
    return *(uint32_t*)&t;
}

__global__ void __launch_bounds__(256, 1) flash_tc_kernel(
    const __nv_bfloat16* __restrict__ qh, const __nv_bfloat16* __restrict__ ql,
    const __nv_bfloat16* __restrict__ kh, const __nv_bfloat16* __restrict__ kl,
    const __nv_bfloat16* __restrict__ vh, const __nv_bfloat16* __restrict__ vl,
    __nv_bfloat16* __restrict__ ath, __nv_bfloat16* __restrict__ atl)
{
    extern __shared__ char smc[];
    const uint32_t sb  = (uint32_t)__cvta_generic_to_shared(smc);
    const uint32_t sQh = sb, sQl = sb + QMAT;

    const int tid  = threadIdx.x;
    const int lane = tid & 31;
    const int w    = tid >> 5;
    const int rl   = lane & 15;
    const int rh   = lane >> 4;
    const int tg   = lane >> 2;
    const int ti   = lane & 3;
    const int vro  = (lane & 7) + ((lane >> 3) & 1) * 8;
    const int vco  = lane >> 4;

    const int qt    = gridDim.x - 1 - blockIdx.x;
    const int h     = blockIdx.y;
    const int kvh   = h >> 2;
    const int qbase = qt * BQ;
    const int wrow  = w * 16;

    for (int f = tid; f < 2048; f += 256) {
        const int r = f >> 4, c = f & 15;
        const size_t go = (size_t)(qbase + r) * DIM + h * HDIM + c * 8;
        CP16(sQh + fsw(r, c), qh + go);
        CP16(sQl + fsw(r, c), ql + go);
    }
    CP_COMMIT();

    auto loadKV = [&](int kt) {
        const uint32_t base = sb + 2 * QMAT + (kt & 1) * FSTAGE;
        const int kvb = kt * BKV;
        for (int f = tid; f < 1024; f += 256) {
            const int r = f >> 4, c = f & 15;
            const size_t go = (size_t)(kvb + r) * KVDIM + kvh * HDIM + c * 8;
            const uint32_t so = fsw(r, c);
            CP16(base + so,             kh + go);
            CP16(base + KVMAT + so,     kl + go);
            CP16(base + 2 * KVMAT + so, vh + go);
            CP16(base + 3 * KVMAT + so, vl + go);
        }
    };

    loadKV(0);
    CP_COMMIT();

    float o[16][4];
    #pragma unroll
    for (int i = 0; i < 16; i++)
        #pragma unroll
        for (int r = 0; r < 4; r++) o[i][r] = 0.0f;
    float m0 = -1e30f, m1 = -1e30f, l0 = 0.0f, l1 = 0.0f;
    const float scale = 0.08838834764831843f;
    const int row0 = qbase + wrow + tg;
    const int row1 = row0 + 8;

    const int nkt = 2 * qt + 2;
    for (int kt = 0; kt < nkt; kt++) {
        if (kt + 1 < nkt) { loadKV(kt + 1); CP_COMMIT(); CP_WAIT(1); }
        else              { CP_WAIT(0); }
        __syncthreads();

        const uint32_t base = sb + 2 * QMAT + (kt & 1) * FSTAGE;
        const uint32_t sKh = base, sKl = base + KVMAT;
        const uint32_t sVh = base + 2 * KVMAT, sVl = base + 3 * KVMAT;
        const int kvb = kt * BKV;

        // ---- S = Q K^T, pass-major ----
        float s[8][4];
        #pragma unroll
        for (int i = 0; i < 8; i++)
            #pragma unroll
            for (int r = 0; r < 4; r++) s[i][r] = 0.0f;

        #pragma unroll
        for (int kc = 0; kc < 8; kc++) {
            uint32_t ah[4], al[4];
            ldsm4(ah, sQh + fsw(wrow + rl, 2 * kc + rh));
            ldsm4(al, sQl + fsw(wrow + rl, 2 * kc + rh));

            uint32_t bh[8][2], bl[8][2];
            #pragma unroll
            for (int nb = 0; nb < 4; nb++) {
                uint32_t rk[4], rkl[4];
                ldsm4(rk,  sKh + fsw(nb * 16 + rl, 2 * kc + rh));
                ldsm4(rkl, sKl + fsw(nb * 16 + rl, 2 * kc + rh));
                bh[2 * nb][0]     = rk[0];  bh[2 * nb][1]     = rk[2];
                bh[2 * nb + 1][0] = rk[1];  bh[2 * nb + 1][1] = rk[3];
                bl[2 * nb][0]     = rkl[0]; bl[2 * nb][1]     = rkl[2];
                bl[2 * nb + 1][0] = rkl[1]; bl[2 * nb + 1][1] = rkl[3];
            }
            #pragma unroll
            for (int nj = 0; nj < 8; nj++) mma16816(s[nj], ah, bh[nj]);
            #pragma unroll
            for (int nj = 0; nj < 8; nj++) mma16816(s[nj], ah, bl[nj]);
            #pragma unroll
            for (int nj = 0; nj < 8; nj++) mma16816(s[nj], al, bh[nj]);
        }

        // ---- scale + causal mask ----
        const bool needmask = (kt >= 2 * qt);
        #pragma unroll
        for (int nj = 0; nj < 8; nj++) {
            #pragma unroll
            for (int r = 0; r < 4; r++) {
                float v = s[nj][r] * scale;
                if (needmask) {
                    const int col = kvb + nj * 8 + 2 * ti + (r & 1);
                    const int row = (r & 2) ? row1 : row0;
                    if (col > row) v = -1e30f;
                }
                s[nj][r] = v;
            }
        }

        // ---- online softmax ----
        float mx0 = -1e30f, mx1 = -1e30f;
        #pragma unroll
        for (int nj = 0; nj < 8; nj++) {
            mx0 = fmaxf(mx0, fmaxf(s[nj][0], s[nj][1]));
            mx1 = fmaxf(mx1, fmaxf(s[nj][2], s[nj][3]));
        }
        mx0 = fmaxf(mx0, __shfl_xor_sync(0xffffffffu, mx0, 1));
        mx0 = fmaxf(mx0, __shfl_xor_sync(0xffffffffu, mx0, 2));
        mx1 = fmaxf(mx1, __shfl_xor_sync(0xffffffffu, mx1, 1));
        mx1 = fmaxf(mx1, __shfl_xor_sync(0xffffffffu, mx1, 2));
        const float mn0 = fmaxf(m0, mx0), mn1 = fmaxf(m1, mx1);
        const float cr0 = __expf(m0 - mn0), cr1 = __expf(m1 - mn1);
        m0 = mn0; m1 = mn1;

        float sum0 = 0.0f, sum1 = 0.0f;
        #pragma unroll
        for (int nj = 0; nj < 8; nj++) {
            s[nj][0] = __expf(s[nj][0] - mn0); sum0 += s[nj][0];
            s[nj][1] = __expf(s[nj][1] - mn0); sum0 += s[nj][1];
            s[nj][2] = __expf(s[nj][2] - mn1); sum1 += s[nj][2];
            s[nj][3] = __expf(s[nj][3] - mn1); sum1 += s[nj][3];
        }
        sum0 += __shfl_xor_sync(0xffffffffu, sum0, 1);
        sum0 += __shfl_xor_sync(0xffffffffu, sum0, 2);
        sum1 += __shfl_xor_sync(0xffffffffu, sum1, 1);
        sum1 += __shfl_xor_sync(0xffffffffu, sum1, 2);
        l0 = l0 * cr0 + sum0;
        l1 = l1 * cr1 + sum1;

        #pragma unroll
        for (int nj = 0; nj < 16; nj++) {
            o[nj][0] *= cr0; o[nj][1] *= cr0;
            o[nj][2] *= cr1; o[nj][3] *= cr1;
        }

        // ---- O += P V, pass-major over halves ----
        #pragma unroll
        for (int kc = 0; kc < 4; kc++) {
            uint32_t pah[4], pal[4];
            {
                float la, lb;
                pah[0] = pack_hi_rz(s[2 * kc][0],     s[2 * kc][1],     la, lb); pal[0] = pack_rn(la, lb);
                pah[1] = pack_hi_rz(s[2 * kc][2],     s[2 * kc][3],     la, lb); pal[1] = pack_rn(la, lb);
                pah[2] = pack_hi_rz(s[2 * kc + 1][0], s[2 * kc + 1][1], la, lb); pal[2] = pack_rn(la, lb);
                pah[3] = pack_hi_rz(s[2 * kc + 1][2], s[2 * kc + 1][3], la, lb); pal[3] = pack_rn(la, lb);
            }
            #pragma unroll
            for (int half = 0; half < 2; half++) {
                uint32_t bv[8][2], cv[8][2];
                #pragma unroll
                for (int n4 = 0; n4 < 4; n4++) {
                    const int nb = half * 4 + n4;
                    uint32_t rv[4], rw[4];
                    const uint32_t so = fsw(kc * 16 + vro, 2 * nb + vco);
                    ldsm4t(rv, sVh + so);
                    ldsm4t(rw, sVl + so);
                    bv[2 * n4][0]     = rv[0]; bv[2 * n4][1]     = rv[1];
                    bv[2 * n4 + 1][0] = rv[2]; bv[2 * n4 + 1][1] = rv[3];
                    cv[2 * n4][0]     = rw[0]; cv[2 * n4][1]     = rw[1];
                    cv[2 * n4 + 1][0] = rw[2]; cv[2 * n4 + 1][1] = rw[3];
                }
                #pragma unroll
                for (int j = 0; j < 8; j++) mma16816(o[8 * half + j], pah, bv[j]);
                #pragma unroll
                for (int j = 0; j < 8; j++) mma16816(o[8 * half + j], pah, cv[j]);
                #pragma unroll
                for (int j = 0; j < 8; j++) mma16816(o[8 * half + j], pal, bv[j]);
            }
        }
        __syncthreads();
    }

    // ---- epilogue: normalize, split hi/lo, store ----
    const float inv0 = 1.0f / l0, inv1 = 1.0f / l1;
    #pragma unroll
    for (int nj = 0; nj < 16; nj++) {
        const int col = h * HDIM + nj * 8 + 2 * ti;
        float v0 = o[nj][0] * inv0, v1 = o[nj][1] * inv0;
        float v2 = o[nj][2] * inv1, v3 = o[nj][3] * inv1;
        __nv_bfloat162 h0 = __floats2bfloat162_rn(v0, v1);
        __nv_bfloat162 h1 = __floats2bfloat162_rn(v2, v3);
        __nv_bfloat162 e0 = __floats2bfloat162_rn(v0 - __low2float(h0), v1 - __high2float(h0));
        __nv_bfloat162 e1 = __floats2bfloat162_rn(v2 - __low2float(h1), v3 - __high2float(h1));
        *(uint32_t*)&ath[(size_t)row0 * DIM + col] = *(uint32_t*)&h0;
        *(uint32_t*)&ath[(size_t)row1 * DIM + col] = *(uint32_t*)&h1;
        *(uint32_t*)&atl[(size_t)row0 * DIM + col] = *(uint32_t*)&e0;
        *(uint32_t*)&atl[(size_t)row1 * DIM + col] = *(uint32_t*)&e1;
    }
}

// ============================================================================
// launch
// ============================================================================
extern "C" void kernel_launch(void* const* d_in, const int* in_sizes, int n_in,
                              void* d_out, int out_size)
{
    (void)in_sizes; (void)n_in; (void)out_size;
    const float* x  = (const float*)d_in[0];
    const float* wq = (const float*)d_in[1];
    const float* wk = (const float*)d_in[2];
    const float* wv = (const float*)d_in[3];
    const float* wo = (const float*)d_in[4];
    const float* fc = (const float*)d_in[5];
    const float* fs = (const float*)d_in[6];
    float* out = (float*)d_out;

    float *xq, *xk, *xv;
    __nv_bfloat16 *xh, *xl, *wqh, *wql, *wkh, *wkl, *wvh, *wvl, *woh, *wol;
    __nv_bfloat16 *ath, *atl, *qh, *ql, *kh, *kl, *vh, *vl;
    cudaGetSymbolAddress((void**)&xq, g_xq);
    cudaGetSymbolAddress((void**)&xk, g_xk);
    cudaGetSymbolAddress((void**)&xv, g_xv);
    cudaGetSymbolAddress((void**)&xh,  g_xh);  cudaGetSymbolAddress((void**)&xl,  g_xl);
    cudaGetSymbolAddress((void**)&wqh, g_wqh); cudaGetSymbolAddress((void**)&wql, g_wql);
    cudaGetSymbolAddress((void**)&wkh, g_wkh); cudaGetSymbolAddress((void**)&wkl, g_wkl);
    cudaGetSymbolAddress((void**)&wvh, g_wvh); cudaGetSymbolAddress((void**)&wvl, g_wvl);
    cudaGetSymbolAddress((void**)&woh, g_woh); cudaGetSymbolAddress((void**)&wol, g_wol);
    cudaGetSymbolAddress((void**)&ath, g_ath); cudaGetSymbolAddress((void**)&atl, g_atl);
    cudaGetSymbolAddress((void**)&qh,  g_qh);  cudaGetSymbolAddress((void**)&ql,  g_ql);
    cudaGetSymbolAddress((void**)&kh,  g_kh);  cudaGetSymbolAddress((void**)&kl,  g_kl);
    cudaGetSymbolAddress((void**)&vh,  g_vh);  cudaGetSymbolAddress((void**)&vl,  g_vl);

    cudaFuncSetAttribute(gemm_bf16x3_kernel,
                         cudaFuncAttributeMaxDynamicSharedMemorySize, GEMM_SMEM);
    cudaFuncSetAttribute(flash_tc_kernel,
                         cudaFuncAttributeMaxDynamicSharedMemorySize, FLASH_SMEM);

    // 0) split inputs to bf16 hi/lo (4 launches: x, wq, wk+wv fused, wo)
    split_kernel<<<dim3((SEQ * DIM / 4 + 255) / 256, 1), 256>>>(
        x, xh, xl, nullptr, nullptr, nullptr, SEQ * DIM / 4);
    split_kernel<<<dim3((DIM * DIM / 4 + 255) / 256, 1), 256>>>(
        wq, wqh, wql, nullptr, nullptr, nullptr, DIM * DIM / 4);
    split_kernel<<<dim3((KVDIM * DIM / 4 + 255) / 256, 2), 256>>>(
        wk, wkh, wkl, wv, wvh, wvl, KVDIM * DIM / 4);
    split_kernel<<<dim3((DIM * DIM / 4 + 255) / 256, 1), 256>>>(
        wo, woh, wol, nullptr, nullptr, nullptr, DIM * DIM / 4);

    // 1) Q projection (fp32 out)
    gemm_bf16x3_kernel<<<dim3(DIM / GBN, SEQ / GBM, 1), 256, GEMM_SMEM>>>(
        xh, xl, wqh, wql, xq, nullptr, nullptr, nullptr, SEQ, DIM, DIM);

    // 2) K and V projections fused
    gemm_bf16x3_kernel<<<dim3(KVDIM / GBN, SEQ / GBM, 2), 256, GEMM_SMEM>>>(
        xh, xl, wkh, wkl, xk, wvh, wvl, xv, SEQ, KVDIM, DIM);

    // 3) RoPE + split to bf16 hi/lo; split V
    {
        const int nq = SEQ * HEADS * (HDIM / 2);
        rope_split_kernel<<<(nq + 255) / 256, 256>>>(xq, fc, fs, qh, ql, HEADS);
        const int nk = SEQ * KVHEADS * (HDIM / 2);
        rope_split_kernel<<<(nk + 255) / 256, 256>>>(xk, fc, fs, kh, kl, KVHEADS);
        split_kernel<<<dim3((SEQ * KVDIM / 4 + 255) / 256, 1), 256>>>(
            xv, vh, vl, nullptr, nullptr, nullptr, SEQ * KVDIM / 4);
    }

    // 4) tensor-core flash attention -> attn hi/lo
    flash_tc_kernel<<<dim3(SEQ / BQ, HEADS), 256, FLASH_SMEM>>>(
        qh, ql, kh, kl, vh, vl, ath, atl);

    // 5) O projection
    gemm_bf16x3_kernel<<<dim3(DIM / GBN, SEQ / GBM, 1), 256, GEMM_SMEM>>>(
        ath, atl, woh, wol, out, nullptr, nullptr, nullptr, SEQ, DIM, DIM);
}

// round 7
// speedup vs baseline: 1.6152x; 1.6152x over previous
#include <cuda_runtime.h>
#include <cuda_bf16.h>
#include <cstdint>
#include <cstddef>

#define DIM     4096
#define SEQ     2048
#define HEADS   32
#define KVHEADS 8
#define HDIM    128
#define KVDIM   1024   // KVHEADS*HDIM

// ------------------------- scratch (static, no allocation) -------------------
__device__ float g_xq[SEQ * DIM];      // fp32 Q proj
__device__ float g_xk[SEQ * KVDIM];
__device__ float g_xv[SEQ * KVDIM];

// bf16 hi/lo splits
__device__ __nv_bfloat16 g_xh[SEQ * DIM],    g_xl[SEQ * DIM];
__device__ __nv_bfloat16 g_wqh[DIM * DIM],   g_wql[DIM * DIM];
__device__ __nv_bfloat16 g_wkh[KVDIM * DIM], g_wkl[KVDIM * DIM];
__device__ __nv_bfloat16 g_wvh[KVDIM * DIM], g_wvl[KVDIM * DIM];
__device__ __nv_bfloat16 g_woh[DIM * DIM],   g_wol[DIM * DIM];
__device__ __nv_bfloat16 g_ath[SEQ * DIM],   g_atl[SEQ * DIM];
__device__ __nv_bfloat16 g_qh[SEQ * DIM],    g_ql[SEQ * DIM];
__device__ __nv_bfloat16 g_kh[SEQ * KVDIM],  g_kl[SEQ * KVDIM];
__device__ __nv_bfloat16 g_vh[SEQ * KVDIM],  g_vl[SEQ * KVDIM];

// ============================================================================
// split: fp32 -> bf16 hi + bf16 lo. blockIdx.y==1 switches to (x2, hi2, lo2).
// ============================================================================
__global__ void split_kernel(const float* __restrict__ x,
                             __nv_bfloat16* __restrict__ hi,
                             __nv_bfloat16* __restrict__ lo,
                             const float* __restrict__ x2,
                             __nv_bfloat16* __restrict__ hi2,
                             __nv_bfloat16* __restrict__ lo2, int n4)
{
    const int i = blockIdx.x * blockDim.x + threadIdx.x;
    if (i >= n4) return;
    if (blockIdx.y == 1) { x = x2; hi = hi2; lo = lo2; }
    float4 v = ((const float4*)x)[i];
    __nv_bfloat16 h0 = __float2bfloat16(v.x);
    __nv_bfloat16 h1 = __float2bfloat16(v.y);
    __nv_bfloat16 h2 = __float2bfloat16(v.z);
    __nv_bfloat16 h3 = __float2bfloat16(v.w);
    __nv_bfloat16 l0 = __float2bfloat16(v.x - __bfloat162float(h0));
    __nv_bfloat16 l1 = __float2bfloat16(v.y - __bfloat162float(h1));
    __nv_bfloat16 l2 = __float2bfloat16(v.z - __bfloat162float(h2));
    __nv_bfloat16 l3 = __float2bfloat16(v.w - __bfloat162float(h3));
    __nv_bfloat162 hp0 = __halves2bfloat162(h0, h1);
    __nv_bfloat162 hp1 = __halves2bfloat162(h2, h3);
    __nv_bfloat162 lp0 = __halves2bfloat162(l0, l1);
    __nv_bfloat162 lp1 = __halves2bfloat162(l2, l3);
    uint2 hv, lv;
    hv.x = *(uint32_t*)&hp0; hv.y = *(uint32_t*)&hp1;
    lv.x = *(uint32_t*)&lp0; lv.y = *(uint32_t*)&lp1;
    ((uint2*)hi)[i] = hv;
    ((uint2*)lo)[i] = lv;
}

// ============================================================================
// RoPE + split: reads fp32 [SEQ][nheads*HDIM], writes rotated bf16 hi/lo
// ============================================================================
__global__ void rope_split_kernel(const float* __restrict__ t,
                                  const float* __restrict__ fc,
                                  const float* __restrict__ fs,
                                  __nv_bfloat16* __restrict__ hi,
                                  __nv_bfloat16* __restrict__ lo,
                                  int nheads)
{
    const int idx = blockIdx.x * blockDim.x + threadIdx.x;
    const int total = SEQ * nheads * (HDIM / 2);
    if (idx >= total) return;
    const int p  = idx & 63;
    const int t2 = idx >> 6;
    const int hh = t2 % nheads;
    const int s  = t2 / nheads;
    const float c  = fc[s * 64 + p];
    const float sn = fs[s * 64 + p];
    const size_t base = ((size_t)s * nheads + hh) * HDIM + 2 * p;
    const float a = t[base];
    const float b = t[base + 1];
    const float ra = a * c - b * sn;
    const float rb = a * sn + b * c;
    __nv_bfloat16 ha = __float2bfloat16(ra);
    __nv_bfloat16 hb = __float2bfloat16(rb);
    __nv_bfloat16 la = __float2bfloat16(ra - __bfloat162float(ha));
    __nv_bfloat16 lb = __float2bfloat16(rb - __bfloat162float(hb));
    __nv_bfloat162 hp = __halves2bfloat162(ha, hb);
    __nv_bfloat162 lp = __halves2bfloat162(la, lb);
    *(uint32_t*)&hi[base] = *(uint32_t*)&hp;
    *(uint32_t*)&lo[base] = *(uint32_t*)&lp;
}

// ============================================================================
// shared mma helpers
// ============================================================================
__device__ __forceinline__ void ldsm4(uint32_t* r, uint32_t addr) {
    asm volatile("ldmatrix.sync.aligned.m8n8.x4.shared.b16 {%0,%1,%2,%3}, [%4];"
                 : "=r"(r[0]), "=r"(r[1]), "=r"(r[2]), "=r"(r[3]) : "r"(addr));
}
__device__ __forceinline__ void ldsm4t(uint32_t* r, uint32_t addr) {
    asm volatile("ldmatrix.sync.aligned.m8n8.x4.trans.shared.b16 {%0,%1,%2,%3}, [%4];"
                 : "=r"(r[0]), "=r"(r[1]), "=r"(r[2]), "=r"(r[3]) : "r"(addr));
}
__device__ __forceinline__ void mma16816(float* c, const uint32_t* a, const uint32_t* b) {
    asm volatile("mma.sync.aligned.m16n8k16.row.col.f32.bf16.bf16.f32 "
                 "{%0,%1,%2,%3},{%4,%5,%6,%7},{%8,%9},{%0,%1,%2,%3};"
                 : "+f"(c[0]), "+f"(c[1]), "+f"(c[2]), "+f"(c[3])
                 : "r"(a[0]), "r"(a[1]), "r"(a[2]), "r"(a[3]), "r"(b[0]), "r"(b[1]));
}

#define CP16(dst, src) asm volatile("cp.async.cg.shared.global [%0], [%1], 16;" :: "r"(dst), "l"(src))
#define CP_COMMIT()    asm volatile("cp.async.commit_group;")
#define CP_WAIT(n)     asm volatile("cp.async.wait_group %0;" :: "n"(n))

// smem byte offset with XOR swizzle (row stride 64B, 16B chunks)
__device__ __forceinline__ uint32_t soff(int row, int chunk) {
    return (uint32_t)((row << 6) + ((chunk ^ ((row >> 1) & 3)) << 4));
}

// ============================================================================
// bf16x3 tensor-core GEMM:  C[M,N](fp32) = A[M,K] * B[N,K]^T
// 128x128x32 CTA tile, 256 thr, warp tile 64x32, 3-STAGE cp.async pipeline,
// 2 CTAs/SM. Column-group dispatch: one launch covers up to 3 concatenated
// output matrices sharing A (fused Q/K/V projection).
// ============================================================================
#define GBM 128
#define GBN 128
#define GBK 32
#define SMAT 8192                   // one 128x32 bf16 matrix (64B rows)
#define GSTAGE (4 * SMAT)           // Ah, Al, Bh, Bl = 32KB
#define GEMM_SMEM (3 * GSTAGE)      // 96KB -> 2 CTAs/SM = 192KB

__global__ void __launch_bounds__(256, 2) gemm_bf16x3_kernel(
    const __nv_bfloat16* __restrict__ Ah, const __nv_bfloat16* __restrict__ Al,
    const __nv_bfloat16* B0h, const __nv_bfloat16* B0l, float* C0, int N0,
    const __nv_bfloat16* B1h, const __nv_bfloat16* B1l, float* C1, int N1,
    const __nv_bfloat16* B2h, const __nv_bfloat16* B2l, float* C2,
    int K)
{
    // column-group selection (uniform per CTA)
    const int bng = blockIdx.x * GBN;
    const __nv_bfloat16 *Bh, *Bl;
    float* C;
    int N, bn;
    if (bng < N0)           { Bh = B0h; Bl = B0l; C = C0; N = N0; bn = bng; }
    else if (bng < N0 + N1) { Bh = B1h; Bl = B1l; C = C1; N = N1; bn = bng - N0; }
    else                    { Bh = B2h; Bl = B2l; C = C2; N = N1; bn = bng - N0 - N1; }

    extern __shared__ char smem[];
    const int tid  = threadIdx.x;
    const int lane = tid & 31;
    const int w    = tid >> 5;
    const int wm   = w >> 2;
    const int wn   = w & 3;
    const int bm   = blockIdx.y * GBM;

    const int lrow = tid >> 2;        // 0..63
    const int lc   = tid & 3;

    float acc[4][4][4];
    #pragma unroll
    for (int i = 0; i < 4; i++)
        #pragma unroll
        for (int j = 0; j < 4; j++)
            #pragma unroll
            for (int r = 0; r < 4; r++) acc[i][j][r] = 0.0f;

    const uint32_t sbase = (uint32_t)__cvta_generic_to_shared(smem);

    auto ldstage = [&](int s) {
        const uint32_t buf = sbase + (uint32_t)(s % 3) * GSTAGE;
        const int k0 = s * GBK;
        const __nv_bfloat16* ga = Ah + (size_t)(bm + lrow) * K + k0 + lc * 8;
        const __nv_bfloat16* gal = Al + (size_t)(bm + lrow) * K + k0 + lc * 8;
        const __nv_bfloat16* gb = Bh + (size_t)(bn + lrow) * K + k0 + lc * 8;
        const __nv_bfloat16* gbl = Bl + (size_t)(bn + lrow) * K + k0 + lc * 8;
        const uint32_t so0 = soff(lrow, lc);
        const uint32_t so1 = soff(lrow + 64, lc);
        CP16(buf + so0,            ga);
        CP16(buf + so1,            ga + (size_t)64 * K);
        CP16(buf + SMAT + so0,     gal);
        CP16(buf + SMAT + so1,     gal + (size_t)64 * K);
        CP16(buf + 2 * SMAT + so0, gb);
        CP16(buf + 2 * SMAT + so1, gb + (size_t)64 * K);
        CP16(buf + 3 * SMAT + so0, gbl);
        CP16(buf + 3 * SMAT + so1, gbl + (size_t)64 * K);
    };

    const int nst = K / GBK;
    ldstage(0); CP_COMMIT();
    ldstage(1); CP_COMMIT();
    ldstage(2); CP_COMMIT();

    const int rl = lane & 15;
    const int rh = lane >> 4;

    for (int it = 0; it < nst; ++it) {
        if (it < nst - 2)       { CP_WAIT(2); }
        else if (it == nst - 2) { CP_WAIT(1); }
        else                    { CP_WAIT(0); }
        __syncthreads();

        const uint32_t buf = sbase + (uint32_t)(it % 3) * GSTAGE;
        const uint32_t sAh = buf;
        const uint32_t sAl = buf + SMAT;
        const uint32_t sBh = buf + 2 * SMAT;
        const uint32_t sBl = buf + 3 * SMAT;

        #pragma unroll
        for (int ks = 0; ks < 2; ks++) {
            const int chunk = 2 * ks + rh;
            uint32_t ah[4][4], al[4][4], bh[4][2], bl[4][2];

            #pragma unroll
            for (int mi = 0; mi < 4; mi++)
                ldsm4(ah[mi], sAh + soff(wm * 64 + mi * 16 + rl, chunk));
            #pragma unroll
            for (int nb = 0; nb < 2; nb++) {
                uint32_t r4[4];
                ldsm4(r4, sBh + soff(wn * 32 + nb * 16 + rl, chunk));
                bh[2 * nb][0] = r4[0]; bh[2 * nb + 1][0] = r4[1];
                bh[2 * nb][1] = r4[2]; bh[2 * nb + 1][1] = r4[3];
            }
            // pass 1: hi*hi (16 independent chains)
            #pragma unroll
            for (int mi = 0; mi < 4; mi++)
                #pragma unroll
                for (int nj = 0; nj < 4; nj++)
                    mma16816(acc[mi][nj], ah[mi], bh[nj]);

            #pragma unroll
            for (int nb = 0; nb < 2; nb++) {
                uint32_t r4[4];
                ldsm4(r4, sBl + soff(wn * 32 + nb * 16 + rl, chunk));
                bl[2 * nb][0] = r4[0]; bl[2 * nb + 1][0] = r4[1];
                bl[2 * nb][1] = r4[2]; bl[2 * nb + 1][1] = r4[3];
            }
            // pass 2: hi*lo
            #pragma unroll
            for (int mi = 0; mi < 4; mi++)
                #pragma unroll
                for (int nj = 0; nj < 4; nj++)
                    mma16816(acc[mi][nj], ah[mi], bl[nj]);

            #pragma unroll
            for (int mi = 0; mi < 4; mi++)
                ldsm4(al[mi], sAl + soff(wm * 64 + mi * 16 + rl, chunk));
            // pass 3: lo*hi
            #pragma unroll
            for (int mi = 0; mi < 4; mi++)
                #pragma unroll
                for (int nj = 0; nj < 4; nj++)
                    mma16816(acc[mi][nj], al[mi], bh[nj]);
        }
        __syncthreads();

        if (it + 3 < nst) {
            ldstage(it + 3);
            CP_COMMIT();
        }
    }

    const int tg = lane >> 2;
    const int ti = lane & 3;
    #pragma unroll
    for (int mi = 0; mi < 4; mi++) {
        const int row = bm + wm * 64 + mi * 16 + tg;
        #pragma unroll
        for (int nj = 0; nj < 4; nj++) {
            const int col = bn + wn * 32 + nj * 8 + 2 * ti;
            float2 v0 = make_float2(acc[mi][nj][0], acc[mi][nj][1]);
            float2 v1 = make_float2(acc[mi][nj][2], acc[mi][nj][3]);
            *(float2*)&C[(size_t)row * N + col]       = v0;
            *(float2*)&C[(size_t)(row + 8) * N + col] = v1;
        }
    }
}

// ============================================================================
// Tensor-core flash attention, bf16x3, causal, GQA. Pass-major schedule (R5).
// ============================================================================
#define BQ 128
#define BKV 64
#define QMAT 32768
#define KVMAT 16384
#define FSTAGE (4 * KVMAT)
#define FLASH_SMEM (2 * QMAT + 2 * FSTAGE)

__device__ __forceinline__ uint32_t fsw(int r, int c) {
    return (uint32_t)((r << 8) + ((c ^ (r & 7)) << 4));
}
__device__ __forceinline__ uint32_t pack_hi_rz(float p0, float p1, float& lo0, float& lo1) {
    uint32_t u0 = __float_as_uint(p0), u1 = __float_as_uint(p1);
    lo0 = p0 - __uint_as_float(u0 & 0xffff0000u);
    lo1 = p1 - __uint_as_float(u1 & 0xffff0000u);
    return __byte_perm(u0, u1, 0x7632);
}
__device__ __forceinline__ uint32_t pack_rn(float a, float b) {
    __nv_bfloat162 t = __floats2bfloat162_rn(a, b);
    return *(uint32_t*)&t;
}

__global__ void __launch_bounds__(256, 1) flash_tc_kernel(
    const __nv_bfloat16* __restrict__ qh, const __nv_bfloat16* __restrict__ ql,
    const __nv_bfloat16* __restrict__ kh, const __nv_bfloat16* __restrict__ kl,
    const __nv_bfloat16* __restrict__ vh, const __nv_bfloat16* __restrict__ vl,
    __nv_bfloat16* __restrict__ ath, __nv_bfloat16* __restrict__ atl)
{
    extern __shared__ char smc[];
    const uint32_t sb  = (uint32_t)__cvta_generic_to_shared(smc);
    const uint32_t sQh = sb, sQl = sb + QMAT;

    const int tid  = threadIdx.x;
    const int lane = tid & 31;
    const int w    = tid >> 5;
    const int rl   = lane & 15;
    const int rh   = lane >> 4;
    const int tg   = lane >> 2;
    const int ti   = lane & 3;
    const int vro  = (lane & 7) + ((lane >> 3) & 1) * 8;
    const int vco  = lane >> 4;

    const int qt    = gridDim.x - 1 - blockIdx.x;
    const int h     = blockIdx.y;
    const int kvh   = h >> 2;
    const int qbase = qt * BQ;
    const int wrow  = w * 16;

    for (int f = tid; f < 2048; f += 256) {
        const int r = f >> 4, c = f & 15;
        const size_t go = (size_t)(qbase + r) * DIM + h * HDIM + c * 8;
        CP16(sQh + fsw(r, c), qh + go);
        CP16(sQl + fsw(r, c), ql + go);
    }
    CP_COMMIT();

    auto loadKV = [&](int kt) {
        const uint32_t base = sb + 2 * QMAT + (kt & 1) * FSTAGE;
        const int kvb = kt * BKV;
        for (int f = tid; f < 1024; f += 256) {
            const int r = f >> 4, c = f & 15;
            const size_t go = (size_t)(kvb + r) * KVDIM + kvh * HDIM + c * 8;
            const uint32_t so = fsw(r, c);
            CP16(base + so,             kh + go);
            CP16(base + KVMAT + so,     kl + go);
            CP16(base + 2 * KVMAT + so, vh + go);
            CP16(base + 3 * KVMAT + so, vl + go);
        }
    };

    loadKV(0);
    CP_COMMIT();

    float o[16][4];
    #pragma unroll
    for (int i = 0; i < 16; i++)
        #pragma unroll
        for (int r = 0; r < 4; r++) o[i][r] = 0.0f;
    float m0 = -1e30f, m1 = -1e30f, l0 = 0.0f, l1 = 0.0f;
    const float scale = 0.08838834764831843f;
    const int row0 = qbase + wrow + tg;
    const int row1 = row0 + 8;

    const int nkt = 2 * qt + 2;
    for (int kt = 0; kt < nkt; kt++) {
        if (kt + 1 < nkt) { loadKV(kt + 1); CP_COMMIT(); CP_WAIT(1); }
        else              { CP_WAIT(0); }
        __syncthreads();

        const uint32_t base = sb + 2 * QMAT + (kt & 1) * FSTAGE;
        const uint32_t sKh = base, sKl = base + KVMAT;
        const uint32_t sVh = base + 2 * KVMAT, sVl = base + 3 * KVMAT;
        const int kvb = kt * BKV;

        // ---- S = Q K^T, pass-major ----
        float s[8][4];
        #pragma unroll
        for (int i = 0; i < 8; i++)
            #pragma unroll
            for (int r = 0; r < 4; r++) s[i][r] = 0.0f;

        #pragma unroll
        for (int kc = 0; kc < 8; kc++) {
            uint32_t ah[4], al[4];
            ldsm4(ah, sQh + fsw(wrow + rl, 2 * kc + rh));
            ldsm4(al, sQl + fsw(wrow + rl, 2 * kc + rh));

            uint32_t bh[8][2], bl[8][2];
            #pragma unroll
            for (int nb = 0; nb < 4; nb++) {
                uint32_t rk[4], rkl[4];
                ldsm4(rk,  sKh + fsw(nb * 16 + rl, 2 * kc + rh));
                ldsm4(rkl, sKl + fsw(nb * 16 + rl, 2 * kc + rh));
                bh[2 * nb][0]     = rk[0];  bh[2 * nb][1]     = rk[2];
                bh[2 * nb + 1][0] = rk[1];  bh[2 * nb + 1][1] = rk[3];
                bl[2 * nb][0]     = rkl[0]; bl[2 * nb][1]     = rkl[2];
                bl[2 * nb + 1][0] = rkl[1]; bl[2 * nb + 1][1] = rkl[3];
            }
            #pragma unroll
            for (int nj = 0; nj < 8; nj++) mma16816(s[nj], ah, bh[nj]);
            #pragma unroll
            for (int nj = 0; nj < 8; nj++) mma16816(s[nj], ah, bl[nj]);
            #pragma unroll
            for (int nj = 0; nj < 8; nj++) mma16816(s[nj], al, bh[nj]);
        }

        // ---- scale + causal mask ----
        const bool needmask = (kt >= 2 * qt);
        #pragma unroll
        for (int nj = 0; nj < 8; nj++) {
            #pragma unroll
            for (int r = 0; r < 4; r++) {
                float v = s[nj][r] * scale;
                if (needmask) {
                    const int col = kvb + nj * 8 + 2 * ti + (r & 1);
                    const int row = (r & 2) ? row1 : row0;
                    if (col > row) v = -1e30f;
                }
                s[nj][r] = v;
            }
        }

        // ---- online softmax ----
        float mx0 = -1e30f, mx1 = -1e30f;
        #pragma unroll
        for (int nj = 0; nj < 8; nj++) {
            mx0 = fmaxf(mx0, fmaxf(s[nj][0], s[nj][1]));
            mx1 = fmaxf(mx1, fmaxf(s[nj][2], s[nj][3]));
        }
        mx0 = fmaxf(mx0, __shfl_xor_sync(0xffffffffu, mx0, 1));
        mx0 = fmaxf(mx0, __shfl_xor_sync(0xffffffffu, mx0, 2));
        mx1 = fmaxf(mx1, __shfl_xor_sync(0xffffffffu, mx1, 1));
        mx1 = fmaxf(mx1, __shfl_xor_sync(0xffffffffu, mx1, 2));
        const float mn0 = fmaxf(m0, mx0), mn1 = fmaxf(m1, mx1);
        const float cr0 = __expf(m0 - mn0), cr1 = __expf(m1 - mn1);
        m0 = mn0; m1 = mn1;

        float sum0 = 0.0f, sum1 = 0.0f;
        #pragma unroll
        for (int nj = 0; nj < 8; nj++) {
            s[nj][0] = __expf(s[nj][0] - mn0); sum0 += s[nj][0];
            s[nj][1] = __expf(s[nj][1] - mn0); sum0 += s[nj][1];
            s[nj][2] = __expf(s[nj][2] - mn1); sum1 += s[nj][2];
            s[nj][3] = __expf(s[nj][3] - mn1); sum1 += s[nj][3];
        }
        sum0 += __shfl_xor_sync(0xffffffffu, sum0, 1);
        sum0 += __shfl_xor_sync(0xffffffffu, sum0, 2);
        sum1 += __shfl_xor_sync(0xffffffffu, sum1, 1);
        sum1 += __shfl_xor_sync(0xffffffffu, sum1, 2);
        l0 = l0 * cr0 + sum0;
        l1 = l1 * cr1 + sum1;

        #pragma unroll
        for (int nj = 0; nj < 16; nj++) {
            o[nj][0] *= cr0; o[nj][1] *= cr0;
            o[nj][2] *= cr1; o[nj][3] *= cr1;
        }

        // ---- O += P V, pass-major over halves ----
        #pragma unroll
        for (int kc = 0; kc < 4; kc++) {
            uint32_t pah[4], pal[4];
            {
                float la, lb;
                pah[0] = pack_hi_rz(s[2 * kc][0],     s[2 * kc][1],     la, lb); pal[0] = pack_rn(la, lb);
                pah[1] = pack_hi_rz(s[2 * kc][2],     s[2 * kc][3],     la, lb); pal[1] = pack_rn(la, lb);
                pah[2] = pack_hi_rz(s[2 * kc + 1][0], s[2 * kc + 1][1], la, lb); pal[2] = pack_rn(la, lb);
                pah[3] = pack_hi_rz(s[2 * kc + 1][2], s[2 * kc + 1][3], la, lb); pal[3] = pack_rn(la, lb);
            }
            #pragma unroll
            for (int half = 0; half < 2; half++) {
                uint32_t bv[8][2], cv[8][2];
                #pragma unroll
                for (int n4 = 0; n4 < 4; n4++) {
                    const int nb = half * 4 + n4;
                    uint32_t rv[4], rw[4];
                    const uint32_t so = fsw(kc * 16 + vro, 2 * nb + vco);
                    ldsm4t(rv, sVh + so);
                    ldsm4t(rw, sVl + so);
                    bv[2 * n4][0]     = rv[0]; bv[2 * n4][1]     = rv[1];
                    bv[2 * n4 + 1][0] = rv[2]; bv[2 * n4 + 1][1] = rv[3];
                    cv[2 * n4][0]     = rw[0]; cv[2 * n4][1]     = rw[1];
                    cv[2 * n4 + 1][0] = rw[2]; cv[2 * n4 + 1][1] = rw[3];
                }
                #pragma unroll
                for (int j = 0; j < 8; j++) mma16816(o[8 * half + j], pah, bv[j]);
                #pragma unroll
                for (int j = 0; j < 8; j++) mma16816(o[8 * half + j], pah, cv[j]);
                #pragma unroll
                for (int j = 0; j < 8; j++) mma16816(o[8 * half + j], pal, bv[j]);
            }
        }
        __syncthreads();
    }

    // ---- epilogue: normalize, split hi/lo, store ----
    const float inv0 = 1.0f / l0, inv1 = 1.0f / l1;
    #pragma unroll
    for (int nj = 0; nj < 16; nj++) {
        const int col = h * HDIM + nj * 8 + 2 * ti;
        float v0 = o[nj][0] * inv0, v1 = o[nj][1] * inv0;
        float v2 = o[nj][2] * inv1, v3 = o[nj][3] * inv1;
        __nv_bfloat162 h0 = __floats2bfloat162_rn(v0, v1);
        __nv_bfloat162 h1 = __floats2bfloat162_rn(v2, v3);
        __nv_bfloat162 e0 = __floats2bfloat162_rn(v0 - __low2float(h0), v1 - __high2float(h0));
        __nv_bfloat162 e1 = __floats2bfloat162_rn(v2 - __low2float(h1), v3 - __high2float(h1));
        *(uint32_t*)&ath[(size_t)row0 * DIM + col] = *(uint32_t*)&h0;
        *(uint32_t*)&ath[(size_t)row1 * DIM + col] = *(uint32_t*)&h1;
        *(uint32_t*)&atl[(size_t)row0 * DIM + col] = *(uint32_t*)&e0;
        *(uint32_t*)&atl[(size_t)row1 * DIM + col] = *(uint32_t*)&e1;
    }
}

// ============================================================================
// launch
// ============================================================================
extern "C" void kernel_launch(void* const* d_in, const int* in_sizes, int n_in,
                              void* d_out, int out_size)
{
    (void)in_sizes; (void)n_in; (void)out_size;
    const float* x  = (const float*)d_in[0];
    const float* wq = (const float*)d_in[1];
    const float* wk = (const float*)d_in[2];
    const float* wv = (const float*)d_in[3];
    const float* wo = (const float*)d_in[4];
    const float* fc = (const float*)d_in[5];
    const float* fs = (const float*)d_in[6];
    float* out = (float*)d_out;

    float *xq, *xk, *xv;
    __nv_bfloat16 *xh, *xl, *wqh, *wql, *wkh, *wkl, *wvh, *wvl, *woh, *wol;
    __nv_bfloat16 *ath, *atl, *qh, *ql, *kh, *kl, *vh, *vl;
    cudaGetSymbolAddress((void**)&xq, g_xq);
    cudaGetSymbolAddress((void**)&xk, g_xk);
    cudaGetSymbolAddress((void**)&xv, g_xv);
    cudaGetSymbolAddress((void**)&xh,  g_xh);  cudaGetSymbolAddress((void**)&xl,  g_xl);
    cudaGetSymbolAddress((void**)&wqh, g_wqh); cudaGetSymbolAddress((void**)&wql, g_wql);
    cudaGetSymbolAddress((void**)&wkh, g_wkh); cudaGetSymbolAddress((void**)&wkl, g_wkl);
    cudaGetSymbolAddress((void**)&wvh, g_wvh); cudaGetSymbolAddress((void**)&wvl, g_wvl);
    cudaGetSymbolAddress((void**)&woh, g_woh); cudaGetSymbolAddress((void**)&wol, g_wol);
    cudaGetSymbolAddress((void**)&ath, g_ath); cudaGetSymbolAddress((void**)&atl, g_atl);
    cudaGetSymbolAddress((void**)&qh,  g_qh);  cudaGetSymbolAddress((void**)&ql,  g_ql);
    cudaGetSymbolAddress((void**)&kh,  g_kh);  cudaGetSymbolAddress((void**)&kl,  g_kl);
    cudaGetSymbolAddress((void**)&vh,  g_vh);  cudaGetSymbolAddress((void**)&vl,  g_vl);

    cudaFuncSetAttribute(gemm_bf16x3_kernel,
                         cudaFuncAttributeMaxDynamicSharedMemorySize, GEMM_SMEM);
    cudaFuncSetAttribute(flash_tc_kernel,
                         cudaFuncAttributeMaxDynamicSharedMemorySize, FLASH_SMEM);

    // 0) split inputs to bf16 hi/lo (4 launches: x, wq, wk+wv fused, wo)
    split_kernel<<<dim3((SEQ * DIM / 4 + 255) / 256, 1), 256>>>(
        x, xh, xl, nullptr, nullptr, nullptr, SEQ * DIM / 4);
    split_kernel<<<dim3((DIM * DIM / 4 + 255) / 256, 1), 256>>>(
        wq, wqh, wql, nullptr, nullptr, nullptr, DIM * DIM / 4);
    split_kernel<<<dim3((KVDIM * DIM / 4 + 255) / 256, 2), 256>>>(
        wk, wkh, wkl, wv, wvh, wvl, KVDIM * DIM / 4);
    split_kernel<<<dim3((DIM * DIM / 4 + 255) / 256, 1), 256>>>(
        wo, woh, wol, nullptr, nullptr, nullptr, DIM * DIM / 4);

    // 1) fused Q + K + V projections in ONE launch (column-group dispatch)
    gemm_bf16x3_kernel<<<dim3((DIM + 2 * KVDIM) / GBN, SEQ / GBM, 1), 256, GEMM_SMEM>>>(
        xh, xl,
        wqh, wql, xq, DIM,
        wkh, wkl, xk, KVDIM,
        wvh, wvl, xv,
        DIM);

    // 2) RoPE + split to bf16 hi/lo; split V
    {
        const int nq = SEQ * HEADS * (HDIM / 2);
        rope_split_kernel<<<(nq + 255) / 256, 256>>>(xq, fc, fs, qh, ql, HEADS);
        const int nk = SEQ * KVHEADS * (HDIM / 2);
        rope_split_kernel<<<(nk + 255) / 256, 256>>>(xk, fc, fs, kh, kl, KVHEADS);
        split_kernel<<<dim3((SEQ * KVDIM / 4 + 255) / 256, 1), 256>>>(
            xv, vh, vl, nullptr, nullptr, nullptr, SEQ * KVDIM / 4);
    }

    // 3) tensor-core flash attention -> attn hi/lo
    flash_tc_kernel<<<dim3(SEQ / BQ, HEADS), 256, FLASH_SMEM>>>(
        qh, ql, kh, kl, vh, vl, ath, atl);

    // 4) O projection (single column group)
    gemm_bf16x3_kernel<<<dim3(DIM / GBN, SEQ / GBM, 1), 256, GEMM_SMEM>>>(
        ath, atl,
        woh, wol, out, DIM,
        nullptr, nullptr, nullptr, 0,
        nullptr, nullptr, nullptr,
        DIM);
}

// round 9
// speedup vs baseline: 1.6520x; 1.0227x over previous
#include <cuda_runtime.h>
#include <cuda_bf16.h>
#include <cstdint>
#include <cstddef>

#define DIM     4096
#define SEQ     2048
#define HEADS   32
#define KVHEADS 8
#define HDIM    128
#define KVDIM   1024   // KVHEADS*HDIM

// ------------------------- scratch (static, no allocation) -------------------
__device__ __nv_bfloat16 g_xh[SEQ * DIM],    g_xl[SEQ * DIM];
__device__ __nv_bfloat16 g_wqh[DIM * DIM],   g_wql[DIM * DIM];
__device__ __nv_bfloat16 g_wkh[KVDIM * DIM], g_wkl[KVDIM * DIM];
__device__ __nv_bfloat16 g_wvh[KVDIM * DIM], g_wvl[KVDIM * DIM];
__device__ __nv_bfloat16 g_woh[DIM * DIM],   g_wol[DIM * DIM];
__device__ __nv_bfloat16 g_ath[SEQ * DIM],   g_atl[SEQ * DIM];
__device__ __nv_bfloat16 g_qh[SEQ * DIM],    g_ql[SEQ * DIM];
__device__ __nv_bfloat16 g_kh[SEQ * KVDIM],  g_kl[SEQ * KVDIM];
__device__ __nv_bfloat16 g_vh[SEQ * KVDIM],  g_vl[SEQ * KVDIM];

// ============================================================================
// split: fp32 -> bf16 hi + bf16 lo. blockIdx.y==1 switches to (x2, hi2, lo2).
// ============================================================================
__global__ void split_kernel(const float* __restrict__ x,
                             __nv_bfloat16* __restrict__ hi,
                             __nv_bfloat16* __restrict__ lo,
                             const float* __restrict__ x2,
                             __nv_bfloat16* __restrict__ hi2,
                             __nv_bfloat16* __restrict__ lo2, int n4)
{
    const int i = blockIdx.x * blockDim.x + threadIdx.x;
    if (i >= n4) return;
    if (blockIdx.y == 1) { x = x2; hi = hi2; lo = lo2; }
    float4 v = ((const float4*)x)[i];
    __nv_bfloat16 h0 = __float2bfloat16(v.x);
    __nv_bfloat16 h1 = __float2bfloat16(v.y);
    __nv_bfloat16 h2 = __float2bfloat16(v.z);
    __nv_bfloat16 h3 = __float2bfloat16(v.w);
    __nv_bfloat16 l0 = __float2bfloat16(v.x - __bfloat162float(h0));
    __nv_bfloat16 l1 = __float2bfloat16(v.y - __bfloat162float(h1));
    __nv_bfloat16 l2 = __float2bfloat16(v.z - __bfloat162float(h2));
    __nv_bfloat16 l3 = __float2bfloat16(v.w - __bfloat162float(h3));
    __nv_bfloat162 hp0 = __halves2bfloat162(h0, h1);
    __nv_bfloat162 hp1 = __halves2bfloat162(h2, h3);
    __nv_bfloat162 lp0 = __halves2bfloat162(l0, l1);
    __nv_bfloat162 lp1 = __halves2bfloat162(l2, l3);
    uint2 hv, lv;
    hv.x = *(uint32_t*)&hp0; hv.y = *(uint32_t*)&hp1;
    lv.x = *(uint32_t*)&lp0; lv.y = *(uint32_t*)&lp1;
    ((uint2*)hi)[i] = hv;
    ((uint2*)lo)[i] = lv;
}

// ============================================================================
// shared mma helpers
// ============================================================================
__device__ __forceinline__ void ldsm4(uint32_t* r, uint32_t addr) {
    asm volatile("ldmatrix.sync.aligned.m8n8.x4.shared.b16 {%0,%1,%2,%3}, [%4];"
                 : "=r"(r[0]), "=r"(r[1]), "=r"(r[2]), "=r"(r[3]) : "r"(addr));
}
__device__ __forceinline__ void ldsm4t(uint32_t* r, uint32_t addr) {
    asm volatile("ldmatrix.sync.aligned.m8n8.x4.trans.shared.b16 {%0,%1,%2,%3}, [%4];"
                 : "=r"(r[0]), "=r"(r[1]), "=r"(r[2]), "=r"(r[3]) : "r"(addr));
}
__device__ __forceinline__ void mma16816(float* c, const uint32_t* a, const uint32_t* b) {
    asm volatile("mma.sync.aligned.m16n8k16.row.col.f32.bf16.bf16.f32 "
                 "{%0,%1,%2,%3},{%4,%5,%6,%7},{%8,%9},{%0,%1,%2,%3};"
                 : "+f"(c[0]), "+f"(c[1]), "+f"(c[2]), "+f"(c[3])
                 : "r"(a[0]), "r"(a[1]), "r"(a[2]), "r"(a[3]), "r"(b[0]), "r"(b[1]));
}

#define CP16(dst, src) asm volatile("cp.async.cg.shared.global [%0], [%1], 16;" :: "r"(dst), "l"(src))
#define CP_COMMIT()    asm volatile("cp.async.commit_group;")
#define CP_WAIT(n)     asm volatile("cp.async.wait_group %0;" :: "n"(n))

// smem byte offset with XOR swizzle (row stride 64B, 16B chunks)
__device__ __forceinline__ uint32_t soff(int row, int chunk) {
    return (uint32_t)((row << 6) + ((chunk ^ ((row >> 1) & 3)) << 4));
}

// split pair -> hi/lo bf16x2 words
__device__ __forceinline__ void split2(float a, float b, uint32_t& h, uint32_t& l) {
    __nv_bfloat162 hp = __floats2bfloat162_rn(a, b);
    __nv_bfloat162 lp = __floats2bfloat162_rn(a - __low2float(hp), b - __high2float(hp));
    h = *(uint32_t*)&hp;
    l = *(uint32_t*)&lp;
}

// ============================================================================
// bf16x3 tensor-core GEMM:  C[M,N](fp32) = A[M,K] * B[N,K]^T
// 128x128x32 CTA tile, 256 thr, warp tile 64x32, 3-stage cp.async pipeline
// with SINGLE barrier per k-iter and refill issued BEFORE compute.
// Column-group dispatch: up to 3 concatenated output matrices sharing A.
// Epilogue modes per group: 0 = fp32 store, 1 = rope + bf16 hi/lo, 2 = bf16 hi/lo.
// ============================================================================
#define GBM 128
#define GBN 128
#define GBK 32
#define SMAT 8192                   // one 128x32 bf16 matrix (64B rows)
#define GSTAGE (4 * SMAT)           // Ah, Al, Bh, Bl = 32KB
#define GEMM_SMEM (3 * GSTAGE)      // 96KB -> 2 CTAs/SM

__global__ void __launch_bounds__(256, 2) gemm_bf16x3_kernel(
    const __nv_bfloat16* __restrict__ Ah, const __nv_bfloat16* __restrict__ Al,
    const __nv_bfloat16* B0h, const __nv_bfloat16* B0l, void* C0h, void* C0l, int N0, int mode0,
    const __nv_bfloat16* B1h, const __nv_bfloat16* B1l, void* C1h, void* C1l, int N1, int mode1,
    const __nv_bfloat16* B2h, const __nv_bfloat16* B2l, void* C2h, void* C2l, int mode2,
    const float* __restrict__ fc, const float* __restrict__ fs, int K)
{
    // column-group selection (uniform per CTA)
    const int bng = blockIdx.x * GBN;
    const __nv_bfloat16 *Bh, *Bl;
    void *Ch, *Cl;
    int N, bn, mode;
    if (bng < N0)           { Bh = B0h; Bl = B0l; Ch = C0h; Cl = C0l; N = N0; bn = bng; mode = mode0; }
    else if (bng < N0 + N1) { Bh = B1h; Bl = B1l; Ch = C1h; Cl = C1l; N = N1; bn = bng - N0; mode = mode1; }
    else                    { Bh = B2h; Bl = B2l; Ch = C2h; Cl = C2l; N = N1; bn = bng - N0 - N1; mode = mode2; }

    extern __shared__ char smem[];
    const int tid  = threadIdx.x;
    const int lane = tid & 31;
    const int w    = tid >> 5;
    const int wm   = w >> 2;
    const int wn   = w & 3;
    const int bm   = blockIdx.y * GBM;

    const int lrow = tid >> 2;        // 0..63
    const int lc   = tid & 3;

    float acc[4][4][4];
    #pragma unroll
    for (int i = 0; i < 4; i++)
        #pragma unroll
        for (int j = 0; j < 4; j++)
            #pragma unroll
            for (int r = 0; r < 4; r++) acc[i][j][r] = 0.0f;

    const uint32_t sbase = (uint32_t)__cvta_generic_to_shared(smem);

    auto ldstage = [&](int s) {
        const uint32_t buf = sbase + (uint32_t)(s % 3) * GSTAGE;
        const int k0 = s * GBK;
        const __nv_bfloat16* ga  = Ah + (size_t)(bm + lrow) * K + k0 + lc * 8;
        const __nv_bfloat16* gal = Al + (size_t)(bm + lrow) * K + k0 + lc * 8;
        const __nv_bfloat16* gb  = Bh + (size_t)(bn + lrow) * K + k0 + lc * 8;
        const __nv_bfloat16* gbl = Bl + (size_t)(bn + lrow) * K + k0 + lc * 8;
        const uint32_t so0 = soff(lrow, lc);
        const uint32_t so1 = soff(lrow + 64, lc);
        CP16(buf + so0,            ga);
        CP16(buf + so1,            ga + (size_t)64 * K);
        CP16(buf + SMAT + so0,     gal);
        CP16(buf + SMAT + so1,     gal + (size_t)64 * K);
        CP16(buf + 2 * SMAT + so0, gb);
        CP16(buf + 2 * SMAT + so1, gb + (size_t)64 * K);
        CP16(buf + 3 * SMAT + so0, gbl);
        CP16(buf + 3 * SMAT + so1, gbl + (size_t)64 * K);
    };

    const int nst = K / GBK;
    ldstage(0); CP_COMMIT();
    ldstage(1); CP_COMMIT();

    const int rl = lane & 15;
    const int rh = lane >> 4;

    for (int it = 0; it < nst; ++it) {
        if (it < nst - 1) { CP_WAIT(1); } else { CP_WAIT(0); }
        __syncthreads();

        // early refill: buffer (it+2)%3 == (it-1)%3 was consumed last iter,
        // and every warp is past this iteration's barrier => safe to overwrite.
        if (it + 2 < nst) {
            ldstage(it + 2);
            CP_COMMIT();
        }

        const uint32_t buf = sbase + (uint32_t)(it % 3) * GSTAGE;
        const uint32_t sAh = buf;
        const uint32_t sAl = buf + SMAT;
        const uint32_t sBh = buf + 2 * SMAT;
        const uint32_t sBl = buf + 3 * SMAT;

        #pragma unroll
        for (int ks = 0; ks < 2; ks++) {
            const int chunk = 2 * ks + rh;
            uint32_t ah[4][4], al[4][4], bh[4][2], bl[4][2];

            #pragma unroll
            for (int mi = 0; mi < 4; mi++)
                ldsm4(ah[mi], sAh + soff(wm * 64 + mi * 16 + rl, chunk));
            #pragma unroll
            for (int nb = 0; nb < 2; nb++) {
                uint32_t r4[4];
                ldsm4(r4, sBh + soff(wn * 32 + nb * 16 + rl, chunk));
                bh[2 * nb][0] = r4[0]; bh[2 * nb + 1][0] = r4[1];
                bh[2 * nb][1] = r4[2]; bh[2 * nb + 1][1] = r4[3];
            }
            // pass 1: hi*hi (16 independent chains)
            #pragma unroll
            for (int mi = 0; mi < 4; mi++)
                #pragma unroll
                for (int nj = 0; nj < 4; nj++)
                    mma16816(acc[mi][nj], ah[mi], bh[nj]);

            #pragma unroll
            for (int nb = 0; nb < 2; nb++) {
                uint32_t r4[4];
                ldsm4(r4, sBl + soff(wn * 32 + nb * 16 + rl, chunk));
                bl[2 * nb][0] = r4[0]; bl[2 * nb + 1][0] = r4[1];
                bl[2 * nb][1] = r4[2]; bl[2 * nb + 1][1] = r4[3];
            }
            // pass 2: hi*lo
            #pragma unroll
            for (int mi = 0; mi < 4; mi++)
                #pragma unroll
                for (int nj = 0; nj < 4; nj++)
                    mma16816(acc[mi][nj], ah[mi], bl[nj]);

            #pragma unroll
            for (int mi = 0; mi < 4; mi++)
                ldsm4(al[mi], sAl + soff(wm * 64 + mi * 16 + rl, chunk));
            // pass 3: lo*hi
            #pragma unroll
            for (int mi = 0; mi < 4; mi++)
                #pragma unroll
                for (int nj = 0; nj < 4; nj++)
                    mma16816(acc[mi][nj], al[mi], bh[nj]);
        }
        __syncthreads();   // all warps done reading buf(it) before next-iter refill
    }

    // ---------------- epilogue ----------------
    const int tg = lane >> 2;
    const int ti = lane & 3;
    if (mode == 0) {
        float* C = (float*)Ch;
        #pragma unroll
        for (int mi = 0; mi < 4; mi++) {
            const int row = bm + wm * 64 + mi * 16 + tg;
            #pragma unroll
            for (int nj = 0; nj < 4; nj++) {
                const int col = bn + wn * 32 + nj * 8 + 2 * ti;
                *(float2*)&C[(size_t)row * N + col]       = make_float2(acc[mi][nj][0], acc[mi][nj][1]);
                *(float2*)&C[(size_t)(row + 8) * N + col] = make_float2(acc[mi][nj][2], acc[mi][nj][3]);
            }
        }
    } else {
        __nv_bfloat16* Hi = (__nv_bfloat16*)Ch;
        __nv_bfloat16* Lo = (__nv_bfloat16*)Cl;
        #pragma unroll
        for (int mi = 0; mi < 4; mi++) {
            const int row = bm + wm * 64 + mi * 16 + tg;
            #pragma unroll
            for (int nj = 0; nj < 4; nj++) {
                const int col = bn + wn * 32 + nj * 8 + 2 * ti;
                float a0 = acc[mi][nj][0], a1 = acc[mi][nj][1];
                float a2 = acc[mi][nj][2], a3 = acc[mi][nj][3];
                if (mode == 1) {
                    const int p = (col & 127) >> 1;
                    const float c0 = fc[row * 64 + p],       s0 = fs[row * 64 + p];
                    const float c1 = fc[(row + 8) * 64 + p], s1 = fs[(row + 8) * 64 + p];
                    float r0 = a0 * c0 - a1 * s0, r1 = a0 * s0 + a1 * c0;
                    float r2 = a2 * c1 - a3 * s1, r3 = a2 * s1 + a3 * c1;
                    a0 = r0; a1 = r1; a2 = r2; a3 = r3;
                }
                uint32_t h0, l0, h1, l1;
                split2(a0, a1, h0, l0);
                split2(a2, a3, h1, l1);
                *(uint32_t*)&Hi[(size_t)row * N + col]       = h0;
                *(uint32_t*)&Lo[(size_t)row * N + col]       = l0;
                *(uint32_t*)&Hi[(size_t)(row + 8) * N + col] = h1;
                *(uint32_t*)&Lo[(size_t)(row + 8) * N + col] = l1;
            }
        }
    }
}

// ============================================================================
// Tensor-core flash attention, bf16x3, causal, GQA. Pass-major schedule.
// ============================================================================
#define BQ 128
#define BKV 64
#define QMAT 32768
#define KVMAT 16384
#define FSTAGE (4 * KVMAT)
#define FLASH_SMEM (2 * QMAT + 2 * FSTAGE)

__device__ __forceinline__ uint32_t fsw(int r, int c) {
    return (uint32_t)((r << 8) + ((c ^ (r & 7)) << 4));
}
__device__ __forceinline__ uint32_t pack_hi_rz(float p0, float p1, float& lo0, float& lo1) {
    uint32_t u0 = __float_as_uint(p0), u1 = __float_as_uint(p1);
    lo0 = p0 - __uint_as_float(u0 & 0xffff0000u);
    lo1 = p1 - __uint_as_float(u1 & 0xffff0000u);
    return __byte_perm(u0, u1, 0x7632);
}
__device__ __forceinline__ uint32_t pack_rn(float a, float b) {
    __nv_bfloat162 t = __floats2bfloat162_rn(a, b);
    return *(uint32_t*)&t;
}

__global__ void __launch_bounds__(256, 1) flash_tc_kernel(
    const __nv_bfloat16* __restrict__ qh, const __nv_bfloat16* __restrict__ ql,
    const __nv_bfloat16* __restrict__ kh, const __nv_bfloat16* __restrict__ kl,
    const __nv_bfloat16* __restrict__ vh, const __nv_bfloat16* __restrict__ vl,
    __nv_bfloat16* __restrict__ ath, __nv_bfloat16* __restrict__ atl)
{
    extern __shared__ char smc[];
    const uint32_t sb  = (uint32_t)__cvta_generic_to_shared(smc);
    const uint32_t sQh = sb, sQl = sb + QMAT;

    const int tid  = threadIdx.x;
    const int lane = tid & 31;
    const int w    = tid >> 5;
    const int rl   = lane & 15;
    const int rh   = lane >> 4;
    const int tg   = lane >> 2;
    const int ti   = lane & 3;
    const int vro  = (lane & 7) + ((lane >> 3) & 1) * 8;
    const int vco  = lane >> 4;

    const int qt    = gridDim.x - 1 - blockIdx.x;
    const int h     = blockIdx.y;
    const int kvh   = h >> 2;
    const int qbase = qt * BQ;
    const int wrow  = w * 16;

    for (int f = tid; f < 2048; f += 256) {
        const int r = f >> 4, c = f & 15;
        const size_t go = (size_t)(qbase + r) * DIM + h * HDIM + c * 8;
        CP16(sQh + fsw(r, c), qh + go);
        CP16(sQl + fsw(r, c), ql + go);
    }
    CP_COMMIT();

    auto loadKV = [&](int kt) {
        const uint32_t base = sb + 2 * QMAT + (kt & 1) * FSTAGE;
        const int kvb = kt * BKV;
        for (int f = tid; f < 1024; f += 256) {
            const int r = f >> 4, c = f & 15;
            const size_t go = (size_t)(kvb + r) * KVDIM + kvh * HDIM + c * 8;
            const uint32_t so = fsw(r, c);
            CP16(base + so,             kh + go);
            CP16(base + KVMAT + so,     kl + go);
            CP16(base + 2 * KVMAT + so, vh + go);
            CP16(base + 3 * KVMAT + so, vl + go);
        }
    };

    loadKV(0);
    CP_COMMIT();

    float o[16][4];
    #pragma unroll
    for (int i = 0; i < 16; i++)
        #pragma unroll
        for (int r = 0; r < 4; r++) o[i][r] = 0.0f;
    float m0 = -1e30f, m1 = -1e30f, l0 = 0.0f, l1 = 0.0f;
    const float scale = 0.08838834764831843f;
    const int row0 = qbase + wrow + tg;
    const int row1 = row0 + 8;

    const int nkt = 2 * qt + 2;
    for (int kt = 0; kt < nkt; kt++) {
        if (kt + 1 < nkt) { loadKV(kt + 1); CP_COMMIT(); CP_WAIT(1); }
        else              { CP_WAIT(0); }
        __syncthreads();

        const uint32_t base = sb + 2 * QMAT + (kt & 1) * FSTAGE;
        const uint32_t sKh = base, sKl = base + KVMAT;
        const uint32_t sVh = base + 2 * KVMAT, sVl = base + 3 * KVMAT;
        const int kvb = kt * BKV;

        // ---- S = Q K^T, pass-major ----
        float s[8][4];
        #pragma unroll
        for (int i = 0; i < 8; i++)
            #pragma unroll
            for (int r = 0; r < 4; r++) s[i][r] = 0.0f;

        #pragma unroll
        for (int kc = 0; kc < 8; kc++) {
            uint32_t ah[4], al[4];
            ldsm4(ah, sQh + fsw(wrow + rl, 2 * kc + rh));
            ldsm4(al, sQl + fsw(wrow + rl, 2 * kc + rh));

            uint32_t bh[8][2], bl[8][2];
            #pragma unroll
            for (int nb = 0; nb < 4; nb++) {
                uint32_t rk[4], rkl[4];
                ldsm4(rk,  sKh + fsw(nb * 16 + rl, 2 * kc + rh));
                ldsm4(rkl, sKl + fsw(nb * 16 + rl, 2 * kc + rh));
                bh[2 * nb][0]     = rk[0];  bh[2 * nb][1]     = rk[2];
                bh[2 * nb + 1][0] = rk[1];  bh[2 * nb + 1][1] = rk[3];
                bl[2 * nb][0]     = rkl[0]; bl[2 * nb][1]     = rkl[2];
                bl[2 * nb + 1][0] = rkl[1]; bl[2 * nb + 1][1] = rkl[3];
            }
            #pragma unroll
            for (int nj = 0; nj < 8; nj++) mma16816(s[nj], ah, bh[nj]);
            #pragma unroll
            for (int nj = 0; nj < 8; nj++) mma16816(s[nj], ah, bl[nj]);
            #pragma unroll
            for (int nj = 0; nj < 8; nj++) mma16816(s[nj], al, bh[nj]);
        }

        // ---- scale + causal mask ----
        const bool needmask = (kt >= 2 * qt);
        #pragma unroll
        for (int nj = 0; nj < 8; nj++) {
            #pragma unroll
            for (int r = 0; r < 4; r++) {
                float v = s[nj][r] * scale;
                if (needmask) {
                    const int col = kvb + nj * 8 + 2 * ti + (r & 1);
                    const int row = (r & 2) ? row1 : row0;
                    if (col > row) v = -1e30f;
                }
                s[nj][r] = v;
            }
        }

        // ---- online softmax ----
        float mx0 = -1e30f, mx1 = -1e30f;
        #pragma unroll
        for (int nj = 0; nj < 8; nj++) {
            mx0 = fmaxf(mx0, fmaxf(s[nj][0], s[nj][1]));
            mx1 = fmaxf(mx1, fmaxf(s[nj][2], s[nj][3]));
        }
        mx0 = fmaxf(mx0, __shfl_xor_sync(0xffffffffu, mx0, 1));
        mx0 = fmaxf(mx0, __shfl_xor_sync(0xffffffffu, mx0, 2));
        mx1 = fmaxf(mx1, __shfl_xor_sync(0xffffffffu, mx1, 1));
        mx1 = fmaxf(mx1, __shfl_xor_sync(0xffffffffu, mx1, 2));
        const float mn0 = fmaxf(m0, mx0), mn1 = fmaxf(m1, mx1);
        const float cr0 = __expf(m0 - mn0), cr1 = __expf(m1 - mn1);
        m0 = mn0; m1 = mn1;

        float sum0 = 0.0f, sum1 = 0.0f;
        #pragma unroll
        for (int nj = 0; nj < 8; nj++) {
            s[nj][0] = __expf(s[nj][0] - mn0); sum0 += s[nj][0];
            s[nj][1] = __expf(s[nj][1] - mn0); sum0 += s[nj][1];
            s[nj][2] = __expf(s[nj][2] - mn1); sum1 += s[nj][2];
            s[nj][3] = __expf(s[nj][3] - mn1); sum1 += s[nj][3];
        }
        sum0 += __shfl_xor_sync(0xffffffffu, sum0, 1);
        sum0 += __shfl_xor_sync(0xffffffffu, sum0, 2);
        sum1 += __shfl_xor_sync(0xffffffffu, sum1, 1);
        sum1 += __shfl_xor_sync(0xffffffffu, sum1, 2);
        l0 = l0 * cr0 + sum0;
        l1 = l1 * cr1 + sum1;

        #pragma unroll
        for (int nj = 0; nj < 16; nj++) {
            o[nj][0] *= cr0; o[nj][1] *= cr0;
            o[nj][2] *= cr1; o[nj][3] *= cr1;
        }

        // ---- O += P V, pass-major over halves ----
        #pragma unroll
        for (int kc = 0; kc < 4; kc++) {
            uint32_t pah[4], pal[4];
            {
                float la, lb;
                pah[0] = pack_hi_rz(s[2 * kc][0],     s[2 * kc][1],     la, lb); pal[0] = pack_rn(la, lb);
                pah[1] = pack_hi_rz(s[2 * kc][2],     s[2 * kc][3],     la, lb); pal[1] = pack_rn(la, lb);
                pah[2] = pack_hi_rz(s[2 * kc + 1][0], s[2 * kc + 1][1], la, lb); pal[2] = pack_rn(la, lb);
                pah[3] = pack_hi_rz(s[2 * kc + 1][2], s[2 * kc + 1][3], la, lb); pal[3] = pack_rn(la, lb);
            }
            #pragma unroll
            for (int half = 0; half < 2; half++) {
                uint32_t bv[8][2], cv[8][2];
                #pragma unroll
                for (int n4 = 0; n4 < 4; n4++) {
                    const int nb = half * 4 + n4;
                    uint32_t rv[4], rw[4];
                    const uint32_t so = fsw(kc * 16 + vro, 2 * nb + vco);
                    ldsm4t(rv, sVh + so);
                    ldsm4t(rw, sVl + so);
                    bv[2 * n4][0]     = rv[0]; bv[2 * n4][1]     = rv[1];
                    bv[2 * n4 + 1][0] = rv[2]; bv[2 * n4 + 1][1] = rv[3];
                    cv[2 * n4][0]     = rw[0]; cv[2 * n4][1]     = rw[1];
                    cv[2 * n4 + 1][0] = rw[2]; cv[2 * n4 + 1][1] = rw[3];
                }
                #pragma unroll
                for (int j = 0; j < 8; j++) mma16816(o[8 * half + j], pah, bv[j]);
                #pragma unroll
                for (int j = 0; j < 8; j++) mma16816(o[8 * half + j], pah, cv[j]);
                #pragma unroll
                for (int j = 0; j < 8; j++) mma16816(o[8 * half + j], pal, bv[j]);
            }
        }
        __syncthreads();
    }

    // ---- epilogue: normalize, split hi/lo, store ----
    const float inv0 = 1.0f / l0, inv1 = 1.0f / l1;
    #pragma unroll
    for (int nj = 0; nj < 16; nj++) {
        const int col = h * HDIM + nj * 8 + 2 * ti;
        float v0 = o[nj][0] * inv0, v1 = o[nj][1] * inv0;
        float v2 = o[nj][2] * inv1, v3 = o[nj][3] * inv1;
        __nv_bfloat162 h0 = __floats2bfloat162_rn(v0, v1);
        __nv_bfloat162 h1 = __floats2bfloat162_rn(v2, v3);
        __nv_bfloat162 e0 = __floats2bfloat162_rn(v0 - __low2float(h0), v1 - __high2float(h0));
        __nv_bfloat162 e1 = __floats2bfloat162_rn(v2 - __low2float(h1), v3 - __high2float(h1));
        *(uint32_t*)&ath[(size_t)row0 * DIM + col] = *(uint32_t*)&h0;
        *(uint32_t*)&ath[(size_t)row1 * DIM + col] = *(uint32_t*)&h1;
        *(uint32_t*)&atl[(size_t)row0 * DIM + col] = *(uint32_t*)&e0;
        *(uint32_t*)&atl[(size_t)row1 * DIM + col] = *(uint32_t*)&e1;
    }
}

// ============================================================================
// launch
// ============================================================================
extern "C" void kernel_launch(void* const* d_in, const int* in_sizes, int n_in,
                              void* d_out, int out_size)
{
    (void)in_sizes; (void)n_in; (void)out_size;
    const float* x  = (const float*)d_in[0];
    const float* wq = (const float*)d_in[1];
    const float* wk = (const float*)d_in[2];
    const float* wv = (const float*)d_in[3];
    const float* wo = (const float*)d_in[4];
    const float* fc = (const float*)d_in[5];
    const float* fs = (const float*)d_in[6];
    float* out = (float*)d_out;

    __nv_bfloat16 *xh, *xl, *wqh, *wql, *wkh, *wkl, *wvh, *wvl, *woh, *wol;
    __nv_bfloat16 *ath, *atl, *qh, *ql, *kh, *kl, *vh, *vl;
    cudaGetSymbolAddress((void**)&xh,  g_xh);  cudaGetSymbolAddress((void**)&xl,  g_xl);
    cudaGetSymbolAddress((void**)&wqh, g_wqh); cudaGetSymbolAddress((void**)&wql, g_wql);
    cudaGetSymbolAddress((void**)&wkh, g_wkh); cudaGetSymbolAddress((void**)&wkl, g_wkl);
    cudaGetSymbolAddress((void**)&wvh, g_wvh); cudaGetSymbolAddress((void**)&wvl, g_wvl);
    cudaGetSymbolAddress((void**)&woh, g_woh); cudaGetSymbolAddress((void**)&wol, g_wol);
    cudaGetSymbolAddress((void**)&ath, g_ath); cudaGetSymbolAddress((void**)&atl, g_atl);
    cudaGetSymbolAddress((void**)&qh,  g_qh);  cudaGetSymbolAddress((void**)&ql,  g_ql);
    cudaGetSymbolAddress((void**)&kh,  g_kh);  cudaGetSymbolAddress((void**)&kl,  g_kl);
    cudaGetSymbolAddress((void**)&vh,  g_vh);  cudaGetSymbolAddress((void**)&vl,  g_vl);

    cudaFuncSetAttribute(gemm_bf16x3_kernel,
                         cudaFuncAttributeMaxDynamicSharedMemorySize, GEMM_SMEM);
    cudaFuncSetAttribute(flash_tc_kernel,
                         cudaFuncAttributeMaxDynamicSharedMemorySize, FLASH_SMEM);

    // 0) splits: x ; wq+wo fused ; wk+wv fused  (3 launches)
    split_kernel<<<dim3((SEQ * DIM / 4 + 255) / 256, 1), 256>>>(
        x, xh, xl, nullptr, nullptr, nullptr, SEQ * DIM / 4);
    split_kernel<<<dim3((DIM * DIM / 4 + 255) / 256, 2), 256>>>(
        wq, wqh, wql, wo, woh, wol, DIM * DIM / 4);
    split_kernel<<<dim3((KVDIM * DIM / 4 + 255) / 256, 2), 256>>>(
        wk, wkh, wkl, wv, wvh, wvl, KVDIM * DIM / 4);

    // 1) fused Q + K + V projections; epilogue applies RoPE (Q,K) / split (V)
    gemm_bf16x3_kernel<<<dim3((DIM + 2 * KVDIM) / GBN, SEQ / GBM, 1), 256, GEMM_SMEM>>>(
        xh, xl,
        wqh, wql, qh, ql, DIM,   1,
        wkh, wkl, kh, kl, KVDIM, 1,
        wvh, wvl, vh, vl,        2,
        fc, fs, DIM);

    // 2) tensor-core flash attention -> attn hi/lo
    flash_tc_kernel<<<dim3(SEQ / BQ, HEADS), 256, FLASH_SMEM>>>(
        qh, ql, kh, kl, vh, vl, ath, atl);

    // 3) O projection (single group, fp32 store)
    gemm_bf16x3_kernel<<<dim3(DIM / GBN, SEQ / GBM, 1), 256, GEMM_SMEM>>>(
        ath, atl,
        woh, wol, out, nullptr, DIM, 0,
        nullptr, nullptr, nullptr, nullptr, 0, 0,
        nullptr, nullptr, nullptr, nullptr, 0,
        nullptr, nullptr, DIM);
}

// round 11
// speedup vs baseline: 1.6573x; 1.0032x over previous
#include <cuda_runtime.h>
#include <cuda_bf16.h>
#include <cstdint>
#include <cstddef>

#define DIM     4096
#define SEQ     2048
#define HEADS   32
#define KVHEADS 8
#define HDIM    128
#define KVDIM   1024   // KVHEADS*HDIM

// ------------------------- scratch (static, no allocation) -------------------
__device__ __nv_bfloat16 g_xh[SEQ * DIM],    g_xl[SEQ * DIM];
__device__ __nv_bfloat16 g_wqh[DIM * DIM],   g_wql[DIM * DIM];
__device__ __nv_bfloat16 g_wkh[KVDIM * DIM], g_wkl[KVDIM * DIM];
__device__ __nv_bfloat16 g_wvh[KVDIM * DIM], g_wvl[KVDIM * DIM];
__device__ __nv_bfloat16 g_woh[DIM * DIM],   g_wol[DIM * DIM];
__device__ __nv_bfloat16 g_ath[SEQ * DIM],   g_atl[SEQ * DIM];
__device__ __nv_bfloat16 g_qh[SEQ * DIM],    g_ql[SEQ * DIM];
__device__ __nv_bfloat16 g_kh[SEQ * KVDIM],  g_kl[SEQ * KVDIM];
__device__ __nv_bfloat16 g_vh[SEQ * KVDIM],  g_vl[SEQ * KVDIM];

// ============================================================================
// split: fp32 -> bf16 hi + bf16 lo. blockIdx.y==1 switches to (x2, hi2, lo2).
// ============================================================================
__global__ void split_kernel(const float* __restrict__ x,
                             __nv_bfloat16* __restrict__ hi,
                             __nv_bfloat16* __restrict__ lo,
                             const float* __restrict__ x2,
                             __nv_bfloat16* __restrict__ hi2,
                             __nv_bfloat16* __restrict__ lo2, int n4)
{
    const int i = blockIdx.x * blockDim.x + threadIdx.x;
    if (i >= n4) return;
    if (blockIdx.y == 1) { x = x2; hi = hi2; lo = lo2; }
    float4 v = ((const float4*)x)[i];
    __nv_bfloat16 h0 = __float2bfloat16(v.x);
    __nv_bfloat16 h1 = __float2bfloat16(v.y);
    __nv_bfloat16 h2 = __float2bfloat16(v.z);
    __nv_bfloat16 h3 = __float2bfloat16(v.w);
    __nv_bfloat16 l0 = __float2bfloat16(v.x - __bfloat162float(h0));
    __nv_bfloat16 l1 = __float2bfloat16(v.y - __bfloat162float(h1));
    __nv_bfloat16 l2 = __float2bfloat16(v.z - __bfloat162float(h2));
    __nv_bfloat16 l3 = __float2bfloat16(v.w - __bfloat162float(h3));
    __nv_bfloat162 hp0 = __halves2bfloat162(h0, h1);
    __nv_bfloat162 hp1 = __halves2bfloat162(h2, h3);
    __nv_bfloat162 lp0 = __halves2bfloat162(l0, l1);
    __nv_bfloat162 lp1 = __halves2bfloat162(l2, l3);
    uint2 hv, lv;
    hv.x = *(uint32_t*)&hp0; hv.y = *(uint32_t*)&hp1;
    lv.x = *(uint32_t*)&lp0; lv.y = *(uint32_t*)&lp1;
    ((uint2*)hi)[i] = hv;
    ((uint2*)lo)[i] = lv;
}

// ============================================================================
// shared mma helpers
// ============================================================================
__device__ __forceinline__ void ldsm4(uint32_t* r, uint32_t addr) {
    asm volatile("ldmatrix.sync.aligned.m8n8.x4.shared.b16 {%0,%1,%2,%3}, [%4];"
                 : "=r"(r[0]), "=r"(r[1]), "=r"(r[2]), "=r"(r[3]) : "r"(addr));
}
__device__ __forceinline__ void ldsm4t(uint32_t* r, uint32_t addr) {
    asm volatile("ldmatrix.sync.aligned.m8n8.x4.trans.shared.b16 {%0,%1,%2,%3}, [%4];"
                 : "=r"(r[0]), "=r"(r[1]), "=r"(r[2]), "=r"(r[3]) : "r"(addr));
}
__device__ __forceinline__ void mma16816(float* c, const uint32_t* a, const uint32_t* b) {
    asm volatile("mma.sync.aligned.m16n8k16.row.col.f32.bf16.bf16.f32 "
                 "{%0,%1,%2,%3},{%4,%5,%6,%7},{%8,%9},{%0,%1,%2,%3};"
                 : "+f"(c[0]), "+f"(c[1]), "+f"(c[2]), "+f"(c[3])
                 : "r"(a[0]), "r"(a[1]), "r"(a[2]), "r"(a[3]), "r"(b[0]), "r"(b[1]));
}

#define CP16(dst, src) asm volatile("cp.async.cg.shared.global [%0], [%1], 16;" :: "r"(dst), "l"(src))
#define CP_COMMIT()    asm volatile("cp.async.commit_group;")
#define CP_WAIT(n)     asm volatile("cp.async.wait_group %0;" :: "n"(n))

// smem byte offset with XOR swizzle (row stride 64B, 16B chunks)
__device__ __forceinline__ uint32_t soff(int row, int chunk) {
    return (uint32_t)((row << 6) + ((chunk ^ ((row >> 1) & 3)) << 4));
}

// split pair -> hi/lo bf16x2 words
__device__ __forceinline__ void split2(float a, float b, uint32_t& h, uint32_t& l) {
    __nv_bfloat162 hp = __floats2bfloat162_rn(a, b);
    __nv_bfloat162 lp = __floats2bfloat162_rn(a - __low2float(hp), b - __high2float(hp));
    h = *(uint32_t*)&hp;
    l = *(uint32_t*)&lp;
}

// ============================================================================
// bf16x3 tensor-core GEMM:  C[M,N](fp32) = A[M,K] * B[N,K]^T
// 128x128x32 CTA tile, 256 thr, warp tile 64x32, 3-stage cp.async ring.
// Loop order: wait(own groups) -> ONE barrier -> refill(it+2) -> compute(it).
// The wait precedes the barrier (cp.async cross-warp visibility contract);
// the top barrier of iter it also licenses refilling buf((it+2)%3), whose
// last reader was compute(it-1).
// Column-group dispatch: up to 3 concatenated output matrices sharing A.
// Epilogue modes per group: 0 = fp32 store, 1 = rope + bf16 hi/lo, 2 = bf16 hi/lo.
// ============================================================================
#define GBM 128
#define GBN 128
#define GBK 32
#define SMAT 8192                   // one 128x32 bf16 matrix (64B rows)
#define GSTAGE (4 * SMAT)           // Ah, Al, Bh, Bl = 32KB
#define GEMM_SMEM (3 * GSTAGE)      // 96KB -> 2 CTAs/SM

__global__ void __launch_bounds__(256, 2) gemm_bf16x3_kernel(
    const __nv_bfloat16* __restrict__ Ah, const __nv_bfloat16* __restrict__ Al,
    const __nv_bfloat16* B0h, const __nv_bfloat16* B0l, void* C0h, void* C0l, int N0, int mode0,
    const __nv_bfloat16* B1h, const __nv_bfloat16* B1l, void* C1h, void* C1l, int N1, int mode1,
    const __nv_bfloat16* B2h, const __nv_bfloat16* B2l, void* C2h, void* C2l, int mode2,
    const float* __restrict__ fc, const float* __restrict__ fs, int K)
{
    // column-group selection (uniform per CTA)
    const int bng = blockIdx.x * GBN;
    const __nv_bfloat16 *Bh, *Bl;
    void *Ch, *Cl;
    int N, bn, mode;
    if (bng < N0)           { Bh = B0h; Bl = B0l; Ch = C0h; Cl = C0l; N = N0; bn = bng; mode = mode0; }
    else if (bng < N0 + N1) { Bh = B1h; Bl = B1l; Ch = C1h; Cl = C1l; N = N1; bn = bng - N0; mode = mode1; }
    else                    { Bh = B2h; Bl = B2l; Ch = C2h; Cl = C2l; N = N1; bn = bng - N0 - N1; mode = mode2; }

    extern __shared__ char smem[];
    const int tid  = threadIdx.x;
    const int lane = tid & 31;
    const int w    = tid >> 5;
    const int wm   = w >> 2;
    const int wn   = w & 3;
    const int bm   = blockIdx.y * GBM;

    const int lrow = tid >> 2;        // 0..63
    const int lc   = tid & 3;

    float acc[4][4][4];
    #pragma unroll
    for (int i = 0; i < 4; i++)
        #pragma unroll
        for (int j = 0; j < 4; j++)
            #pragma unroll
            for (int r = 0; r < 4; r++) acc[i][j][r] = 0.0f;

    const uint32_t sbase = (uint32_t)__cvta_generic_to_shared(smem);

    auto ldstage = [&](int s) {
        const uint32_t buf = sbase + (uint32_t)(s % 3) * GSTAGE;
        const int k0 = s * GBK;
        const __nv_bfloat16* ga  = Ah + (size_t)(bm + lrow) * K + k0 + lc * 8;
        const __nv_bfloat16* gal = Al + (size_t)(bm + lrow) * K + k0 + lc * 8;
        const __nv_bfloat16* gb  = Bh + (size_t)(bn + lrow) * K + k0 + lc * 8;
        const __nv_bfloat16* gbl = Bl + (size_t)(bn + lrow) * K + k0 + lc * 8;
        const uint32_t so0 = soff(lrow, lc);
        const uint32_t so1 = soff(lrow + 64, lc);
        CP16(buf + so0,            ga);
        CP16(buf + so1,            ga + (size_t)64 * K);
        CP16(buf + SMAT + so0,     gal);
        CP16(buf + SMAT + so1,     gal + (size_t)64 * K);
        CP16(buf + 2 * SMAT + so0, gb);
        CP16(buf + 2 * SMAT + so1, gb + (size_t)64 * K);
        CP16(buf + 3 * SMAT + so0, gbl);
        CP16(buf + 3 * SMAT + so1, gbl + (size_t)64 * K);
    };

    const int nst = K / GBK;
    ldstage(0); CP_COMMIT();
    ldstage(1); CP_COMMIT();

    const int rl = lane & 15;
    const int rh = lane >> 4;

    for (int it = 0; it < nst; ++it) {
        // wait own groups FIRST (stage it complete in this warp) ...
        if (it < nst - 1) { CP_WAIT(1); } else { CP_WAIT(0); }
        // ... then ONE barrier: publishes stage it CTA-wide AND proves all
        // warps finished compute(it-1), the last reader of buf((it+2)%3).
        __syncthreads();

        if (it + 2 < nst) {
            ldstage(it + 2);
            CP_COMMIT();
        }

        const uint32_t buf = sbase + (uint32_t)(it % 3) * GSTAGE;
        const uint32_t sAh = buf;
        const uint32_t sAl = buf + SMAT;
        const uint32_t sBh = buf + 2 * SMAT;
        const uint32_t sBl = buf + 3 * SMAT;

        #pragma unroll
        for (int ks = 0; ks < 2; ks++) {
            const int chunk = 2 * ks + rh;
            uint32_t ah[4][4], al[4][4], bh[4][2], bl[4][2];

            #pragma unroll
            for (int mi = 0; mi < 4; mi++)
                ldsm4(ah[mi], sAh + soff(wm * 64 + mi * 16 + rl, chunk));
            #pragma unroll
            for (int nb = 0; nb < 2; nb++) {
                uint32_t r4[4];
                ldsm4(r4, sBh + soff(wn * 32 + nb * 16 + rl, chunk));
                bh[2 * nb][0] = r4[0]; bh[2 * nb + 1][0] = r4[1];
                bh[2 * nb][1] = r4[2]; bh[2 * nb + 1][1] = r4[3];
            }
            // pass 1: hi*hi (16 independent chains)
            #pragma unroll
            for (int mi = 0; mi < 4; mi++)
                #pragma unroll
                for (int nj = 0; nj < 4; nj++)
                    mma16816(acc[mi][nj], ah[mi], bh[nj]);

            #pragma unroll
            for (int nb = 0; nb < 2; nb++) {
                uint32_t r4[4];
                ldsm4(r4, sBl + soff(wn * 32 + nb * 16 + rl, chunk));
                bl[2 * nb][0] = r4[0]; bl[2 * nb + 1][0] = r4[1];
                bl[2 * nb][1] = r4[2]; bl[2 * nb + 1][1] = r4[3];
            }
            // pass 2: hi*lo
            #pragma unroll
            for (int mi = 0; mi < 4; mi++)
                #pragma unroll
                for (int nj = 0; nj < 4; nj++)
                    mma16816(acc[mi][nj], ah[mi], bl[nj]);

            #pragma unroll
            for (int mi = 0; mi < 4; mi++)
                ldsm4(al[mi], sAl + soff(wm * 64 + mi * 16 + rl, chunk));
            // pass 3: lo*hi
            #pragma unroll
            for (int mi = 0; mi < 4; mi++)
                #pragma unroll
                for (int nj = 0; nj < 4; nj++)
                    mma16816(acc[mi][nj], al[mi], bh[nj]);
        }
        // no bottom barrier: next iter's top barrier provides the WAR guard.
    }

    // ---------------- epilogue ----------------
    const int tg = lane >> 2;
    const int ti = lane & 3;
    if (mode == 0) {
        float* C = (float*)Ch;
        #pragma unroll
        for (int mi = 0; mi < 4; mi++) {
            const int row = bm + wm * 64 + mi * 16 + tg;
            #pragma unroll
            for (int nj = 0; nj < 4; nj++) {
                const int col = bn + wn * 32 + nj * 8 + 2 * ti;
                *(float2*)&C[(size_t)row * N + col]       = make_float2(acc[mi][nj][0], acc[mi][nj][1]);
                *(float2*)&C[(size_t)(row + 8) * N + col] = make_float2(acc[mi][nj][2], acc[mi][nj][3]);
            }
        }
    } else {
        __nv_bfloat16* Hi = (__nv_bfloat16*)Ch;
        __nv_bfloat16* Lo = (__nv_bfloat16*)Cl;
        #pragma unroll
        for (int mi = 0; mi < 4; mi++) {
            const int row = bm + wm * 64 + mi * 16 + tg;
            #pragma unroll
            for (int nj = 0; nj < 4; nj++) {
                const int col = bn + wn * 32 + nj * 8 + 2 * ti;
                float a0 = acc[mi][nj][0], a1 = acc[mi][nj][1];
                float a2 = acc[mi][nj][2], a3 = acc[mi][nj][3];
                if (mode == 1) {
                    const int p = (col & 127) >> 1;
                    const float c0 = fc[row * 64 + p],       s0 = fs[row * 64 + p];
                    const float c1 = fc[(row + 8) * 64 + p], s1 = fs[(row + 8) * 64 + p];
                    float r0 = a0 * c0 - a1 * s0, r1 = a0 * s0 + a1 * c0;
                    float r2 = a2 * c1 - a3 * s1, r3 = a2 * s1 + a3 * c1;
                    a0 = r0; a1 = r1; a2 = r2; a3 = r3;
                }
                uint32_t h0, l0, h1, l1;
                split2(a0, a1, h0, l0);
                split2(a2, a3, h1, l1);
                *(uint32_t*)&Hi[(size_t)row * N + col]       = h0;
                *(uint32_t*)&Lo[(size_t)row * N + col]       = l0;
                *(uint32_t*)&Hi[(size_t)(row + 8) * N + col] = h1;
                *(uint32_t*)&Lo[(size_t)(row + 8) * N + col] = l1;
            }
        }
    }
}

// ============================================================================
// Tensor-core flash attention, bf16x3, causal, GQA. Pass-major schedule.
// ============================================================================
#define BQ 128
#define BKV 64
#define QMAT 32768
#define KVMAT 16384
#define FSTAGE (4 * KVMAT)
#define FLASH_SMEM (2 * QMAT + 2 * FSTAGE)

__device__ __forceinline__ uint32_t fsw(int r, int c) {
    return (uint32_t)((r << 8) + ((c ^ (r & 7)) << 4));
}
__device__ __forceinline__ uint32_t pack_hi_rz(float p0, float p1, float& lo0, float& lo1) {
    uint32_t u0 = __float_as_uint(p0), u1 = __float_as_uint(p1);
    lo0 = p0 - __uint_as_float(u0 & 0xffff0000u);
    lo1 = p1 - __uint_as_float(u1 & 0xffff0000u);
    return __byte_perm(u0, u1, 0x7632);
}
__device__ __forceinline__ uint32_t pack_rn(float a, float b) {
    __nv_bfloat162 t = __floats2bfloat162_rn(a, b);
    return *(uint32_t*)&t;
}

__global__ void __launch_bounds__(256, 1) flash_tc_kernel(
    const __nv_bfloat16* __restrict__ qh, const __nv_bfloat16* __restrict__ ql,
    const __nv_bfloat16* __restrict__ kh, const __nv_bfloat16* __restrict__ kl,
    const __nv_bfloat16* __restrict__ vh, const __nv_bfloat16* __restrict__ vl,
    __nv_bfloat16* __restrict__ ath, __nv_bfloat16* __restrict__ atl)
{
    extern __shared__ char smc[];
    const uint32_t sb  = (uint32_t)__cvta_generic_to_shared(smc);
    const uint32_t sQh = sb, sQl = sb + QMAT;

    const int tid  = threadIdx.x;
    const int lane = tid & 31;
    const int w    = tid >> 5;
    const int rl   = lane & 15;
    const int rh   = lane >> 4;
    const int tg   = lane >> 2;
    const int ti   = lane & 3;
    const int vro  = (lane & 7) + ((lane >> 3) & 1) * 8;
    const int vco  = lane >> 4;

    const int qt    = gridDim.x - 1 - blockIdx.x;
    const int h     = blockIdx.y;
    const int kvh   = h >> 2;
    const int qbase = qt * BQ;
    const int wrow  = w * 16;

    for (int f = tid; f < 2048; f += 256) {
        const int r = f >> 4, c = f & 15;
        const size_t go = (size_t)(qbase + r) * DIM + h * HDIM + c * 8;
        CP16(sQh + fsw(r, c), qh + go);
        CP16(sQl + fsw(r, c), ql + go);
    }
    CP_COMMIT();

    auto loadKV = [&](int kt) {
        const uint32_t base = sb + 2 * QMAT + (kt & 1) * FSTAGE;
        const int kvb = kt * BKV;
        for (int f = tid; f < 1024; f += 256) {
            const int r = f >> 4, c = f & 15;
            const size_t go = (size_t)(kvb + r) * KVDIM + kvh * HDIM + c * 8;
            const uint32_t so = fsw(r, c);
            CP16(base + so,             kh + go);
            CP16(base + KVMAT + so,     kl + go);
            CP16(base + 2 * KVMAT + so, vh + go);
            CP16(base + 3 * KVMAT + so, vl + go);
        }
    };

    loadKV(0);
    CP_COMMIT();

    float o[16][4];
    #pragma unroll
    for (int i = 0; i < 16; i++)
        #pragma unroll
        for (int r = 0; r < 4; r++) o[i][r] = 0.0f;
    float m0 = -1e30f, m1 = -1e30f, l0 = 0.0f, l1 = 0.0f;
    const float scale = 0.08838834764831843f;
    const int row0 = qbase + wrow + tg;
    const int row1 = row0 + 8;

    const int nkt = 2 * qt + 2;
    for (int kt = 0; kt < nkt; kt++) {
        if (kt + 1 < nkt) { loadKV(kt + 1); CP_COMMIT(); CP_WAIT(1); }
        else              { CP_WAIT(0); }
        __syncthreads();

        const uint32_t base = sb + 2 * QMAT + (kt & 1) * FSTAGE;
        const uint32_t sKh = base, sKl = base + KVMAT;
        const uint32_t sVh = base + 2 * KVMAT, sVl = base + 3 * KVMAT;
        const int kvb = kt * BKV;

        // ---- S = Q K^T, pass-major ----
        float s[8][4];
        #pragma unroll
        for (int i = 0; i < 8; i++)
            #pragma unroll
            for (int r = 0; r < 4; r++) s[i][r] = 0.0f;

        #pragma unroll
        for (int kc = 0; kc < 8; kc++) {
            uint32_t ah[4], al[4];
            ldsm4(ah, sQh + fsw(wrow + rl, 2 * kc + rh));
            ldsm4(al, sQl + fsw(wrow + rl, 2 * kc + rh));

            uint32_t bh[8][2], bl[8][2];
            #pragma unroll
            for (int nb = 0; nb < 4; nb++) {
                uint32_t rk[4], rkl[4];
                ldsm4(rk,  sKh + fsw(nb * 16 + rl, 2 * kc + rh));
                ldsm4(rkl, sKl + fsw(nb * 16 + rl, 2 * kc + rh));
                bh[2 * nb][0]     = rk[0];  bh[2 * nb][1]     = rk[2];
                bh[2 * nb + 1][0] = rk[1];  bh[2 * nb + 1][1] = rk[3];
                bl[2 * nb][0]     = rkl[0]; bl[2 * nb][1]     = rkl[2];
                bl[2 * nb + 1][0] = rkl[1]; bl[2 * nb + 1][1] = rkl[3];
            }
            #pragma unroll
            for (int nj = 0; nj < 8; nj++) mma16816(s[nj], ah, bh[nj]);
            #pragma unroll
            for (int nj = 0; nj < 8; nj++) mma16816(s[nj], ah, bl[nj]);
            #pragma unroll
            for (int nj = 0; nj < 8; nj++) mma16816(s[nj], al, bh[nj]);
        }

        // ---- scale + causal mask ----
        const bool needmask = (kt >= 2 * qt);
        #pragma unroll
        for (int nj = 0; nj < 8; nj++) {
            #pragma unroll
            for (int r = 0; r < 4; r++) {
                float v = s[nj][r] * scale;
                if (needmask) {
                    const int col = kvb + nj * 8 + 2 * ti + (r & 1);
                    const int row = (r & 2) ? row1 : row0;
                    if (col > row) v = -1e30f;
                }
                s[nj][r] = v;
            }
        }

        // ---- online softmax ----
        float mx0 = -1e30f, mx1 = -1e30f;
        #pragma unroll
        for (int nj = 0; nj < 8; nj++) {
            mx0 = fmaxf(mx0, fmaxf(s[nj][0], s[nj][1]));
            mx1 = fmaxf(mx1, fmaxf(s[nj][2], s[nj][3]));
        }
        mx0 = fmaxf(mx0, __shfl_xor_sync(0xffffffffu, mx0, 1));
        mx0 = fmaxf(mx0, __shfl_xor_sync(0xffffffffu, mx0, 2));
        mx1 = fmaxf(mx1, __shfl_xor_sync(0xffffffffu, mx1, 1));
        mx1 = fmaxf(mx1, __shfl_xor_sync(0xffffffffu, mx1, 2));
        const float mn0 = fmaxf(m0, mx0), mn1 = fmaxf(m1, mx1);
        const float cr0 = __expf(m0 - mn0), cr1 = __expf(m1 - mn1);
        m0 = mn0; m1 = mn1;

        float sum0 = 0.0f, sum1 = 0.0f;
        #pragma unroll
        for (int nj = 0; nj < 8; nj++) {
            s[nj][0] = __expf(s[nj][0] - mn0); sum0 += s[nj][0];
            s[nj][1] = __expf(s[nj][1] - mn0); sum0 += s[nj][1];
            s[nj][2] = __expf(s[nj][2] - mn1); sum1 += s[nj][2];
            s[nj][3] = __expf(s[nj][3] - mn1); sum1 += s[nj][3];
        }
        sum0 += __shfl_xor_sync(0xffffffffu, sum0, 1);
        sum0 += __shfl_xor_sync(0xffffffffu, sum0, 2);
        sum1 += __shfl_xor_sync(0xffffffffu, sum1, 1);
        sum1 += __shfl_xor_sync(0xffffffffu, sum1, 2);
        l0 = l0 * cr0 + sum0;
        l1 = l1 * cr1 + sum1;

        #pragma unroll
        for (int nj = 0; nj < 16; nj++) {
            o[nj][0] *= cr0; o[nj][1] *= cr0;
            o[nj][2] *= cr1; o[nj][3] *= cr1;
        }

        // ---- O += P V, pass-major over halves ----
        #pragma unroll
        for (int kc = 0; kc < 4; kc++) {
            uint32_t pah[4], pal[4];
            {
                float la, lb;
                pah[0] = pack_hi_rz(s[2 * kc][0],     s[2 * kc][1],     la, lb); pal[0] = pack_rn(la, lb);
                pah[1] = pack_hi_rz(s[2 * kc][2],     s[2 * kc][3],     la, lb); pal[1] = pack_rn(la, lb);
                pah[2] = pack_hi_rz(s[2 * kc + 1][0], s[2 * kc + 1][1], la, lb); pal[2] = pack_rn(la, lb);
                pah[3] = pack_hi_rz(s[2 * kc + 1][2], s[2 * kc + 1][3], la, lb); pal[3] = pack_rn(la, lb);
            }
            #pragma unroll
            for (int half = 0; half < 2; half++) {
                uint32_t bv[8][2], cv[8][2];
                #pragma unroll
                for (int n4 = 0; n4 < 4; n4++) {
                    const int nb = half * 4 + n4;
                    uint32_t rv[4], rw[4];
                    const uint32_t so = fsw(kc * 16 + vro, 2 * nb + vco);
                    ldsm4t(rv, sVh + so);
                    ldsm4t(rw, sVl + so);
                    bv[2 * n4][0]     = rv[0]; bv[2 * n4][1]     = rv[1];
                    bv[2 * n4 + 1][0] = rv[2]; bv[2 * n4 + 1][1] = rv[3];
                    cv[2 * n4][0]     = rw[0]; cv[2 * n4][1]     = rw[1];
                    cv[2 * n4 + 1][0] = rw[2]; cv[2 * n4 + 1][1] = rw[3];
                }
                #pragma unroll
                for (int j = 0; j < 8; j++) mma16816(o[8 * half + j], pah, bv[j]);
                #pragma unroll
                for (int j = 0; j < 8; j++) mma16816(o[8 * half + j], pah, cv[j]);
                #pragma unroll
                for (int j = 0; j < 8; j++) mma16816(o[8 * half + j], pal, bv[j]);
            }
        }
        __syncthreads();
    }

    // ---- epilogue: normalize, split hi/lo, store ----
    const float inv0 = 1.0f / l0, inv1 = 1.0f / l1;
    #pragma unroll
    for (int nj = 0; nj < 16; nj++) {
        const int col = h * HDIM + nj * 8 + 2 * ti;
        float v0 = o[nj][0] * inv0, v1 = o[nj][1] * inv0;
        float v2 = o[nj][2] * inv1, v3 = o[nj][3] * inv1;
        __nv_bfloat162 h0 = __floats2bfloat162_rn(v0, v1);
        __nv_bfloat162 h1 = __floats2bfloat162_rn(v2, v3);
        __nv_bfloat162 e0 = __floats2bfloat162_rn(v0 - __low2float(h0), v1 - __high2float(h0));
        __nv_bfloat162 e1 = __floats2bfloat162_rn(v2 - __low2float(h1), v3 - __high2float(h1));
        *(uint32_t*)&ath[(size_t)row0 * DIM + col] = *(uint32_t*)&h0;
        *(uint32_t*)&ath[(size_t)row1 * DIM + col] = *(uint32_t*)&h1;
        *(uint32_t*)&atl[(size_t)row0 * DIM + col] = *(uint32_t*)&e0;
        *(uint32_t*)&atl[(size_t)row1 * DIM + col] = *(uint32_t*)&e1;
    }
}

// ============================================================================
// launch
// ============================================================================
extern "C" void kernel_launch(void* const* d_in, const int* in_sizes, int n_in,
                              void* d_out, int out_size)
{
    (void)in_sizes; (void)n_in; (void)out_size;
    const float* x  = (const float*)d_in[0];
    const float* wq = (const float*)d_in[1];
    const float* wk = (const float*)d_in[2];
    const float* wv = (const float*)d_in[3];
    const float* wo = (const float*)d_in[4];
    const float* fc = (const float*)d_in[5];
    const float* fs = (const float*)d_in[6];
    float* out = (float*)d_out;

    __nv_bfloat16 *xh, *xl, *wqh, *wql, *wkh, *wkl, *wvh, *wvl, *woh, *wol;
    __nv_bfloat16 *ath, *atl, *qh, *ql, *kh, *kl, *vh, *vl;
    cudaGetSymbolAddress((void**)&xh,  g_xh);  cudaGetSymbolAddress((void**)&xl,  g_xl);
    cudaGetSymbolAddress((void**)&wqh, g_wqh); cudaGetSymbolAddress((void**)&wql, g_wql);
    cudaGetSymbolAddress((void**)&wkh, g_wkh); cudaGetSymbolAddress((void**)&wkl, g_wkl);
    cudaGetSymbolAddress((void**)&wvh, g_wvh); cudaGetSymbolAddress((void**)&wvl, g_wvl);
    cudaGetSymbolAddress((void**)&woh, g_woh); cudaGetSymbolAddress((void**)&wol, g_wol);
    cudaGetSymbolAddress((void**)&ath, g_ath); cudaGetSymbolAddress((void**)&atl, g_atl);
    cudaGetSymbolAddress((void**)&qh,  g_qh);  cudaGetSymbolAddress((void**)&ql,  g_ql);
    cudaGetSymbolAddress((void**)&kh,  g_kh);  cudaGetSymbolAddress((void**)&kl,  g_kl);
    cudaGetSymbolAddress((void**)&vh,  g_vh);  cudaGetSymbolAddress((void**)&vl,  g_vl);

    cudaFuncSetAttribute(gemm_bf16x3_kernel,
                         cudaFuncAttributeMaxDynamicSharedMemorySize, GEMM_SMEM);
    cudaFuncSetAttribute(flash_tc_kernel,
                         cudaFuncAttributeMaxDynamicSharedMemorySize, FLASH_SMEM);

    // 0) splits: x ; wq+wo fused ; wk+wv fused  (3 launches)
    split_kernel<<<dim3((SEQ * DIM / 4 + 255) / 256, 1), 256>>>(
        x, xh, xl, nullptr, nullptr, nullptr, SEQ * DIM / 4);
    split_kernel<<<dim3((DIM * DIM / 4 + 255) / 256, 2), 256>>>(
        wq, wqh, wql, wo, woh, wol, DIM * DIM / 4);
    split_kernel<<<dim3((KVDIM * DIM / 4 + 255) / 256, 2), 256>>>(
        wk, wkh, wkl, wv, wvh, wvl, KVDIM * DIM / 4);

    // 1) fused Q + K + V projections; epilogue applies RoPE (Q,K) / split (V)
    gemm_bf16x3_kernel<<<dim3((DIM + 2 * KVDIM) / GBN, SEQ / GBM, 1), 256, GEMM_SMEM>>>(
        xh, xl,
        wqh, wql, qh, ql, DIM,   1,
        wkh, wkl, kh, kl, KVDIM, 1,
        wvh, wvl, vh, vl,        2,
        fc, fs, DIM);

    // 2) tensor-core flash attention -> attn hi/lo
    flash_tc_kernel<<<dim3(SEQ / BQ, HEADS), 256, FLASH_SMEM>>>(
        qh, ql, kh, kl, vh, vl, ath, atl);

    // 3) O projection (single group, fp32 store)
    gemm_bf16x3_kernel<<<dim3(DIM / GBN, SEQ / GBM, 1), 256, GEMM_SMEM>>>(
        ath, atl,
        woh, wol, out, nullptr, DIM, 0,
        nullptr, nullptr, nullptr, nullptr, 0, 0,
        nullptr, nullptr, nullptr, nullptr, 0,
        nullptr, nullptr, DIM);
}

// round 12
// speedup vs baseline: 1.7627x; 1.0636x over previous
#include <cuda_runtime.h>
#include <cuda_bf16.h>
#include <cstdint>
#include <cstddef>

#define DIM     4096
#define SEQ     2048
#define HEADS   32
#define KVHEADS 8
#define HDIM    128
#define KVDIM   1024   // KVHEADS*HDIM

// ------------------------- scratch (static, no allocation) -------------------
__device__ __nv_bfloat16 g_xh[SEQ * DIM],    g_xl[SEQ * DIM];
__device__ __nv_bfloat16 g_wqh[DIM * DIM],   g_wql[DIM * DIM];
__device__ __nv_bfloat16 g_wkh[KVDIM * DIM], g_wkl[KVDIM * DIM];
__device__ __nv_bfloat16 g_wvh[KVDIM * DIM], g_wvl[KVDIM * DIM];
__device__ __nv_bfloat16 g_woh[DIM * DIM],   g_wol[DIM * DIM];
__device__ __nv_bfloat16 g_ath[SEQ * DIM],   g_atl[SEQ * DIM];
__device__ __nv_bfloat16 g_qh[SEQ * DIM],    g_ql[SEQ * DIM];
__device__ __nv_bfloat16 g_kh[SEQ * KVDIM],  g_kl[SEQ * KVDIM];
__device__ __nv_bfloat16 g_vh[SEQ * KVDIM],  g_vl[SEQ * KVDIM];

// ============================================================================
// split: fp32 -> bf16 hi + bf16 lo. blockIdx.y==1 switches to (x2, hi2, lo2).
// ============================================================================
__global__ void split_kernel(const float* __restrict__ x,
                             __nv_bfloat16* __restrict__ hi,
                             __nv_bfloat16* __restrict__ lo,
                             const float* __restrict__ x2,
                             __nv_bfloat16* __restrict__ hi2,
                             __nv_bfloat16* __restrict__ lo2, int n4)
{
    const int i = blockIdx.x * blockDim.x + threadIdx.x;
    if (i >= n4) return;
    if (blockIdx.y == 1) { x = x2; hi = hi2; lo = lo2; }
    float4 v = ((const float4*)x)[i];
    __nv_bfloat16 h0 = __float2bfloat16(v.x);
    __nv_bfloat16 h1 = __float2bfloat16(v.y);
    __nv_bfloat16 h2 = __float2bfloat16(v.z);
    __nv_bfloat16 h3 = __float2bfloat16(v.w);
    __nv_bfloat16 l0 = __float2bfloat16(v.x - __bfloat162float(h0));
    __nv_bfloat16 l1 = __float2bfloat16(v.y - __bfloat162float(h1));
    __nv_bfloat16 l2 = __float2bfloat16(v.z - __bfloat162float(h2));
    __nv_bfloat16 l3 = __float2bfloat16(v.w - __bfloat162float(h3));
    __nv_bfloat162 hp0 = __halves2bfloat162(h0, h1);
    __nv_bfloat162 hp1 = __halves2bfloat162(h2, h3);
    __nv_bfloat162 lp0 = __halves2bfloat162(l0, l1);
    __nv_bfloat162 lp1 = __halves2bfloat162(l2, l3);
    uint2 hv, lv;
    hv.x = *(uint32_t*)&hp0; hv.y = *(uint32_t*)&hp1;
    lv.x = *(uint32_t*)&lp0; lv.y = *(uint32_t*)&lp1;
    ((uint2*)hi)[i] = hv;
    ((uint2*)lo)[i] = lv;
}

// ============================================================================
// shared mma helpers
// ============================================================================
__device__ __forceinline__ void ldsm4(uint32_t* r, uint32_t addr) {
    asm volatile("ldmatrix.sync.aligned.m8n8.x4.shared.b16 {%0,%1,%2,%3}, [%4];"
                 : "=r"(r[0]), "=r"(r[1]), "=r"(r[2]), "=r"(r[3]) : "r"(addr));
}
__device__ __forceinline__ void ldsm4t(uint32_t* r, uint32_t addr) {
    asm volatile("ldmatrix.sync.aligned.m8n8.x4.trans.shared.b16 {%0,%1,%2,%3}, [%4];"
                 : "=r"(r[0]), "=r"(r[1]), "=r"(r[2]), "=r"(r[3]) : "r"(addr));
}
__device__ __forceinline__ void mma16816(float* c, const uint32_t* a, const uint32_t* b) {
    asm volatile("mma.sync.aligned.m16n8k16.row.col.f32.bf16.bf16.f32 "
                 "{%0,%1,%2,%3},{%4,%5,%6,%7},{%8,%9},{%0,%1,%2,%3};"
                 : "+f"(c[0]), "+f"(c[1]), "+f"(c[2]), "+f"(c[3])
                 : "r"(a[0]), "r"(a[1]), "r"(a[2]), "r"(a[3]), "r"(b[0]), "r"(b[1]));
}

#define CP16(dst, src) asm volatile("cp.async.cg.shared.global [%0], [%1], 16;" :: "r"(dst), "l"(src))
#define CP_COMMIT()    asm volatile("cp.async.commit_group;")
#define CP_WAIT(n)     asm volatile("cp.async.wait_group %0;" :: "n"(n))

// smem byte offset with XOR swizzle (row stride 64B, 16B chunks)
__device__ __forceinline__ uint32_t soff(int row, int chunk) {
    return (uint32_t)((row << 6) + ((chunk ^ ((row >> 1) & 3)) << 4));
}

// split pair -> hi/lo bf16x2 words
__device__ __forceinline__ void split2(float a, float b, uint32_t& h, uint32_t& l) {
    __nv_bfloat162 hp = __floats2bfloat162_rn(a, b);
    __nv_bfloat162 lp = __floats2bfloat162_rn(a - __low2float(hp), b - __high2float(hp));
    h = *(uint32_t*)&hp;
    l = *(uint32_t*)&lp;
}

// ============================================================================
// bf16x3 tensor-core GEMM:  C[M,N](fp32) = A[M,K] * B[N,K]^T
// 128x64x32 CTA tile, 256 thr (8 warps, 2x4), warp tile 64x16,
// 3 CTAs/SM (reg cap 85 -> 24 warps/SM), 3-stage cp.async ring,
// single barrier per k-iter, persistent advancing loader pointers.
// Column-group dispatch: up to 3 concatenated output matrices sharing A.
// Epilogue modes per group: 0 = fp32 store, 1 = rope + bf16 hi/lo, 2 = bf16 hi/lo.
// ============================================================================
#define GBM 128
#define GBN 64
#define GBK 32
#define SMATA 8192                  // A: 128 rows x 64B
#define SMATB 4096                  // B:  64 rows x 64B
#define GSTAGE (2 * SMATA + 2 * SMATB)  // 24KB
#define GEMM_SMEM (3 * GSTAGE)          // 72KB -> 3 CTAs/SM

__global__ void __launch_bounds__(256, 3) gemm_bf16x3_kernel(
    const __nv_bfloat16* __restrict__ Ah, const __nv_bfloat16* __restrict__ Al,
    const __nv_bfloat16* B0h, const __nv_bfloat16* B0l, void* C0h, void* C0l, int N0, int mode0,
    const __nv_bfloat16* B1h, const __nv_bfloat16* B1l, void* C1h, void* C1l, int N1, int mode1,
    const __nv_bfloat16* B2h, const __nv_bfloat16* B2l, void* C2h, void* C2l, int mode2,
    const float* __restrict__ fc, const float* __restrict__ fs, int K)
{
    // column-group selection (uniform per CTA)
    const int bng = blockIdx.x * GBN;
    const __nv_bfloat16 *Bh, *Bl;
    void *Ch, *Cl;
    int N, bn, mode;
    if (bng < N0)           { Bh = B0h; Bl = B0l; Ch = C0h; Cl = C0l; N = N0; bn = bng; mode = mode0; }
    else if (bng < N0 + N1) { Bh = B1h; Bl = B1l; Ch = C1h; Cl = C1l; N = N1; bn = bng - N0; mode = mode1; }
    else                    { Bh = B2h; Bl = B2l; Ch = C2h; Cl = C2l; N = N1; bn = bng - N0 - N1; mode = mode2; }

    extern __shared__ char smem[];
    const int tid  = threadIdx.x;
    const int lane = tid & 31;
    const int w    = tid >> 5;
    const int wm   = w >> 2;          // 0..1  (64-row band)
    const int wn   = w & 3;           // 0..3  (16-col band)
    const int bm   = blockIdx.y * GBM;

    const int lrow = tid >> 2;        // 0..63
    const int lc   = tid & 3;

    float acc[4][2][4];
    #pragma unroll
    for (int i = 0; i < 4; i++)
        #pragma unroll
        for (int j = 0; j < 2; j++)
            #pragma unroll
            for (int r = 0; r < 4; r++) acc[i][j][r] = 0.0f;

    const uint32_t sbase = (uint32_t)__cvta_generic_to_shared(smem);

    // persistent loader pointers (advance by GBK after each stage issued)
    const __nv_bfloat16* pa  = Ah + (size_t)(bm + lrow) * K + lc * 8;
    const __nv_bfloat16* pal = Al + (size_t)(bm + lrow) * K + lc * 8;
    const __nv_bfloat16* pb  = Bh + (size_t)(bn + lrow) * K + lc * 8;
    const __nv_bfloat16* pbl = Bl + (size_t)(bn + lrow) * K + lc * 8;
    const size_t arow64 = (size_t)64 * K;
    const uint32_t soA0 = soff(lrow, lc);
    const uint32_t soA1 = soff(lrow + 64, lc);

    auto ldstage = [&](int bufi) {
        const uint32_t buf = sbase + (uint32_t)bufi * GSTAGE;
        CP16(buf + soA0,                     pa);
        CP16(buf + soA1,                     pa + arow64);
        CP16(buf + SMATA + soA0,             pal);
        CP16(buf + SMATA + soA1,             pal + arow64);
        CP16(buf + 2 * SMATA + soA0,         pb);
        CP16(buf + 2 * SMATA + SMATB + soA0, pbl);
        pa += GBK; pal += GBK; pb += GBK; pbl += GBK;
    };

    const int nst = K / GBK;
    ldstage(0); CP_COMMIT();
    ldstage(1); CP_COMMIT();

    const int rl = lane & 15;
    const int rh = lane >> 4;
    int nbuf = 2;   // buffer for stage it+2
    int cbuf = 0;   // buffer for stage it

    for (int it = 0; it < nst; ++it) {
        // wait own groups FIRST, then one barrier (publishes stage it CTA-wide
        // and licenses refilling buf((it+2)%3), last read by compute(it-1)).
        if (it < nst - 1) { CP_WAIT(1); } else { CP_WAIT(0); }
        __syncthreads();

        if (it + 2 < nst) {
            ldstage(nbuf);
            CP_COMMIT();
            nbuf = (nbuf == 2) ? 0 : nbuf + 1;
        }

        const uint32_t buf = sbase + (uint32_t)cbuf * GSTAGE;
        cbuf = (cbuf == 2) ? 0 : cbuf + 1;
        const uint32_t sAh = buf;
        const uint32_t sAl = buf + SMATA;
        const uint32_t sBh = buf + 2 * SMATA;
        const uint32_t sBl = buf + 2 * SMATA + SMATB;

        #pragma unroll
        for (int ks = 0; ks < 2; ks++) {
            const int chunk = 2 * ks + rh;
            uint32_t ah[4][4], bh[2][2], bl[2][2];

            #pragma unroll
            for (int mi = 0; mi < 4; mi++)
                ldsm4(ah[mi], sAh + soff(wm * 64 + mi * 16 + rl, chunk));
            {
                uint32_t r4[4];
                ldsm4(r4, sBh + soff(wn * 16 + rl, chunk));
                bh[0][0] = r4[0]; bh[0][1] = r4[2];
                bh[1][0] = r4[1]; bh[1][1] = r4[3];
            }
            {
                uint32_t r4[4];
                ldsm4(r4, sBl + soff(wn * 16 + rl, chunk));
                bl[0][0] = r4[0]; bl[0][1] = r4[2];
                bl[1][0] = r4[1]; bl[1][1] = r4[3];
            }
            // pass 1: hi*hi (8 independent chains)
            #pragma unroll
            for (int mi = 0; mi < 4; mi++)
                #pragma unroll
                for (int nj = 0; nj < 2; nj++)
                    mma16816(acc[mi][nj], ah[mi], bh[nj]);
            // pass 2: hi*lo
            #pragma unroll
            for (int mi = 0; mi < 4; mi++)
                #pragma unroll
                for (int nj = 0; nj < 2; nj++)
                    mma16816(acc[mi][nj], ah[mi], bl[nj]);
            // pass 3: lo*hi (reuse ah registers for al — ah dead after pass 2)
            #pragma unroll
            for (int mi = 0; mi < 4; mi++)
                ldsm4(ah[mi], sAl + soff(wm * 64 + mi * 16 + rl, chunk));
            #pragma unroll
            for (int mi = 0; mi < 4; mi++)
                #pragma unroll
                for (int nj = 0; nj < 2; nj++)
                    mma16816(acc[mi][nj], ah[mi], bh[nj]);
        }
        // no bottom barrier: next iter's top barrier provides the WAR guard.
    }

    // ---------------- epilogue ----------------
    const int tg = lane >> 2;
    const int ti = lane & 3;
    if (mode == 0) {
        float* C = (float*)Ch;
        #pragma unroll
        for (int mi = 0; mi < 4; mi++) {
            const int row = bm + wm * 64 + mi * 16 + tg;
            #pragma unroll
            for (int nj = 0; nj < 2; nj++) {
                const int col = bn + wn * 16 + nj * 8 + 2 * ti;
                *(float2*)&C[(size_t)row * N + col]       = make_float2(acc[mi][nj][0], acc[mi][nj][1]);
                *(float2*)&C[(size_t)(row + 8) * N + col] = make_float2(acc[mi][nj][2], acc[mi][nj][3]);
            }
        }
    } else {
        __nv_bfloat16* Hi = (__nv_bfloat16*)Ch;
        __nv_bfloat16* Lo = (__nv_bfloat16*)Cl;
        #pragma unroll
        for (int mi = 0; mi < 4; mi++) {
            const int row = bm + wm * 64 + mi * 16 + tg;
            #pragma unroll
            for (int nj = 0; nj < 2; nj++) {
                const int col = bn + wn * 16 + nj * 8 + 2 * ti;
                float a0 = acc[mi][nj][0], a1 = acc[mi][nj][1];
                float a2 = acc[mi][nj][2], a3 = acc[mi][nj][3];
                if (mode == 1) {
                    const int p = (col & 127) >> 1;
                    const float c0 = fc[row * 64 + p],       s0 = fs[row * 64 + p];
                    const float c1 = fc[(row + 8) * 64 + p], s1 = fs[(row + 8) * 64 + p];
                    float r0 = a0 * c0 - a1 * s0, r1 = a0 * s0 + a1 * c0;
                    float r2 = a2 * c1 - a3 * s1, r3 = a2 * s1 + a3 * c1;
                    a0 = r0; a1 = r1; a2 = r2; a3 = r3;
                }
                uint32_t h0, l0, h1, l1;
                split2(a0, a1, h0, l0);
                split2(a2, a3, h1, l1);
                *(uint32_t*)&Hi[(size_t)row * N + col]       = h0;
                *(uint32_t*)&Lo[(size_t)row * N + col]       = l0;
                *(uint32_t*)&Hi[(size_t)(row + 8) * N + col] = h1;
                *(uint32_t*)&Lo[(size_t)(row + 8) * N + col] = l1;
            }
        }
    }
}

// ============================================================================
// Tensor-core flash attention, bf16x3, causal, GQA. Pass-major schedule.
// ============================================================================
#define BQ 128
#define BKV 64
#define QMAT 32768
#define KVMAT 16384
#define FSTAGE (4 * KVMAT)
#define FLASH_SMEM (2 * QMAT + 2 * FSTAGE)

__device__ __forceinline__ uint32_t fsw(int r, int c) {
    return (uint32_t)((r << 8) + ((c ^ (r & 7)) << 4));
}
__device__ __forceinline__ uint32_t pack_hi_rz(float p0, float p1, float& lo0, float& lo1) {
    uint32_t u0 = __float_as_uint(p0), u1 = __float_as_uint(p1);
    lo0 = p0 - __uint_as_float(u0 & 0xffff0000u);
    lo1 = p1 - __uint_as_float(u1 & 0xffff0000u);
    return __byte_perm(u0, u1, 0x7632);
}
__device__ __forceinline__ uint32_t pack_rn(float a, float b) {
    __nv_bfloat162 t = __floats2bfloat162_rn(a, b);
    return *(uint32_t*)&t;
}

__global__ void __launch_bounds__(256, 1) flash_tc_kernel(
    const __nv_bfloat16* __restrict__ qh, const __nv_bfloat16* __restrict__ ql,
    const __nv_bfloat16* __restrict__ kh, const __nv_bfloat16* __restrict__ kl,
    const __nv_bfloat16* __restrict__ vh, const __nv_bfloat16* __restrict__ vl,
    __nv_bfloat16* __restrict__ ath, __nv_bfloat16* __restrict__ atl)
{
    extern __shared__ char smc[];
    const uint32_t sb  = (uint32_t)__cvta_generic_to_shared(smc);
    const uint32_t sQh = sb, sQl = sb + QMAT;

    const int tid  = threadIdx.x;
    const int lane = tid & 31;
    const int w    = tid >> 5;
    const int rl   = lane & 15;
    const int rh   = lane >> 4;
    const int tg   = lane >> 2;
    const int ti   = lane & 3;
    const int vro  = (lane & 7) + ((lane >> 3) & 1) * 8;
    const int vco  = lane >> 4;

    const int qt    = gridDim.x - 1 - blockIdx.x;
    const int h     = blockIdx.y;
    const int kvh   = h >> 2;
    const int qbase = qt * BQ;
    const int wrow  = w * 16;

    for (int f = tid; f < 2048; f += 256) {
        const int r = f >> 4, c = f & 15;
        const size_t go = (size_t)(qbase + r) * DIM + h * HDIM + c * 8;
        CP16(sQh + fsw(r, c), qh + go);
        CP16(sQl + fsw(r, c), ql + go);
    }
    CP_COMMIT();

    auto loadKV = [&](int kt) {
        const uint32_t base = sb + 2 * QMAT + (kt & 1) * FSTAGE;
        const int kvb = kt * BKV;
        for (int f = tid; f < 1024; f += 256) {
            const int r = f >> 4, c = f & 15;
            const size_t go = (size_t)(kvb + r) * KVDIM + kvh * HDIM + c * 8;
            const uint32_t so = fsw(r, c);
            CP16(base + so,             kh + go);
            CP16(base + KVMAT + so,     kl + go);
            CP16(base + 2 * KVMAT + so, vh + go);
            CP16(base + 3 * KVMAT + so, vl + go);
        }
    };

    loadKV(0);
    CP_COMMIT();

    float o[16][4];
    #pragma unroll
    for (int i = 0; i < 16; i++)
        #pragma unroll
        for (int r = 0; r < 4; r++) o[i][r] = 0.0f;
    float m0 = -1e30f, m1 = -1e30f, l0 = 0.0f, l1 = 0.0f;
    const float scale = 0.08838834764831843f;
    const int row0 = qbase + wrow + tg;
    const int row1 = row0 + 8;

    const int nkt = 2 * qt + 2;
    for (int kt = 0; kt < nkt; kt++) {
        if (kt + 1 < nkt) { loadKV(kt + 1); CP_COMMIT(); CP_WAIT(1); }
        else              { CP_WAIT(0); }
        __syncthreads();

        const uint32_t base = sb + 2 * QMAT + (kt & 1) * FSTAGE;
        const uint32_t sKh = base, sKl = base + KVMAT;
        const uint32_t sVh = base + 2 * KVMAT, sVl = base + 3 * KVMAT;
        const int kvb = kt * BKV;

        // ---- S = Q K^T, pass-major ----
        float s[8][4];
        #pragma unroll
        for (int i = 0; i < 8; i++)
            #pragma unroll
            for (int r = 0; r < 4; r++) s[i][r] = 0.0f;

        #pragma unroll
        for (int kc = 0; kc < 8; kc++) {
            uint32_t ah[4], al[4];
            ldsm4(ah, sQh + fsw(wrow + rl, 2 * kc + rh));
            ldsm4(al, sQl + fsw(wrow + rl, 2 * kc + rh));

            uint32_t bh[8][2], bl[8][2];
            #pragma unroll
            for (int nb = 0; nb < 4; nb++) {
                uint32_t rk[4], rkl[4];
                ldsm4(rk,  sKh + fsw(nb * 16 + rl, 2 * kc + rh));
                ldsm4(rkl, sKl + fsw(nb * 16 + rl, 2 * kc + rh));
                bh[2 * nb][0]     = rk[0];  bh[2 * nb][1]     = rk[2];
                bh[2 * nb + 1][0] = rk[1];  bh[2 * nb + 1][1] = rk[3];
                bl[2 * nb][0]     = rkl[0]; bl[2 * nb][1]     = rkl[2];
                bl[2 * nb + 1][0] = rkl[1]; bl[2 * nb + 1][1] = rkl[3];
            }
            #pragma unroll
            for (int nj = 0; nj < 8; nj++) mma16816(s[nj], ah, bh[nj]);
            #pragma unroll
            for (int nj = 0; nj < 8; nj++) mma16816(s[nj], ah, bl[nj]);
            #pragma unroll
            for (int nj = 0; nj < 8; nj++) mma16816(s[nj], al, bh[nj]);
        }

        // ---- scale + causal mask ----
        const bool needmask = (kt >= 2 * qt);
        #pragma unroll
        for (int nj = 0; nj < 8; nj++) {
            #pragma unroll
            for (int r = 0; r < 4; r++) {
                float v = s[nj][r] * scale;
                if (needmask) {
                    const int col = kvb + nj * 8 + 2 * ti + (r & 1);
                    const int row = (r & 2) ? row1 : row0;
                    if (col > row) v = -1e30f;
                }
                s[nj][r] = v;
            }
        }

        // ---- online softmax ----
        float mx0 = -1e30f, mx1 = -1e30f;
        #pragma unroll
        for (int nj = 0; nj < 8; nj++) {
            mx0 = fmaxf(mx0, fmaxf(s[nj][0], s[nj][1]));
            mx1 = fmaxf(mx1, fmaxf(s[nj][2], s[nj][3]));
        }
        mx0 = fmaxf(mx0, __shfl_xor_sync(0xffffffffu, mx0, 1));
        mx0 = fmaxf(mx0, __shfl_xor_sync(0xffffffffu, mx0, 2));
        mx1 = fmaxf(mx1, __shfl_xor_sync(0xffffffffu, mx1, 1));
        mx1 = fmaxf(mx1, __shfl_xor_sync(0xffffffffu, mx1, 2));
        const float mn0 = fmaxf(m0, mx0), mn1 = fmaxf(m1, mx1);
        const float cr0 = __expf(m0 - mn0), cr1 = __expf(m1 - mn1);
        m0 = mn0; m1 = mn1;

        float sum0 = 0.0f, sum1 = 0.0f;
        #pragma unroll
        for (int nj = 0; nj < 8; nj++) {
            s[nj][0] = __expf(s[nj][0] - mn0); sum0 += s[nj][0];
            s[nj][1] = __expf(s[nj][1] - mn0); sum0 += s[nj][1];
            s[nj][2] = __expf(s[nj][2] - mn1); sum1 += s[nj][2];
            s[nj][3] = __expf(s[nj][3] - mn1); sum1 += s[nj][3];
        }
        sum0 += __shfl_xor_sync(0xffffffffu, sum0, 1);
        sum0 += __shfl_xor_sync(0xffffffffu, sum0, 2);
        sum1 += __shfl_xor_sync(0xffffffffu, sum1, 1);
        sum1 += __shfl_xor_sync(0xffffffffu, sum1, 2);
        l0 = l0 * cr0 + sum0;
        l1 = l1 * cr1 + sum1;

        #pragma unroll
        for (int nj = 0; nj < 16; nj++) {
            o[nj][0] *= cr0; o[nj][1] *= cr0;
            o[nj][2] *= cr1; o[nj][3] *= cr1;
        }

        // ---- O += P V, pass-major over halves ----
        #pragma unroll
        for (int kc = 0; kc < 4; kc++) {
            uint32_t pah[4], pal[4];
            {
                float la, lb;
                pah[0] = pack_hi_rz(s[2 * kc][0],     s[2 * kc][1],     la, lb); pal[0] = pack_rn(la, lb);
                pah[1] = pack_hi_rz(s[2 * kc][2],     s[2 * kc][3],     la, lb); pal[1] = pack_rn(la, lb);
                pah[2] = pack_hi_rz(s[2 * kc + 1][0], s[2 * kc + 1][1], la, lb); pal[2] = pack_rn(la, lb);
                pah[3] = pack_hi_rz(s[2 * kc + 1][2], s[2 * kc + 1][3], la, lb); pal[3] = pack_rn(la, lb);
            }
            #pragma unroll
            for (int half = 0; half < 2; half++) {
                uint32_t bv[8][2], cv[8][2];
                #pragma unroll
                for (int n4 = 0; n4 < 4; n4++) {
                    const int nb = half * 4 + n4;
                    uint32_t rv[4], rw[4];
                    const uint32_t so = fsw(kc * 16 + vro, 2 * nb + vco);
                    ldsm4t(rv, sVh + so);
                    ldsm4t(rw, sVl + so);
                    bv[2 * n4][0]     = rv[0]; bv[2 * n4][1]     = rv[1];
                    bv[2 * n4 + 1][0] = rv[2]; bv[2 * n4 + 1][1] = rv[3];
                    cv[2 * n4][0]     = rw[0]; cv[2 * n4][1]     = rw[1];
                    cv[2 * n4 + 1][0] = rw[2]; cv[2 * n4 + 1][1] = rw[3];
                }
                #pragma unroll
                for (int j = 0; j < 8; j++) mma16816(o[8 * half + j], pah, bv[j]);
                #pragma unroll
                for (int j = 0; j < 8; j++) mma16816(o[8 * half + j], pah, cv[j]);
                #pragma unroll
                for (int j = 0; j < 8; j++) mma16816(o[8 * half + j], pal, bv[j]);
            }
        }
        __syncthreads();
    }

    // ---- epilogue: normalize, split hi/lo, store ----
    const float inv0 = 1.0f / l0, inv1 = 1.0f / l1;
    #pragma unroll
    for (int nj = 0; nj < 16; nj++) {
        const int col = h * HDIM + nj * 8 + 2 * ti;
        float v0 = o[nj][0] * inv0, v1 = o[nj][1] * inv0;
        float v2 = o[nj][2] * inv1, v3 = o[nj][3] * inv1;
        __nv_bfloat162 h0 = __floats2bfloat162_rn(v0, v1);
        __nv_bfloat162 h1 = __floats2bfloat162_rn(v2, v3);
        __nv_bfloat162 e0 = __floats2bfloat162_rn(v0 - __low2float(h0), v1 - __high2float(h0));
        __nv_bfloat162 e1 = __floats2bfloat162_rn(v2 - __low2float(h1), v3 - __high2float(h1));
        *(uint32_t*)&ath[(size_t)row0 * DIM + col] = *(uint32_t*)&h0;
        *(uint32_t*)&ath[(size_t)row1 * DIM + col] = *(uint32_t*)&h1;
        *(uint32_t*)&atl[(size_t)row0 * DIM + col] = *(uint32_t*)&e0;
        *(uint32_t*)&atl[(size_t)row1 * DIM + col] = *(uint32_t*)&e1;
    }
}

// ============================================================================
// launch
// ============================================================================
extern "C" void kernel_launch(void* const* d_in, const int* in_sizes, int n_in,
                              void* d_out, int out_size)
{
    (void)in_sizes; (void)n_in; (void)out_size;
    const float* x  = (const float*)d_in[0];
    const float* wq = (const float*)d_in[1];
    const float* wk = (const float*)d_in[2];
    const float* wv = (const float*)d_in[3];
    const float* wo = (const float*)d_in[4];
    const float* fc = (const float*)d_in[5];
    const float* fs = (const float*)d_in[6];
    float* out = (float*)d_out;

    __nv_bfloat16 *xh, *xl, *wqh, *wql, *wkh, *wkl, *wvh, *wvl, *woh, *wol;
    __nv_bfloat16 *ath, *atl, *qh, *ql, *kh, *kl, *vh, *vl;
    cudaGetSymbolAddress((void**)&xh,  g_xh);  cudaGetSymbolAddress((void**)&xl,  g_xl);
    cudaGetSymbolAddress((void**)&wqh, g_wqh); cudaGetSymbolAddress((void**)&wql, g_wql);
    cudaGetSymbolAddress((void**)&wkh, g_wkh); cudaGetSymbolAddress((void**)&wkl, g_wkl);
    cudaGetSymbolAddress((void**)&wvh, g_wvh); cudaGetSymbolAddress((void**)&wvl, g_wvl);
    cudaGetSymbolAddress((void**)&woh, g_woh); cudaGetSymbolAddress((void**)&wol, g_wol);
    cudaGetSymbolAddress((void**)&ath, g_ath); cudaGetSymbolAddress((void**)&atl, g_atl);
    cudaGetSymbolAddress((void**)&qh,  g_qh);  cudaGetSymbolAddress((void**)&ql,  g_ql);
    cudaGetSymbolAddress((void**)&kh,  g_kh);  cudaGetSymbolAddress((void**)&kl,  g_kl);
    cudaGetSymbolAddress((void**)&vh,  g_vh);  cudaGetSymbolAddress((void**)&vl,  g_vl);

    cudaFuncSetAttribute(gemm_bf16x3_kernel,
                         cudaFuncAttributeMaxDynamicSharedMemorySize, GEMM_SMEM);
    cudaFuncSetAttribute(flash_tc_kernel,
                         cudaFuncAttributeMaxDynamicSharedMemorySize, FLASH_SMEM);

    // 0) splits: x ; wq+wo fused ; wk+wv fused  (3 launches)
    split_kernel<<<dim3((SEQ * DIM / 4 + 255) / 256, 1), 256>>>(
        x, xh, xl, nullptr, nullptr, nullptr, SEQ * DIM / 4);
    split_kernel<<<dim3((DIM * DIM / 4 + 255) / 256, 2), 256>>>(
        wq, wqh, wql, wo, woh, wol, DIM * DIM / 4);
    split_kernel<<<dim3((KVDIM * DIM / 4 + 255) / 256, 2), 256>>>(
        wk, wkh, wkl, wv, wvh, wvl, KVDIM * DIM / 4);

    // 1) fused Q + K + V projections; epilogue applies RoPE (Q,K) / split (V)
    gemm_bf16x3_kernel<<<dim3((DIM + 2 * KVDIM) / GBN, SEQ / GBM, 1), 256, GEMM_SMEM>>>(
        xh, xl,
        wqh, wql, qh, ql, DIM,   1,
        wkh, wkl, kh, kl, KVDIM, 1,
        wvh, wvl, vh, vl,        2,
        fc, fs, DIM);

    // 2) tensor-core flash attention -> attn hi/lo
    flash_tc_kernel<<<dim3(SEQ / BQ, HEADS), 256, FLASH_SMEM>>>(
        qh, ql, kh, kl, vh, vl, ath, atl);

    // 3) O projection (single group, fp32 store)
    gemm_bf16x3_kernel<<<dim3(DIM / GBN, SEQ / GBM, 1), 256, GEMM_SMEM>>>(
        ath, atl,
        woh, wol, out, nullptr, DIM, 0,
        nullptr, nullptr, nullptr, nullptr, 0, 0,
        nullptr, nullptr, nullptr, nullptr, 0,
        nullptr, nullptr, DIM);
}

// round 13
// speedup vs baseline: 1.7670x; 1.0024x over previous
#include <cuda_runtime.h>
#include <cuda_bf16.h>
#include <cstdint>
#include <cstddef>

#define DIM     4096
#define SEQ     2048
#define HEADS   32
#define KVHEADS 8
#define HDIM    128
#define KVDIM   1024   // KVHEADS*HDIM

// ------------------------- scratch (static, no allocation) -------------------
__device__ __nv_bfloat16 g_xh[SEQ * DIM],    g_xl[SEQ * DIM];
__device__ __nv_bfloat16 g_wqh[DIM * DIM],   g_wql[DIM * DIM];
__device__ __nv_bfloat16 g_wkh[KVDIM * DIM], g_wkl[KVDIM * DIM];
__device__ __nv_bfloat16 g_wvh[KVDIM * DIM], g_wvl[KVDIM * DIM];
__device__ __nv_bfloat16 g_woh[DIM * DIM],   g_wol[DIM * DIM];
__device__ __nv_bfloat16 g_ath[SEQ * DIM],   g_atl[SEQ * DIM];
__device__ __nv_bfloat16 g_qh[SEQ * DIM],    g_ql[SEQ * DIM];
__device__ __nv_bfloat16 g_kh[SEQ * KVDIM],  g_kl[SEQ * KVDIM];
__device__ __nv_bfloat16 g_vh[SEQ * KVDIM],  g_vl[SEQ * KVDIM];

// ============================================================================
// split: fp32 -> bf16 hi + bf16 lo. blockIdx.y==1 switches to (x2, hi2, lo2).
// ============================================================================
__global__ void split_kernel(const float* __restrict__ x,
                             __nv_bfloat16* __restrict__ hi,
                             __nv_bfloat16* __restrict__ lo,
                             const float* __restrict__ x2,
                             __nv_bfloat16* __restrict__ hi2,
                             __nv_bfloat16* __restrict__ lo2, int n4)
{
    const int i = blockIdx.x * blockDim.x + threadIdx.x;
    if (i >= n4) return;
    if (blockIdx.y == 1) { x = x2; hi = hi2; lo = lo2; }
    float4 v = ((const float4*)x)[i];
    __nv_bfloat16 h0 = __float2bfloat16(v.x);
    __nv_bfloat16 h1 = __float2bfloat16(v.y);
    __nv_bfloat16 h2 = __float2bfloat16(v.z);
    __nv_bfloat16 h3 = __float2bfloat16(v.w);
    __nv_bfloat16 l0 = __float2bfloat16(v.x - __bfloat162float(h0));
    __nv_bfloat16 l1 = __float2bfloat16(v.y - __bfloat162float(h1));
    __nv_bfloat16 l2 = __float2bfloat16(v.z - __bfloat162float(h2));
    __nv_bfloat16 l3 = __float2bfloat16(v.w - __bfloat162float(h3));
    __nv_bfloat162 hp0 = __halves2bfloat162(h0, h1);
    __nv_bfloat162 hp1 = __halves2bfloat162(h2, h3);
    __nv_bfloat162 lp0 = __halves2bfloat162(l0, l1);
    __nv_bfloat162 lp1 = __halves2bfloat162(l2, l3);
    uint2 hv, lv;
    hv.x = *(uint32_t*)&hp0; hv.y = *(uint32_t*)&hp1;
    lv.x = *(uint32_t*)&lp0; lv.y = *(uint32_t*)&lp1;
    ((uint2*)hi)[i] = hv;
    ((uint2*)lo)[i] = lv;
}

// ============================================================================
// shared mma helpers
// ============================================================================
__device__ __forceinline__ void ldsm4(uint32_t* r, uint32_t addr) {
    asm volatile("ldmatrix.sync.aligned.m8n8.x4.shared.b16 {%0,%1,%2,%3}, [%4];"
                 : "=r"(r[0]), "=r"(r[1]), "=r"(r[2]), "=r"(r[3]) : "r"(addr));
}
__device__ __forceinline__ void ldsm4t(uint32_t* r, uint32_t addr) {
    asm volatile("ldmatrix.sync.aligned.m8n8.x4.trans.shared.b16 {%0,%1,%2,%3}, [%4];"
                 : "=r"(r[0]), "=r"(r[1]), "=r"(r[2]), "=r"(r[3]) : "r"(addr));
}
__device__ __forceinline__ void mma16816(float* c, const uint32_t* a, const uint32_t* b) {
    asm volatile("mma.sync.aligned.m16n8k16.row.col.f32.bf16.bf16.f32 "
                 "{%0,%1,%2,%3},{%4,%5,%6,%7},{%8,%9},{%0,%1,%2,%3};"
                 : "+f"(c[0]), "+f"(c[1]), "+f"(c[2]), "+f"(c[3])
                 : "r"(a[0]), "r"(a[1]), "r"(a[2]), "r"(a[3]), "r"(b[0]), "r"(b[1]));
}

#define CP16(dst, src) asm volatile("cp.async.cg.shared.global [%0], [%1], 16;" :: "r"(dst), "l"(src))
#define CP_COMMIT()    asm volatile("cp.async.commit_group;")
#define CP_WAIT(n)     asm volatile("cp.async.wait_group %0;" :: "n"(n))

// smem byte offset with XOR swizzle (row stride 64B, 16B chunks)
__device__ __forceinline__ uint32_t soff(int row, int chunk) {
    return (uint32_t)((row << 6) + ((chunk ^ ((row >> 1) & 3)) << 4));
}

// split pair -> hi/lo bf16x2 words
__device__ __forceinline__ void split2(float a, float b, uint32_t& h, uint32_t& l) {
    __nv_bfloat162 hp = __floats2bfloat162_rn(a, b);
    __nv_bfloat162 lp = __floats2bfloat162_rn(a - __low2float(hp), b - __high2float(hp));
    h = *(uint32_t*)&hp;
    l = *(uint32_t*)&lp;
}

// ============================================================================
// bf16x3 tensor-core GEMM:  C[M,N](fp32) = A[M,K] * B[N,K]^T
// 64x64x32 CTA tile, 256 thr (8 warps, 2x4), warp tile 32x16,
// 4 CTAs/SM (reg cap 64 -> 32 warps/SM), 3-stage cp.async ring,
// single barrier per k-iter.
// Column-group dispatch: up to 3 concatenated output matrices sharing A.
// Epilogue modes per group: 0 = fp32 store, 1 = rope + bf16 hi/lo, 2 = bf16 hi/lo.
// ============================================================================
#define GBM 64
#define GBN 64
#define GBK 32
#define SMATG 4096                  // one 64x32 bf16 matrix (64B rows)
#define GSTAGE (4 * SMATG)          // Ah, Al, Bh, Bl = 16KB
#define GEMM_SMEM (3 * GSTAGE)      // 48KB -> 4 CTAs/SM

__global__ void __launch_bounds__(256, 4) gemm_bf16x3_kernel(
    const __nv_bfloat16* __restrict__ Ah, const __nv_bfloat16* __restrict__ Al,
    const __nv_bfloat16* B0h, const __nv_bfloat16* B0l, void* C0h, void* C0l, int N0, int mode0,
    const __nv_bfloat16* B1h, const __nv_bfloat16* B1l, void* C1h, void* C1l, int N1, int mode1,
    const __nv_bfloat16* B2h, const __nv_bfloat16* B2l, void* C2h, void* C2l, int mode2,
    const float* __restrict__ fc, const float* __restrict__ fs, int K)
{
    // column-group selection (uniform per CTA)
    const int bng = blockIdx.x * GBN;
    const __nv_bfloat16 *Bh, *Bl;
    void *Ch, *Cl;
    int N, bn, mode;
    if (bng < N0)           { Bh = B0h; Bl = B0l; Ch = C0h; Cl = C0l; N = N0; bn = bng; mode = mode0; }
    else if (bng < N0 + N1) { Bh = B1h; Bl = B1l; Ch = C1h; Cl = C1l; N = N1; bn = bng - N0; mode = mode1; }
    else                    { Bh = B2h; Bl = B2l; Ch = C2h; Cl = C2l; N = N1; bn = bng - N0 - N1; mode = mode2; }

    extern __shared__ char smem[];
    const int tid  = threadIdx.x;
    const int lane = tid & 31;
    const int w    = tid >> 5;
    const int wm   = w >> 2;          // 0..1  (32-row band)
    const int wn   = w & 3;           // 0..3  (16-col band)
    const int bm   = blockIdx.y * GBM;

    const int lrow = tid >> 2;        // 0..63
    const int lc   = tid & 3;

    float acc[2][2][4];
    #pragma unroll
    for (int i = 0; i < 2; i++)
        #pragma unroll
        for (int j = 0; j < 2; j++)
            #pragma unroll
            for (int r = 0; r < 4; r++) acc[i][j][r] = 0.0f;

    const uint32_t sbase = (uint32_t)__cvta_generic_to_shared(smem);

    // persistent loader pointers (advance by GBK per stage issued)
    const __nv_bfloat16* pa  = Ah + (size_t)(bm + lrow) * K + lc * 8;
    const __nv_bfloat16* pal = Al + (size_t)(bm + lrow) * K + lc * 8;
    const __nv_bfloat16* pb  = Bh + (size_t)(bn + lrow) * K + lc * 8;
    const __nv_bfloat16* pbl = Bl + (size_t)(bn + lrow) * K + lc * 8;
    const uint32_t soL = soff(lrow, lc);

    auto ldstage = [&](int bufi) {
        const uint32_t buf = sbase + (uint32_t)bufi * GSTAGE;
        CP16(buf + soL,             pa);
        CP16(buf + SMATG + soL,     pal);
        CP16(buf + 2 * SMATG + soL, pb);
        CP16(buf + 3 * SMATG + soL, pbl);
        pa += GBK; pal += GBK; pb += GBK; pbl += GBK;
    };

    const int nst = K / GBK;
    ldstage(0); CP_COMMIT();
    ldstage(1); CP_COMMIT();

    const int rl = lane & 15;
    const int rh = lane >> 4;
    int nbuf = 2;   // buffer for stage it+2
    int cbuf = 0;   // buffer for stage it

    for (int it = 0; it < nst; ++it) {
        // wait own groups FIRST, then one barrier (publishes stage it CTA-wide
        // and licenses refilling buf((it+2)%3), last read by compute(it-1)).
        if (it < nst - 1) { CP_WAIT(1); } else { CP_WAIT(0); }
        __syncthreads();

        if (it + 2 < nst) {
            ldstage(nbuf);
            CP_COMMIT();
            nbuf = (nbuf == 2) ? 0 : nbuf + 1;
        }

        const uint32_t buf = sbase + (uint32_t)cbuf * GSTAGE;
        cbuf = (cbuf == 2) ? 0 : cbuf + 1;
        const uint32_t sAh = buf;
        const uint32_t sAl = buf + SMATG;
        const uint32_t sBh = buf + 2 * SMATG;
        const uint32_t sBl = buf + 2 * SMATG + SMATG;

        #pragma unroll
        for (int ks = 0; ks < 2; ks++) {
            const int chunk = 2 * ks + rh;
            uint32_t ah[2][4], bh[2][2], bl[2][2];

            #pragma unroll
            for (int mi = 0; mi < 2; mi++)
                ldsm4(ah[mi], sAh + soff(wm * 32 + mi * 16 + rl, chunk));
            {
                uint32_t r4[4];
                ldsm4(r4, sBh + soff(wn * 16 + rl, chunk));
                bh[0][0] = r4[0]; bh[0][1] = r4[2];
                bh[1][0] = r4[1]; bh[1][1] = r4[3];
            }
            {
                uint32_t r4[4];
                ldsm4(r4, sBl + soff(wn * 16 + rl, chunk));
                bl[0][0] = r4[0]; bl[0][1] = r4[2];
                bl[1][0] = r4[1]; bl[1][1] = r4[3];
            }
            // pass 1: hi*hi (4 independent chains)
            #pragma unroll
            for (int mi = 0; mi < 2; mi++)
                #pragma unroll
                for (int nj = 0; nj < 2; nj++)
                    mma16816(acc[mi][nj], ah[mi], bh[nj]);
            // pass 2: hi*lo
            #pragma unroll
            for (int mi = 0; mi < 2; mi++)
                #pragma unroll
                for (int nj = 0; nj < 2; nj++)
                    mma16816(acc[mi][nj], ah[mi], bl[nj]);
            // pass 3: lo*hi (reuse ah registers for al — ah dead after pass 2)
            #pragma unroll
            for (int mi = 0; mi < 2; mi++)
                ldsm4(ah[mi], sAl + soff(wm * 32 + mi * 16 + rl, chunk));
            #pragma unroll
            for (int mi = 0; mi < 2; mi++)
                #pragma unroll
                for (int nj = 0; nj < 2; nj++)
                    mma16816(acc[mi][nj], ah[mi], bh[nj]);
        }
        // no bottom barrier: next iter's top barrier provides the WAR guard.
    }

    // ---------------- epilogue ----------------
    const int tg = lane >> 2;
    const int ti = lane & 3;
    if (mode == 0) {
        float* C = (float*)Ch;
        #pragma unroll
        for (int mi = 0; mi < 2; mi++) {
            const int row = bm + wm * 32 + mi * 16 + tg;
            #pragma unroll
            for (int nj = 0; nj < 2; nj++) {
                const int col = bn + wn * 16 + nj * 8 + 2 * ti;
                *(float2*)&C[(size_t)row * N + col]       = make_float2(acc[mi][nj][0], acc[mi][nj][1]);
                *(float2*)&C[(size_t)(row + 8) * N + col] = make_float2(acc[mi][nj][2], acc[mi][nj][3]);
            }
        }
    } else {
        __nv_bfloat16* Hi = (__nv_bfloat16*)Ch;
        __nv_bfloat16* Lo = (__nv_bfloat16*)Cl;
        #pragma unroll
        for (int mi = 0; mi < 2; mi++) {
            const int row = bm + wm * 32 + mi * 16 + tg;
            #pragma unroll
            for (int nj = 0; nj < 2; nj++) {
                const int col = bn + wn * 16 + nj * 8 + 2 * ti;
                float a0 = acc[mi][nj][0], a1 = acc[mi][nj][1];
                float a2 = acc[mi][nj][2], a3 = acc[mi][nj][3];
                if (mode == 1) {
                    const int p = (col & 127) >> 1;
                    const float c0 = fc[row * 64 + p],       s0 = fs[row * 64 + p];
                    const float c1 = fc[(row + 8) * 64 + p], s1 = fs[(row + 8) * 64 + p];
                    float r0 = a0 * c0 - a1 * s0, r1 = a0 * s0 + a1 * c0;
                    float r2 = a2 * c1 - a3 * s1, r3 = a2 * s1 + a3 * c1;
                    a0 = r0; a1 = r1; a2 = r2; a3 = r3;
                }
                uint32_t h0, l0, h1, l1;
                split2(a0, a1, h0, l0);
                split2(a2, a3, h1, l1);
                *(uint32_t*)&Hi[(size_t)row * N + col]       = h0;
                *(uint32_t*)&Lo[(size_t)row * N + col]       = l0;
                *(uint32_t*)&Hi[(size_t)(row + 8) * N + col] = h1;
                *(uint32_t*)&Lo[(size_t)(row + 8) * N + col] = l1;
            }
        }
    }
}

// ============================================================================
// Tensor-core flash attention, bf16x3, causal, GQA. Pass-major schedule.
// ============================================================================
#define BQ 128
#define BKV 64
#define QMAT 32768
#define KVMAT 16384
#define FSTAGE (4 * KVMAT)
#define FLASH_SMEM (2 * QMAT + 2 * FSTAGE)

__device__ __forceinline__ uint32_t fsw(int r, int c) {
    return (uint32_t)((r << 8) + ((c ^ (r & 7)) << 4));
}
__device__ __forceinline__ uint32_t pack_hi_rz(float p0, float p1, float& lo0, float& lo1) {
    uint32_t u0 = __float_as_uint(p0), u1 = __float_as_uint(p1);
    lo0 = p0 - __uint_as_float(u0 & 0xffff0000u);
    lo1 = p1 - __uint_as_float(u1 & 0xffff0000u);
    return __byte_perm(u0, u1, 0x7632);
}
__device__ __forceinline__ uint32_t pack_rn(float a, float b) {
    __nv_bfloat162 t = __floats2bfloat162_rn(a, b);
    return *(uint32_t*)&t;
}

__global__ void __launch_bounds__(256, 1) flash_tc_kernel(
    const __nv_bfloat16* __restrict__ qh, const __nv_bfloat16* __restrict__ ql,
    const __nv_bfloat16* __restrict__ kh, const __nv_bfloat16* __restrict__ kl,
    const __nv_bfloat16* __restrict__ vh, const __nv_bfloat16* __restrict__ vl,
    __nv_bfloat16* __restrict__ ath, __nv_bfloat16* __restrict__ atl)
{
    extern __shared__ char smc[];
    const uint32_t sb  = (uint32_t)__cvta_generic_to_shared(smc);
    const uint32_t sQh = sb, sQl = sb + QMAT;

    const int tid  = threadIdx.x;
    const int lane = tid & 31;
    const int w    = tid >> 5;
    const int rl   = lane & 15;
    const int rh   = lane >> 4;
    const int tg   = lane >> 2;
    const int ti   = lane & 3;
    const int vro  = (lane & 7) + ((lane >> 3) & 1) * 8;
    const int vco  = lane >> 4;

    const int qt    = gridDim.x - 1 - blockIdx.x;
    const int h     = blockIdx.y;
    const int kvh   = h >> 2;
    const int qbase = qt * BQ;
    const int wrow  = w * 16;

    for (int f = tid; f < 2048; f += 256) {
        const int r = f >> 4, c = f & 15;
        const size_t go = (size_t)(qbase + r) * DIM + h * HDIM + c * 8;
        CP16(sQh + fsw(r, c), qh + go);
        CP16(sQl + fsw(r, c), ql + go);
    }
    CP_COMMIT();

    auto loadKV = [&](int kt) {
        const uint32_t base = sb + 2 * QMAT + (kt & 1) * FSTAGE;
        const int kvb = kt * BKV;
        for (int f = tid; f < 1024; f += 256) {
            const int r = f >> 4, c = f & 15;
            const size_t go = (size_t)(kvb + r) * KVDIM + kvh * HDIM + c * 8;
            const uint32_t so = fsw(r, c);
            CP16(base + so,             kh + go);
            CP16(base + KVMAT + so,     kl + go);
            CP16(base + 2 * KVMAT + so, vh + go);
            CP16(base + 3 * KVMAT + so, vl + go);
        }
    };

    loadKV(0);
    CP_COMMIT();

    float o[16][4];
    #pragma unroll
    for (int i = 0; i < 16; i++)
        #pragma unroll
        for (int r = 0; r < 4; r++) o[i][r] = 0.0f;
    float m0 = -1e30f, m1 = -1e30f, l0 = 0.0f, l1 = 0.0f;
    const float scale = 0.08838834764831843f;
    const int row0 = qbase + wrow + tg;
    const int row1 = row0 + 8;

    const int nkt = 2 * qt + 2;
    for (int kt = 0; kt < nkt; kt++) {
        if (kt + 1 < nkt) { loadKV(kt + 1); CP_COMMIT(); CP_WAIT(1); }
        else              { CP_WAIT(0); }
        __syncthreads();

        const uint32_t base = sb + 2 * QMAT + (kt & 1) * FSTAGE;
        const uint32_t sKh = base, sKl = base + KVMAT;
        const uint32_t sVh = base + 2 * KVMAT, sVl = base + 3 * KVMAT;
        const int kvb = kt * BKV;

        // ---- S = Q K^T, pass-major ----
        float s[8][4];
        #pragma unroll
        for (int i = 0; i < 8; i++)
            #pragma unroll
            for (int r = 0; r < 4; r++) s[i][r] = 0.0f;

        #pragma unroll
        for (int kc = 0; kc < 8; kc++) {
            uint32_t ah[4], al[4];
            ldsm4(ah, sQh + fsw(wrow + rl, 2 * kc + rh));
            ldsm4(al, sQl + fsw(wrow + rl, 2 * kc + rh));

            uint32_t bh[8][2], bl[8][2];
            #pragma unroll
            for (int nb = 0; nb < 4; nb++) {
                uint32_t rk[4], rkl[4];
                ldsm4(rk,  sKh + fsw(nb * 16 + rl, 2 * kc + rh));
                ldsm4(rkl, sKl + fsw(nb * 16 + rl, 2 * kc + rh));
                bh[2 * nb][0]     = rk[0];  bh[2 * nb][1]     = rk[2];
                bh[2 * nb + 1][0] = rk[1];  bh[2 * nb + 1][1] = rk[3];
                bl[2 * nb][0]     = rkl[0]; bl[2 * nb][1]     = rkl[2];
                bl[2 * nb + 1][0] = rkl[1]; bl[2 * nb + 1][1] = rkl[3];
            }
            #pragma unroll
            for (int nj = 0; nj < 8; nj++) mma16816(s[nj], ah, bh[nj]);
            #pragma unroll
            for (int nj = 0; nj < 8; nj++) mma16816(s[nj], ah, bl[nj]);
            #pragma unroll
            for (int nj = 0; nj < 8; nj++) mma16816(s[nj], al, bh[nj]);
        }

        // ---- scale + causal mask ----
        const bool needmask = (kt >= 2 * qt);
        #pragma unroll
        for (int nj = 0; nj < 8; nj++) {
            #pragma unroll
            for (int r = 0; r < 4; r++) {
                float v = s[nj][r] * scale;
                if (needmask) {
                    const int col = kvb + nj * 8 + 2 * ti + (r & 1);
                    const int row = (r & 2) ? row1 : row0;
                    if (col > row) v = -1e30f;
                }
                s[nj][r] = v;
            }
        }

        // ---- online softmax ----
        float mx0 = -1e30f, mx1 = -1e30f;
        #pragma unroll
        for (int nj = 0; nj < 8; nj++) {
            mx0 = fmaxf(mx0, fmaxf(s[nj][0], s[nj][1]));
            mx1 = fmaxf(mx1, fmaxf(s[nj][2], s[nj][3]));
        }
        mx0 = fmaxf(mx0, __shfl_xor_sync(0xffffffffu, mx0, 1));
        mx0 = fmaxf(mx0, __shfl_xor_sync(0xffffffffu, mx0, 2));
        mx1 = fmaxf(mx1, __shfl_xor_sync(0xffffffffu, mx1, 1));
        mx1 = fmaxf(mx1, __shfl_xor_sync(0xffffffffu, mx1, 2));
        const float mn0 = fmaxf(m0, mx0), mn1 = fmaxf(m1, mx1);
        const float cr0 = __expf(m0 - mn0), cr1 = __expf(m1 - mn1);
        m0 = mn0; m1 = mn1;

        float sum0 = 0.0f, sum1 = 0.0f;
        #pragma unroll
        for (int nj = 0; nj < 8; nj++) {
            s[nj][0] = __expf(s[nj][0] - mn0); sum0 += s[nj][0];
            s[nj][1] = __expf(s[nj][1] - mn0); sum0 += s[nj][1];
            s[nj][2] = __expf(s[nj][2] - mn1); sum1 += s[nj][2];
            s[nj][3] = __expf(s[nj][3] - mn1); sum1 += s[nj][3];
        }
        sum0 += __shfl_xor_sync(0xffffffffu, sum0, 1);
        sum0 += __shfl_xor_sync(0xffffffffu, sum0, 2);
        sum1 += __shfl_xor_sync(0xffffffffu, sum1, 1);
        sum1 += __shfl_xor_sync(0xffffffffu, sum1, 2);
        l0 = l0 * cr0 + sum0;
        l1 = l1 * cr1 + sum1;

        #pragma unroll
        for (int nj = 0; nj < 16; nj++) {
            o[nj][0] *= cr0; o[nj][1] *= cr0;
            o[nj][2] *= cr1; o[nj][3] *= cr1;
        }

        // ---- O += P V, pass-major over halves ----
        #pragma unroll
        for (int kc = 0; kc < 4; kc++) {
            uint32_t pah[4], pal[4];
            {
                float la, lb;
                pah[0] = pack_hi_rz(s[2 * kc][0],     s[2 * kc][1],     la, lb); pal[0] = pack_rn(la, lb);
                pah[1] = pack_hi_rz(s[2 * kc][2],     s[2 * kc][3],     la, lb); pal[1] = pack_rn(la, lb);
                pah[2] = pack_hi_rz(s[2 * kc + 1][0], s[2 * kc + 1][1], la, lb); pal[2] = pack_rn(la, lb);
                pah[3] = pack_hi_rz(s[2 * kc + 1][2], s[2 * kc + 1][3], la, lb); pal[3] = pack_rn(la, lb);
            }
            #pragma unroll
            for (int half = 0; half < 2; half++) {
                uint32_t bv[8][2], cv[8][2];
                #pragma unroll
                for (int n4 = 0; n4 < 4; n4++) {
                    const int nb = half * 4 + n4;
                    uint32_t rv[4], rw[4];
                    const uint32_t so = fsw(kc * 16 + vro, 2 * nb + vco);
                    ldsm4t(rv, sVh + so);
                    ldsm4t(rw, sVl + so);
                    bv[2 * n4][0]     = rv[0]; bv[2 * n4][1]     = rv[1];
                    bv[2 * n4 + 1][0] = rv[2]; bv[2 * n4 + 1][1] = rv[3];
                    cv[2 * n4][0]     = rw[0]; cv[2 * n4][1]     = rw[1];
                    cv[2 * n4 + 1][0] = rw[2]; cv[2 * n4 + 1][1] = rw[3];
                }
                #pragma unroll
                for (int j = 0; j < 8; j++) mma16816(o[8 * half + j], pah, bv[j]);
                #pragma unroll
                for (int j = 0; j < 8; j++) mma16816(o[8 * half + j], pah, cv[j]);
                #pragma unroll
                for (int j = 0; j < 8; j++) mma16816(o[8 * half + j], pal, bv[j]);
            }
        }
        __syncthreads();
    }

    // ---- epilogue: normalize, split hi/lo, store ----
    const float inv0 = 1.0f / l0, inv1 = 1.0f / l1;
    #pragma unroll
    for (int nj = 0; nj < 16; nj++) {
        const int col = h * HDIM + nj * 8 + 2 * ti;
        float v0 = o[nj][0] * inv0, v1 = o[nj][1] * inv0;
        float v2 = o[nj][2] * inv1, v3 = o[nj][3] * inv1;
        __nv_bfloat162 h0 = __floats2bfloat162_rn(v0, v1);
        __nv_bfloat162 h1 = __floats2bfloat162_rn(v2, v3);
        __nv_bfloat162 e0 = __floats2bfloat162_rn(v0 - __low2float(h0), v1 - __high2float(h0));
        __nv_bfloat162 e1 = __floats2bfloat162_rn(v2 - __low2float(h1), v3 - __high2float(h1));
        *(uint32_t*)&ath[(size_t)row0 * DIM + col] = *(uint32_t*)&h0;
        *(uint32_t*)&ath[(size_t)row1 * DIM + col] = *(uint32_t*)&h1;
        *(uint32_t*)&atl[(size_t)row0 * DIM + col] = *(uint32_t*)&e0;
        *(uint32_t*)&atl[(size_t)row1 * DIM + col] = *(uint32_t*)&e1;
    }
}

// ============================================================================
// launch
// ============================================================================
extern "C" void kernel_launch(void* const* d_in, const int* in_sizes, int n_in,
                              void* d_out, int out_size)
{
    (void)in_sizes; (void)n_in; (void)out_size;
    const float* x  = (const float*)d_in[0];
    const float* wq = (const float*)d_in[1];
    const float* wk = (const float*)d_in[2];
    const float* wv = (const float*)d_in[3];
    const float* wo = (const float*)d_in[4];
    const float* fc = (const float*)d_in[5];
    const float* fs = (const float*)d_in[6];
    float* out = (float*)d_out;

    __nv_bfloat16 *xh, *xl, *wqh, *wql, *wkh, *wkl, *wvh, *wvl, *woh, *wol;
    __nv_bfloat16 *ath, *atl, *qh, *ql, *kh, *kl, *vh, *vl;
    cudaGetSymbolAddress((void**)&xh,  g_xh);  cudaGetSymbolAddress((void**)&xl,  g_xl);
    cudaGetSymbolAddress((void**)&wqh, g_wqh); cudaGetSymbolAddress((void**)&wql, g_wql);
    cudaGetSymbolAddress((void**)&wkh, g_wkh); cudaGetSymbolAddress((void**)&wkl, g_wkl);
    cudaGetSymbolAddress((void**)&wvh, g_wvh); cudaGetSymbolAddress((void**)&wvl, g_wvl);
    cudaGetSymbolAddress((void**)&woh, g_woh); cudaGetSymbolAddress((void**)&wol, g_wol);
    cudaGetSymbolAddress((void**)&ath, g_ath); cudaGetSymbolAddress((void**)&atl, g_atl);
    cudaGetSymbolAddress((void**)&qh,  g_qh);  cudaGetSymbolAddress((void**)&ql,  g_ql);
    cudaGetSymbolAddress((void**)&kh,  g_kh);  cudaGetSymbolAddress((void**)&kl,  g_kl);
    cudaGetSymbolAddress((void**)&vh,  g_vh);  cudaGetSymbolAddress((void**)&vl,  g_vl);

    cudaFuncSetAttribute(gemm_bf16x3_kernel,
                         cudaFuncAttributeMaxDynamicSharedMemorySize, GEMM_SMEM);
    cudaFuncSetAttribute(flash_tc_kernel,
                         cudaFuncAttributeMaxDynamicSharedMemorySize, FLASH_SMEM);

    // 0) splits: x ; wq+wo fused ; wk+wv fused  (3 launches)
    split_kernel<<<dim3((SEQ * DIM / 4 + 255) / 256, 1), 256>>>(
        x, xh, xl, nullptr, nullptr, nullptr, SEQ * DIM / 4);
    split_kernel<<<dim3((DIM * DIM / 4 + 255) / 256, 2), 256>>>(
        wq, wqh, wql, wo, woh, wol, DIM * DIM / 4);
    split_kernel<<<dim3((KVDIM * DIM / 4 + 255) / 256, 2), 256>>>(
        wk, wkh, wkl, wv, wvh, wvl, KVDIM * DIM / 4);

    // 1) fused Q + K + V projections; epilogue applies RoPE (Q,K) / split (V)
    gemm_bf16x3_kernel<<<dim3((DIM + 2 * KVDIM) / GBN, SEQ / GBM, 1), 256, GEMM_SMEM>>>(
        xh, xl,
        wqh, wql, qh, ql, DIM,   1,
        wkh, wkl, kh, kl, KVDIM, 1,
        wvh, wvl, vh, vl,        2,
        fc, fs, DIM);

    // 2) tensor-core flash attention -> attn hi/lo
    flash_tc_kernel<<<dim3(SEQ / BQ, HEADS), 256, FLASH_SMEM>>>(
        qh, ql, kh, kl, vh, vl, ath, atl);

    // 3) O projection (single group, fp32 store)
    gemm_bf16x3_kernel<<<dim3(DIM / GBN, SEQ / GBM, 1), 256, GEMM_SMEM>>>(
        ath, atl,
        woh, wol, out, nullptr, DIM, 0,
        nullptr, nullptr, nullptr, nullptr, 0, 0,
        nullptr, nullptr, nullptr, nullptr, 0,
        nullptr, nullptr, DIM);
}

// round 14
// speedup vs baseline: 1.8386x; 1.0406x over previous
#include <cuda_runtime.h>
#include <cuda_bf16.h>
#include <cstdint>
#include <cstddef>

#define DIM     4096
#define SEQ     2048
#define HEADS   32
#define KVHEADS 8
#define HDIM    128
#define KVDIM   1024   // KVHEADS*HDIM

// ------------------------- scratch (static, no allocation) -------------------
__device__ __nv_bfloat16 g_xh[SEQ * DIM],    g_xl[SEQ * DIM];
__device__ __nv_bfloat16 g_wqh[DIM * DIM],   g_wql[DIM * DIM];
__device__ __nv_bfloat16 g_wkh[KVDIM * DIM], g_wkl[KVDIM * DIM];
__device__ __nv_bfloat16 g_wvh[KVDIM * DIM], g_wvl[KVDIM * DIM];
__device__ __nv_bfloat16 g_woh[DIM * DIM],   g_wol[DIM * DIM];
__device__ __nv_bfloat16 g_ath[SEQ * DIM],   g_atl[SEQ * DIM];
__device__ __nv_bfloat16 g_qh[SEQ * DIM],    g_ql[SEQ * DIM];
__device__ __nv_bfloat16 g_kh[SEQ * KVDIM],  g_kl[SEQ * KVDIM];
__device__ __nv_bfloat16 g_vh[SEQ * KVDIM],  g_vl[SEQ * KVDIM];

// ============================================================================
// split: fp32 -> bf16 hi + bf16 lo. blockIdx.y==1 switches to (x2, hi2, lo2).
// ============================================================================
__global__ void split_kernel(const float* __restrict__ x,
                             __nv_bfloat16* __restrict__ hi,
                             __nv_bfloat16* __restrict__ lo,
                             const float* __restrict__ x2,
                             __nv_bfloat16* __restrict__ hi2,
                             __nv_bfloat16* __restrict__ lo2, int n4)
{
    const int i = blockIdx.x * blockDim.x + threadIdx.x;
    if (i >= n4) return;
    if (blockIdx.y == 1) { x = x2; hi = hi2; lo = lo2; }
    float4 v = ((const float4*)x)[i];
    __nv_bfloat16 h0 = __float2bfloat16(v.x);
    __nv_bfloat16 h1 = __float2bfloat16(v.y);
    __nv_bfloat16 h2 = __float2bfloat16(v.z);
    __nv_bfloat16 h3 = __float2bfloat16(v.w);
    __nv_bfloat16 l0 = __float2bfloat16(v.x - __bfloat162float(h0));
    __nv_bfloat16 l1 = __float2bfloat16(v.y - __bfloat162float(h1));
    __nv_bfloat16 l2 = __float2bfloat16(v.z - __bfloat162float(h2));
    __nv_bfloat16 l3 = __float2bfloat16(v.w - __bfloat162float(h3));
    __nv_bfloat162 hp0 = __halves2bfloat162(h0, h1);
    __nv_bfloat162 hp1 = __halves2bfloat162(h2, h3);
    __nv_bfloat162 lp0 = __halves2bfloat162(l0, l1);
    __nv_bfloat162 lp1 = __halves2bfloat162(l2, l3);
    uint2 hv, lv;
    hv.x = *(uint32_t*)&hp0; hv.y = *(uint32_t*)&hp1;
    lv.x = *(uint32_t*)&lp0; lv.y = *(uint32_t*)&lp1;
    ((uint2*)hi)[i] = hv;
    ((uint2*)lo)[i] = lv;
}

// ============================================================================
// shared mma helpers
// ============================================================================
__device__ __forceinline__ void ldsm4(uint32_t* r, uint32_t addr) {
    asm volatile("ldmatrix.sync.aligned.m8n8.x4.shared.b16 {%0,%1,%2,%3}, [%4];"
                 : "=r"(r[0]), "=r"(r[1]), "=r"(r[2]), "=r"(r[3]) : "r"(addr));
}
__device__ __forceinline__ void ldsm4t(uint32_t* r, uint32_t addr) {
    asm volatile("ldmatrix.sync.aligned.m8n8.x4.trans.shared.b16 {%0,%1,%2,%3}, [%4];"
                 : "=r"(r[0]), "=r"(r[1]), "=r"(r[2]), "=r"(r[3]) : "r"(addr));
}
__device__ __forceinline__ void mma16816(float* c, const uint32_t* a, const uint32_t* b) {
    asm volatile("mma.sync.aligned.m16n8k16.row.col.f32.bf16.bf16.f32 "
                 "{%0,%1,%2,%3},{%4,%5,%6,%7},{%8,%9},{%0,%1,%2,%3};"
                 : "+f"(c[0]), "+f"(c[1]), "+f"(c[2]), "+f"(c[3])
                 : "r"(a[0]), "r"(a[1]), "r"(a[2]), "r"(a[3]), "r"(b[0]), "r"(b[1]));
}

#define CP16(dst, src) asm volatile("cp.async.cg.shared.global [%0], [%1], 16;" :: "r"(dst), "l"(src))
#define CP_COMMIT()    asm volatile("cp.async.commit_group;")
#define CP_WAIT(n)     asm volatile("cp.async.wait_group %0;" :: "n"(n))

// smem byte offset with XOR swizzle (row stride 64B, 16B chunks)
__device__ __forceinline__ uint32_t soff(int row, int chunk) {
    return (uint32_t)((row << 6) + ((chunk ^ ((row >> 1) & 3)) << 4));
}

// split pair -> hi/lo bf16x2 words
__device__ __forceinline__ void split2(float a, float b, uint32_t& h, uint32_t& l) {
    __nv_bfloat162 hp = __floats2bfloat162_rn(a, b);
    __nv_bfloat162 lp = __floats2bfloat162_rn(a - __low2float(hp), b - __high2float(hp));
    h = *(uint32_t*)&hp;
    l = *(uint32_t*)&lp;
}

// ============================================================================
// bf16x3 tensor-core GEMM:  C[M,N](fp32) = A[M,K] * B[N,K]^T
// 64x128x32 CTA tile, 256 thr (8 warps, 2m x 4n), warp tile 32x32
// (square tile minimizes LDSM bytes per MAC), 3 CTAs/SM (reg cap 85),
// 3-stage cp.async ring, single barrier per k-iter.
// Column-group dispatch: up to 3 concatenated output matrices sharing A.
// Epilogue modes per group: 0 = fp32 store, 1 = rope + bf16 hi/lo, 2 = bf16 hi/lo.
// ============================================================================
#define GBM 64
#define GBN 128
#define GBK 32
#define ASZ 4096                    // A: 64 rows x 64B
#define BSZ 8192                    // B: 128 rows x 64B
#define GSTAGE (2 * ASZ + 2 * BSZ)  // 24KB
#define GEMM_SMEM (3 * GSTAGE)      // 72KB -> 3 CTAs/SM

__global__ void __launch_bounds__(256, 3) gemm_bf16x3_kernel(
    const __nv_bfloat16* __restrict__ Ah, const __nv_bfloat16* __restrict__ Al,
    const __nv_bfloat16* B0h, const __nv_bfloat16* B0l, void* C0h, void* C0l, int N0, int mode0,
    const __nv_bfloat16* B1h, const __nv_bfloat16* B1l, void* C1h, void* C1l, int N1, int mode1,
    const __nv_bfloat16* B2h, const __nv_bfloat16* B2l, void* C2h, void* C2l, int mode2,
    const float* __restrict__ fc, const float* __restrict__ fs, int K)
{
    // column-group selection (uniform per CTA)
    const int bng = blockIdx.x * GBN;
    const __nv_bfloat16 *Bh, *Bl;
    void *Ch, *Cl;
    int N, bn, mode;
    if (bng < N0)           { Bh = B0h; Bl = B0l; Ch = C0h; Cl = C0l; N = N0; bn = bng; mode = mode0; }
    else if (bng < N0 + N1) { Bh = B1h; Bl = B1l; Ch = C1h; Cl = C1l; N = N1; bn = bng - N0; mode = mode1; }
    else                    { Bh = B2h; Bl = B2l; Ch = C2h; Cl = C2l; N = N1; bn = bng - N0 - N1; mode = mode2; }

    extern __shared__ char smem[];
    const int tid  = threadIdx.x;
    const int lane = tid & 31;
    const int w    = tid >> 5;
    const int wm   = w >> 2;          // 0..1  (32-row band)
    const int wn   = w & 3;           // 0..3  (32-col band)
    const int bm   = blockIdx.y * GBM;

    const int lrow = tid >> 2;        // 0..63
    const int lc   = tid & 3;

    float acc[2][4][4];
    #pragma unroll
    for (int i = 0; i < 2; i++)
        #pragma unroll
        for (int j = 0; j < 4; j++)
            #pragma unroll
            for (int r = 0; r < 4; r++) acc[i][j][r] = 0.0f;

    const uint32_t sbase = (uint32_t)__cvta_generic_to_shared(smem);

    // persistent loader pointers (advance by GBK per stage issued)
    const __nv_bfloat16* pa  = Ah + (size_t)(bm + lrow) * K + lc * 8;
    const __nv_bfloat16* pal = Al + (size_t)(bm + lrow) * K + lc * 8;
    const __nv_bfloat16* pb  = Bh + (size_t)(bn + lrow) * K + lc * 8;
    const __nv_bfloat16* pbl = Bl + (size_t)(bn + lrow) * K + lc * 8;
    const size_t brow64 = (size_t)64 * K;
    const uint32_t soA  = soff(lrow, lc);
    const uint32_t soB1 = soff(lrow + 64, lc);

    auto ldstage = [&](int bufi) {
        const uint32_t buf = sbase + (uint32_t)bufi * GSTAGE;
        CP16(buf + soA,                   pa);
        CP16(buf + ASZ + soA,             pal);
        CP16(buf + 2 * ASZ + soA,         pb);
        CP16(buf + 2 * ASZ + soB1,        pb + brow64);
        CP16(buf + 2 * ASZ + BSZ + soA,   pbl);
        CP16(buf + 2 * ASZ + BSZ + soB1,  pbl + brow64);
        pa += GBK; pal += GBK; pb += GBK; pbl += GBK;
    };

    const int nst = K / GBK;
    ldstage(0); CP_COMMIT();
    ldstage(1); CP_COMMIT();

    const int rl = lane & 15;
    const int rh = lane >> 4;
    int nbuf = 2;   // buffer for stage it+2
    int cbuf = 0;   // buffer for stage it

    for (int it = 0; it < nst; ++it) {
        // wait own groups FIRST, then one barrier (publishes stage it CTA-wide
        // and licenses refilling buf((it+2)%3), last read by compute(it-1)).
        if (it < nst - 1) { CP_WAIT(1); } else { CP_WAIT(0); }
        __syncthreads();

        if (it + 2 < nst) {
            ldstage(nbuf);
            CP_COMMIT();
            nbuf = (nbuf == 2) ? 0 : nbuf + 1;
        }

        const uint32_t buf = sbase + (uint32_t)cbuf * GSTAGE;
        cbuf = (cbuf == 2) ? 0 : cbuf + 1;
        const uint32_t sAh = buf;
        const uint32_t sAl = buf + ASZ;
        const uint32_t sBh = buf + 2 * ASZ;
        const uint32_t sBl = buf + 2 * ASZ + BSZ;

        #pragma unroll
        for (int ks = 0; ks < 2; ks++) {
            const int chunk = 2 * ks + rh;
            uint32_t ah[2][4], bh[4][2], bl[4][2];

            #pragma unroll
            for (int mi = 0; mi < 2; mi++)
                ldsm4(ah[mi], sAh + soff(wm * 32 + mi * 16 + rl, chunk));
            #pragma unroll
            for (int nb = 0; nb < 2; nb++) {
                uint32_t r4[4];
                ldsm4(r4, sBh + soff(wn * 32 + nb * 16 + rl, chunk));
                bh[2 * nb][0] = r4[0]; bh[2 * nb + 1][0] = r4[1];
                bh[2 * nb][1] = r4[2]; bh[2 * nb + 1][1] = r4[3];
            }
            #pragma unroll
            for (int nb = 0; nb < 2; nb++) {
                uint32_t r4[4];
                ldsm4(r4, sBl + soff(wn * 32 + nb * 16 + rl, chunk));
                bl[2 * nb][0] = r4[0]; bl[2 * nb + 1][0] = r4[1];
                bl[2 * nb][1] = r4[2]; bl[2 * nb + 1][1] = r4[3];
            }
            // pass 1: hi*hi (8 independent chains)
            #pragma unroll
            for (int mi = 0; mi < 2; mi++)
                #pragma unroll
                for (int nj = 0; nj < 4; nj++)
                    mma16816(acc[mi][nj], ah[mi], bh[nj]);
            // pass 2: hi*lo
            #pragma unroll
            for (int mi = 0; mi < 2; mi++)
                #pragma unroll
                for (int nj = 0; nj < 4; nj++)
                    mma16816(acc[mi][nj], ah[mi], bl[nj]);
            // pass 3: lo*hi (reuse ah registers for al — ah dead after pass 2)
            #pragma unroll
            for (int mi = 0; mi < 2; mi++)
                ldsm4(ah[mi], sAl + soff(wm * 32 + mi * 16 + rl, chunk));
            #pragma unroll
            for (int mi = 0; mi < 2; mi++)
                #pragma unroll
                for (int nj = 0; nj < 4; nj++)
                    mma16816(acc[mi][nj], ah[mi], bh[nj]);
        }
        // no bottom barrier: next iter's top barrier provides the WAR guard.
    }

    // ---------------- epilogue ----------------
    const int tg = lane >> 2;
    const int ti = lane & 3;
    if (mode == 0) {
        float* C = (float*)Ch;
        #pragma unroll
        for (int mi = 0; mi < 2; mi++) {
            const int row = bm + wm * 32 + mi * 16 + tg;
            #pragma unroll
            for (int nj = 0; nj < 4; nj++) {
                const int col = bn + wn * 32 + nj * 8 + 2 * ti;
                *(float2*)&C[(size_t)row * N + col]       = make_float2(acc[mi][nj][0], acc[mi][nj][1]);
                *(float2*)&C[(size_t)(row + 8) * N + col] = make_float2(acc[mi][nj][2], acc[mi][nj][3]);
            }
        }
    } else {
        __nv_bfloat16* Hi = (__nv_bfloat16*)Ch;
        __nv_bfloat16* Lo = (__nv_bfloat16*)Cl;
        #pragma unroll
        for (int mi = 0; mi < 2; mi++) {
            const int row = bm + wm * 32 + mi * 16 + tg;
            #pragma unroll
            for (int nj = 0; nj < 4; nj++) {
                const int col = bn + wn * 32 + nj * 8 + 2 * ti;
                float a0 = acc[mi][nj][0], a1 = acc[mi][nj][1];
                float a2 = acc[mi][nj][2], a3 = acc[mi][nj][3];
                if (mode == 1) {
                    const int p = (col & 127) >> 1;
                    const float c0 = fc[row * 64 + p],       s0 = fs[row * 64 + p];
                    const float c1 = fc[(row + 8) * 64 + p], s1 = fs[(row + 8) * 64 + p];
                    float r0 = a0 * c0 - a1 * s0, r1 = a0 * s0 + a1 * c0;
                    float r2 = a2 * c1 - a3 * s1, r3 = a2 * s1 + a3 * c1;
                    a0 = r0; a1 = r1; a2 = r2; a3 = r3;
                }
                uint32_t h0, l0, h1, l1;
                split2(a0, a1, h0, l0);
                split2(a2, a3, h1, l1);
                *(uint32_t*)&Hi[(size_t)row * N + col]       = h0;
                *(uint32_t*)&Lo[(size_t)row * N + col]       = l0;
                *(uint32_t*)&Hi[(size_t)(row + 8) * N + col] = h1;
                *(uint32_t*)&Lo[(size_t)(row + 8) * N + col] = l1;
            }
        }
    }
}

// ============================================================================
// Tensor-core flash attention, bf16x3, causal, GQA. Pass-major schedule.
// ============================================================================
#define BQ 128
#define BKV 64
#define QMAT 32768
#define KVMAT 16384
#define FSTAGE (4 * KVMAT)
#define FLASH_SMEM (2 * QMAT + 2 * FSTAGE)

__device__ __forceinline__ uint32_t fsw(int r, int c) {
    return (uint32_t)((r << 8) + ((c ^ (r & 7)) << 4));
}
__device__ __forceinline__ uint32_t pack_hi_rz(float p0, float p1, float& lo0, float& lo1) {
    uint32_t u0 = __float_as_uint(p0), u1 = __float_as_uint(p1);
    lo0 = p0 - __uint_as_float(u0 & 0xffff0000u);
    lo1 = p1 - __uint_as_float(u1 & 0xffff0000u);
    return __byte_perm(u0, u1, 0x7632);
}
__device__ __forceinline__ uint32_t pack_rn(float a, float b) {
    __nv_bfloat162 t = __floats2bfloat162_rn(a, b);
    return *(uint32_t*)&t;
}

__global__ void __launch_bounds__(256, 1) flash_tc_kernel(
    const __nv_bfloat16* __restrict__ qh, const __nv_bfloat16* __restrict__ ql,
    const __nv_bfloat16* __restrict__ kh, const __nv_bfloat16* __restrict__ kl,
    const __nv_bfloat16* __restrict__ vh, const __nv_bfloat16* __restrict__ vl,
    __nv_bfloat16* __restrict__ ath, __nv_bfloat16* __restrict__ atl)
{
    extern __shared__ char smc[];
    const uint32_t sb  = (uint32_t)__cvta_generic_to_shared(smc);
    const uint32_t sQh = sb, sQl = sb + QMAT;

    const int tid  = threadIdx.x;
    const int lane = tid & 31;
    const int w    = tid >> 5;
    const int rl   = lane & 15;
    const int rh   = lane >> 4;
    const int tg   = lane >> 2;
    const int ti   = lane & 3;
    const int vro  = (lane & 7) + ((lane >> 3) & 1) * 8;
    const int vco  = lane >> 4;

    const int qt    = gridDim.x - 1 - blockIdx.x;
    const int h     = blockIdx.y;
    const int kvh   = h >> 2;
    const int qbase = qt * BQ;
    const int wrow  = w * 16;

    for (int f = tid; f < 2048; f += 256) {
        const int r = f >> 4, c = f & 15;
        const size_t go = (size_t)(qbase + r) * DIM + h * HDIM + c * 8;
        CP16(sQh + fsw(r, c), qh + go);
        CP16(sQl + fsw(r, c), ql + go);
    }
    CP_COMMIT();

    auto loadKV = [&](int kt) {
        const uint32_t base = sb + 2 * QMAT + (kt & 1) * FSTAGE;
        const int kvb = kt * BKV;
        for (int f = tid; f < 1024; f += 256) {
            const int r = f >> 4, c = f & 15;
            const size_t go = (size_t)(kvb + r) * KVDIM + kvh * HDIM + c * 8;
            const uint32_t so = fsw(r, c);
            CP16(base + so,             kh + go);
            CP16(base + KVMAT + so,     kl + go);
            CP16(base + 2 * KVMAT + so, vh + go);
            CP16(base + 3 * KVMAT + so, vl + go);
        }
    };

    loadKV(0);
    CP_COMMIT();

    float o[16][4];
    #pragma unroll
    for (int i = 0; i < 16; i++)
        #pragma unroll
        for (int r = 0; r < 4; r++) o[i][r] = 0.0f;
    float m0 = -1e30f, m1 = -1e30f, l0 = 0.0f, l1 = 0.0f;
    const float scale = 0.08838834764831843f;
    const int row0 = qbase + wrow + tg;
    const int row1 = row0 + 8;

    const int nkt = 2 * qt + 2;
    for (int kt = 0; kt < nkt; kt++) {
        if (kt + 1 < nkt) { loadKV(kt + 1); CP_COMMIT(); CP_WAIT(1); }
        else              { CP_WAIT(0); }
        __syncthreads();

        const uint32_t base = sb + 2 * QMAT + (kt & 1) * FSTAGE;
        const uint32_t sKh = base, sKl = base + KVMAT;
        const uint32_t sVh = base + 2 * KVMAT, sVl = base + 3 * KVMAT;
        const int kvb = kt * BKV;

        // ---- S = Q K^T, pass-major ----
        float s[8][4];
        #pragma unroll
        for (int i = 0; i < 8; i++)
            #pragma unroll
            for (int r = 0; r < 4; r++) s[i][r] = 0.0f;

        #pragma unroll
        for (int kc = 0; kc < 8; kc++) {
            uint32_t ah[4], al[4];
            ldsm4(ah, sQh + fsw(wrow + rl, 2 * kc + rh));
            ldsm4(al, sQl + fsw(wrow + rl, 2 * kc + rh));

            uint32_t bh[8][2], bl[8][2];
            #pragma unroll
            for (int nb = 0; nb < 4; nb++) {
                uint32_t rk[4], rkl[4];
                ldsm4(rk,  sKh + fsw(nb * 16 + rl, 2 * kc + rh));
                ldsm4(rkl, sKl + fsw(nb * 16 + rl, 2 * kc + rh));
                bh[2 * nb][0]     = rk[0];  bh[2 * nb][1]     = rk[2];
                bh[2 * nb + 1][0] = rk[1];  bh[2 * nb + 1][1] = rk[3];
                bl[2 * nb][0]     = rkl[0]; bl[2 * nb][1]     = rkl[2];
                bl[2 * nb + 1][0] = rkl[1]; bl[2 * nb + 1][1] = rkl[3];
            }
            #pragma unroll
            for (int nj = 0; nj < 8; nj++) mma16816(s[nj], ah, bh[nj]);
            #pragma unroll
            for (int nj = 0; nj < 8; nj++) mma16816(s[nj], ah, bl[nj]);
            #pragma unroll
            for (int nj = 0; nj < 8; nj++) mma16816(s[nj], al, bh[nj]);
        }

        // ---- scale + causal mask ----
        const bool needmask = (kt >= 2 * qt);
        #pragma unroll
        for (int nj = 0; nj < 8; nj++) {
            #pragma unroll
            for (int r = 0; r < 4; r++) {
                float v = s[nj][r] * scale;
                if (needmask) {
                    const int col = kvb + nj * 8 + 2 * ti + (r & 1);
                    const int row = (r & 2) ? row1 : row0;
                    if (col > row) v = -1e30f;
                }
                s[nj][r] = v;
            }
        }

        // ---- online softmax ----
        float mx0 = -1e30f, mx1 = -1e30f;
        #pragma unroll
        for (int nj = 0; nj < 8; nj++) {
            mx0 = fmaxf(mx0, fmaxf(s[nj][0], s[nj][1]));
            mx1 = fmaxf(mx1, fmaxf(s[nj][2], s[nj][3]));
        }
        mx0 = fmaxf(mx0, __shfl_xor_sync(0xffffffffu, mx0, 1));
        mx0 = fmaxf(mx0, __shfl_xor_sync(0xffffffffu, mx0, 2));
        mx1 = fmaxf(mx1, __shfl_xor_sync(0xffffffffu, mx1, 1));
        mx1 = fmaxf(mx1, __shfl_xor_sync(0xffffffffu, mx1, 2));
        const float mn0 = fmaxf(m0, mx0), mn1 = fmaxf(m1, mx1);
        const float cr0 = __expf(m0 - mn0), cr1 = __expf(m1 - mn1);
        m0 = mn0; m1 = mn1;

        float sum0 = 0.0f, sum1 = 0.0f;
        #pragma unroll
        for (int nj = 0; nj < 8; nj++) {
            s[nj][0] = __expf(s[nj][0] - mn0); sum0 += s[nj][0];
            s[nj][1] = __expf(s[nj][1] - mn0); sum0 += s[nj][1];
            s[nj][2] = __expf(s[nj][2] - mn1); sum1 += s[nj][2];
            s[nj][3] = __expf(s[nj][3] - mn1); sum1 += s[nj][3];
        }
        sum0 += __shfl_xor_sync(0xffffffffu, sum0, 1);
        sum0 += __shfl_xor_sync(0xffffffffu, sum0, 2);
        sum1 += __shfl_xor_sync(0xffffffffu, sum1, 1);
        sum1 += __shfl_xor_sync(0xffffffffu, sum1, 2);
        l0 = l0 * cr0 + sum0;
        l1 = l1 * cr1 + sum1;

        #pragma unroll
        for (int nj = 0; nj < 16; nj++) {
            o[nj][0] *= cr0; o[nj][1] *= cr0;
            o[nj][2] *= cr1; o[nj][3] *= cr1;
        }

        // ---- O += P V, pass-major over halves ----
        #pragma unroll
        for (int kc = 0; kc < 4; kc++) {
            uint32_t pah[4], pal[4];
            {
                float la, lb;
                pah[0] = pack_hi_rz(s[2 * kc][0],     s[2 * kc][1],     la, lb); pal[0] = pack_rn(la, lb);
                pah[1] = pack_hi_rz(s[2 * kc][2],     s[2 * kc][3],     la, lb); pal[1] = pack_rn(la, lb);
                pah[2] = pack_hi_rz(s[2 * kc + 1][0], s[2 * kc + 1][1], la, lb); pal[2] = pack_rn(la, lb);
                pah[3] = pack_hi_rz(s[2 * kc + 1][2], s[2 * kc + 1][3], la, lb); pal[3] = pack_rn(la, lb);
            }
            #pragma unroll
            for (int half = 0; half < 2; half++) {
                uint32_t bv[8][2], cv[8][2];
                #pragma unroll
                for (int n4 = 0; n4 < 4; n4++) {
                    const int nb = half * 4 + n4;
                    uint32_t rv[4], rw[4];
                    const uint32_t so = fsw(kc * 16 + vro, 2 * nb + vco);
                    ldsm4t(rv, sVh + so);
                    ldsm4t(rw, sVl + so);
                    bv[2 * n4][0]     = rv[0]; bv[2 * n4][1]     = rv[1];
                    bv[2 * n4 + 1][0] = rv[2]; bv[2 * n4 + 1][1] = rv[3];
                    cv[2 * n4][0]     = rw[0]; cv[2 * n4][1]     = rw[1];
                    cv[2 * n4 + 1][0] = rw[2]; cv[2 * n4 + 1][1] = rw[3];
                }
                #pragma unroll
                for (int j = 0; j < 8; j++) mma16816(o[8 * half + j], pah, bv[j]);
                #pragma unroll
                for (int j = 0; j < 8; j++) mma16816(o[8 * half + j], pah, cv[j]);
                #pragma unroll
                for (int j = 0; j < 8; j++) mma16816(o[8 * half + j], pal, bv[j]);
            }
        }
        __syncthreads();
    }

    // ---- epilogue: normalize, split hi/lo, store ----
    const float inv0 = 1.0f / l0, inv1 = 1.0f / l1;
    #pragma unroll
    for (int nj = 0; nj < 16; nj++) {
        const int col = h * HDIM + nj * 8 + 2 * ti;
        float v0 = o[nj][0] * inv0, v1 = o[nj][1] * inv0;
        float v2 = o[nj][2] * inv1, v3 = o[nj][3] * inv1;
        __nv_bfloat162 h0 = __floats2bfloat162_rn(v0, v1);
        __nv_bfloat162 h1 = __floats2bfloat162_rn(v2, v3);
        __nv_bfloat162 e0 = __floats2bfloat162_rn(v0 - __low2float(h0), v1 - __high2float(h0));
        __nv_bfloat162 e1 = __floats2bfloat162_rn(v2 - __low2float(h1), v3 - __high2float(h1));
        *(uint32_t*)&ath[(size_t)row0 * DIM + col] = *(uint32_t*)&h0;
        *(uint32_t*)&ath[(size_t)row1 * DIM + col] = *(uint32_t*)&h1;
        *(uint32_t*)&atl[(size_t)row0 * DIM + col] = *(uint32_t*)&e0;
        *(uint32_t*)&atl[(size_t)row1 * DIM + col] = *(uint32_t*)&e1;
    }
}

// ============================================================================
// launch
// ============================================================================
extern "C" void kernel_launch(void* const* d_in, const int* in_sizes, int n_in,
                              void* d_out, int out_size)
{
    (void)in_sizes; (void)n_in; (void)out_size;
    const float* x  = (const float*)d_in[0];
    const float* wq = (const float*)d_in[1];
    const float* wk = (const float*)d_in[2];
    const float* wv = (const float*)d_in[3];
    const float* wo = (const float*)d_in[4];
    const float* fc = (const float*)d_in[5];
    const float* fs = (const float*)d_in[6];
    float* out = (float*)d_out;

    __nv_bfloat16 *xh, *xl, *wqh, *wql, *wkh, *wkl, *wvh, *wvl, *woh, *wol;
    __nv_bfloat16 *ath, *atl, *qh, *ql, *kh, *kl, *vh, *vl;
    cudaGetSymbolAddress((void**)&xh,  g_xh);  cudaGetSymbolAddress((void**)&xl,  g_xl);
    cudaGetSymbolAddress((void**)&wqh, g_wqh); cudaGetSymbolAddress((void**)&wql, g_wql);
    cudaGetSymbolAddress((void**)&wkh, g_wkh); cudaGetSymbolAddress((void**)&wkl, g_wkl);
    cudaGetSymbolAddress((void**)&wvh, g_wvh); cudaGetSymbolAddress((void**)&wvl, g_wvl);
    cudaGetSymbolAddress((void**)&woh, g_woh); cudaGetSymbolAddress((void**)&wol, g_wol);
    cudaGetSymbolAddress((void**)&ath, g_ath); cudaGetSymbolAddress((void**)&atl, g_atl);
    cudaGetSymbolAddress((void**)&qh,  g_qh);  cudaGetSymbolAddress((void**)&ql,  g_ql);
    cudaGetSymbolAddress((void**)&kh,  g_kh);  cudaGetSymbolAddress((void**)&kl,  g_kl);
    cudaGetSymbolAddress((void**)&vh,  g_vh);  cudaGetSymbolAddress((void**)&vl,  g_vl);

    cudaFuncSetAttribute(gemm_bf16x3_kernel,
                         cudaFuncAttributeMaxDynamicSharedMemorySize, GEMM_SMEM);
    cudaFuncSetAttribute(flash_tc_kernel,
                         cudaFuncAttributeMaxDynamicSharedMemorySize, FLASH_SMEM);

    // 0) splits: x ; wq+wo fused ; wk+wv fused  (3 launches)
    split_kernel<<<dim3((SEQ * DIM / 4 + 255) / 256, 1), 256>>>(
        x, xh, xl, nullptr, nullptr, nullptr, SEQ * DIM / 4);
    split_kernel<<<dim3((DIM * DIM / 4 + 255) / 256, 2), 256>>>(
        wq, wqh, wql, wo, woh, wol, DIM * DIM / 4);
    split_kernel<<<dim3((KVDIM * DIM / 4 + 255) / 256, 2), 256>>>(
        wk, wkh, wkl, wv, wvh, wvl, KVDIM * DIM / 4);

    // 1) fused Q + K + V projections; epilogue applies RoPE (Q,K) / split (V)
    gemm_bf16x3_kernel<<<dim3((DIM + 2 * KVDIM) / GBN, SEQ / GBM, 1), 256, GEMM_SMEM>>>(
        xh, xl,
        wqh, wql, qh, ql, DIM,   1,
        wkh, wkl, kh, kl, KVDIM, 1,
        wvh, wvl, vh, vl,        2,
        fc, fs, DIM);

    // 2) tensor-core flash attention -> attn hi/lo
    flash_tc_kernel<<<dim3(SEQ / BQ, HEADS), 256, FLASH_SMEM>>>(
        qh, ql, kh, kl, vh, vl, ath, atl);

    // 3) O projection (single group, fp32 store)
    gemm_bf16x3_kernel<<<dim3(DIM / GBN, SEQ / GBM, 1), 256, GEMM_SMEM>>>(
        ath, atl,
        woh, wol, out, nullptr, DIM, 0,
        nullptr, nullptr, nullptr, nullptr, 0, 0,
        nullptr, nullptr, nullptr, nullptr, 0,
        nullptr, nullptr, DIM);
}